// round 7
// baseline (speedup 1.0000x reference)
#include <cuda_runtime.h>
#include <cstdint>

#define NNODES 768
#define NFACES 256
#define NTOT   1024
#define E0     6144
#define EF     1536
#define ETOT   9216
#define C      64
#define COLCAP 64
#define NKT    16
#define HSTR   68
#define SMEM_L2_BYTES ((64 * HSTR * 2 + 64 * 64) * 4)
#define SMEM_L1_BYTES ((64 * 65 + 1024 + 64 * 65 + 64 * 64) * 4)

// ---------------- device scratch ----------------
__device__ float g_feat[(NTOT + E0) * C];   // [0,1024): node_all; [1024,7168): edge conn
__device__ float g_adjn[NTOT * NTOT];
__device__ int   g_outcnt[NTOT];
__device__ float g_srow[NTOT];
__device__ int   g_row_cnt[NTOT];
__device__ int   g_row_col[NTOT * 192];
__device__ float g_row_val[NTOT * 192];
__device__ int   g_col_cnt[NTOT];
__device__ int   g_col_sc[NTOT * COLCAP];   // (src<<13)|conn_row
__device__ float g_delta[67108864];
__device__ unsigned char g_islot[NTOT * NKT * 64];  // inverse map: (seg, kl) -> entry | 0xFF
__device__ int   g_scnt[NTOT * NKT];

__device__ __forceinline__ float f2lo(uint64_t v) { return __uint_as_float((unsigned)v); }
__device__ __forceinline__ float f2hi(uint64_t v) { return __uint_as_float((unsigned)(v >> 32)); }
__device__ __forceinline__ void fma2(uint64_t& d, uint64_t a, uint64_t b) {
    asm("fma.rn.f32x2 %0, %1, %2, %0;" : "+l"(d) : "l"(a), "l"(b));
}
__device__ __forceinline__ uint64_t splat2(float a) {
    uint64_t v; asm("mov.b64 %0, {%1, %1};" : "=l"(v) : "f"(a)); return v;
}

// ---------------- embedding body ----------------
__device__ __forceinline__ void embed_body(
    const float* __restrict__ X, int blk, int R, int Din,
    const float* __restrict__ W1, const float* __restrict__ b1,
    const float* __restrict__ W2, const float* __restrict__ b2,
    float* __restrict__ Y, float* Xs, float* Hs)
{
    int r0 = blk * 16;
    int t = threadIdx.x;
    for (int idx = t; idx < 16 * Din; idx += 128) {
        int r = idx / Din, d = idx % Din;
        Xs[r * Din + d] = (r0 + r < R) ? X[(size_t)(r0 + r) * Din + d] : 0.f;
    }
    __syncthreads();
    int lr = t >> 3;
    int c0 = (t & 7) * 8;
    float h[8];
#pragma unroll
    for (int q = 0; q < 8; q++) h[q] = b1[c0 + q];
    for (int d = 0; d < Din; d++) {
        float x = Xs[lr * Din + d];
        const float* w = W1 + d * C + c0;
#pragma unroll
        for (int q = 0; q < 8; q++) h[q] += x * w[q];
    }
#pragma unroll
    for (int q = 0; q < 8; q++) Hs[lr * C + c0 + q] = fmaxf(h[q], 0.f);
    __syncthreads();
    float y[8];
#pragma unroll
    for (int q = 0; q < 8; q++) y[q] = b2[c0 + q];
    for (int m = 0; m < C; m++) {
        float hm = Hs[lr * C + m];
        const float* w = W2 + m * C + c0;
#pragma unroll
        for (int q = 0; q < 8; q++) y[q] += hm * w[q];
    }
    if (r0 + lr < R) {
        float* yo = Y + (size_t)(r0 + lr) * C + c0;
#pragma unroll
        for (int q = 0; q < 8; q++) yo[q] = fmaxf(y[q], 0.f);
    }
}

// ---------------- launch 1: embeds + zeroing ----------------
__global__ __launch_bounds__(128) void k_init(
    const float* __restrict__ node_x, const float* __restrict__ edge_x,
    const float* __restrict__ face_x,
    const float* __restrict__ nW1, const float* __restrict__ nb1,
    const float* __restrict__ nW2, const float* __restrict__ nb2,
    const float* __restrict__ eW1, const float* __restrict__ eb1,
    const float* __restrict__ eW2, const float* __restrict__ eb2,
    const float* __restrict__ fW1, const float* __restrict__ fb1,
    const float* __restrict__ fW2, const float* __restrict__ fb2)
{
    __shared__ float Xs[16 * 144];
    __shared__ float Hs[16 * C];
    int b = blockIdx.x;
    int t = threadIdx.x;
    if (b < 48) {
        embed_body(node_x, b, NNODES, 144, nW1, nb1, nW2, nb2, g_feat, Xs, Hs);
    } else if (b < 432) {
        embed_body(edge_x, b - 48, E0, 144, eW1, eb1, eW2, eb2, g_feat + NTOT * C, Xs, Hs);
    } else if (b < 448) {
        embed_body(face_x, b - 432, NFACES, 12, fW1, fb1, fW2, fb2, g_feat + NNODES * C, Xs, Hs);
    } else {
        int z = b - 448;  // 0..1023
        float4 zv = make_float4(0.f, 0.f, 0.f, 0.f);
        float4* ap = (float4*)(g_adjn) + (size_t)z * 256 + t * 2;
        ap[0] = zv; ap[1] = zv;
        if (z == 0) {
            for (int q = 0; q < 8; q++) g_col_cnt[t * 8 + q] = 0;
        } else if (z == 1) {
            for (int q = 0; q < 8; q++) g_outcnt[t * 8 + q] = 0;
        }
    }
}

// ---------------- launch 2: edges + diag + out-degree counts ----------------
__global__ void k_edges(const int* __restrict__ ei, const int* __restrict__ fn) {
    int e = blockIdx.x * blockDim.x + threadIdx.x;
    if (e >= ETOT + NTOT) return;
    if (e >= ETOT) {
        int i = e - ETOT;
        atomicAdd(&g_adjn[i * NTOT + i], 1.0f);
        return;
    }
    int s, d, cr;
    if (e < E0)            { s = ei[e]; d = ei[E0 + e]; cr = NTOT + e; }
    else if (e < E0 + EF)  { int q = e - E0; int f = q / 6; s = fn[q]; d = NNODES + f; cr = NNODES + f; }
    else                   { int r = e - (E0 + EF); int rr = 1535 - r; int f = rr / 6;
                             s = NNODES + f; d = fn[rr]; cr = NNODES + f; }
    atomicAdd(&g_adjn[s * NTOT + d], 1.0f);
    atomicAdd(&g_outcnt[s], 1);
    int p = atomicAdd(&g_col_cnt[d], 1);
    if (p < COLCAP) g_col_sc[d * COLCAP + p] = (s << 13) | cr;
}

// ---------------- launch 3: scale + CSR + row sums (deg = outcnt + 1) ----------------
__global__ __launch_bounds__(256) void k_scale_csr() {
    int i = blockIdx.x;
    __shared__ int cnt;
    __shared__ float red[8];
    if (threadIdx.x == 0) cnt = 0;
    __syncthreads();
    float di = 1.f / sqrtf(1.f + (float)g_outcnt[i]);
    float sv = 0.f;
    for (int j = threadIdx.x; j < NTOT; j += 256) {
        float v = g_adjn[i * NTOT + j];
        if (v != 0.f) {
            float dj = 1.f / sqrtf(1.f + (float)g_outcnt[j]);
            v *= di * dj;
            g_adjn[i * NTOT + j] = v;
            sv += v;
            int p = atomicAdd(&cnt, 1);
            if (p < 192) { g_row_col[i * 192 + p] = j; g_row_val[i * 192 + p] = v; }
        }
    }
#pragma unroll
    for (int o = 16; o > 0; o >>= 1) sv += __shfl_down_sync(0xffffffffu, sv, o);
    if ((threadIdx.x & 31) == 0) red[threadIdx.x >> 5] = sv;
    __syncthreads();
    if (threadIdx.x == 0) {
        float tot = 0.f;
        for (int w = 0; w < 8; w++) tot += red[w];
        g_srow[i] = tot;
        g_row_cnt[i] = min(cnt, 192);
    }
}

// ---------------- launch 4: layer-1 delta rows (shared-staged, W in smem) ----------------
__global__ __launch_bounds__(256) void k_layer1(
    const float* __restrict__ plW, const float* __restrict__ plb)
{
    extern __shared__ float dyn[];
    float* Hs     = dyn;                      // [64][65]
    float* sAdj   = dyn + 64 * 65;            // [1024]
    int*   sColsc = (int*)(dyn + 64 * 65 + 1024);  // [64][65]
    float* Ws     = dyn + 64 * 65 + 1024 + 64 * 65; // [64][64]
    __shared__ int sCnt[64];
    __shared__ int flist[64];
    __shared__ unsigned char ipos[64];
    __shared__ int nf;

    const int kt = blockIdx.x;
    const int j  = blockIdx.y;
    const int t  = threadIdx.x;
    if (t == 0) nf = 0;
    if (t < 64) ipos[t] = 0xFF;

    // stage plW (1024 float4), adjn row j, packed col lists
    {
        const float4* wsrc = (const float4*)plW;
        float4* wdst = (float4*)Ws;
#pragma unroll
        for (int q = 0; q < 4; q++) wdst[t + q * 256] = wsrc[t + q * 256];
    }
    {
        const float4* src = (const float4*)(g_adjn + (size_t)j * NTOT);
        ((float4*)sAdj)[t] = src[t];
    }
    {
        const int4* src = (const int4*)(g_col_sc + kt * 64 * COLCAP);
#pragma unroll
        for (int q = 0; q < 4; q++) {
            int idx4 = t + q * 256;
            int4 v = src[idx4];
            int kl = idx4 >> 4;
            int c  = (idx4 & 15) * 4;
            int* dst = sColsc + kl * 65 + c;
            dst[0] = v.x; dst[1] = v.y; dst[2] = v.z; dst[3] = v.w;
        }
    }
    if (t < 64) sCnt[t] = min(g_col_cnt[kt * 64 + t], COLCAP);
    __syncthreads();

    const int kl = t & 63;
    const int m0 = (t >> 6) * 16;
    const int k  = kt * 64 + kl;

    float acc[16];
    bool fl = false;
    float ajk = sAdj[k];
    if (ajk != 0.f) {
        fl = true;
        const float* na = g_feat + k * C + m0;
#pragma unroll
        for (int q = 0; q < 16; q++) acc[q] = ajk * na[q];
    } else {
#pragma unroll
        for (int q = 0; q < 16; q++) acc[q] = 0.f;
    }
    const int cc = sCnt[kl];
    const int* lst = sColsc + kl * 65;
    for (int c = 0; c < cc; c++) {
        int packed = lst[c];
        float a = sAdj[packed >> 13];
        if (a != 0.f) {
            fl = true;
            const float4* cp = (const float4*)(g_feat + (packed & 8191) * C + m0);
#pragma unroll
            for (int q = 0; q < 4; q++) {
                float4 v = cp[q];
                acc[4*q+0] += a * v.x; acc[4*q+1] += a * v.y;
                acc[4*q+2] += a * v.z; acc[4*q+3] += a * v.w;
            }
        }
    }
#pragma unroll
    for (int q = 0; q < 16; q++) Hs[kl * 65 + m0 + q] = acc[q];
    if ((t >> 6) == 0 && fl) { int p = atomicAdd(&nf, 1); flist[p] = kl; }
    __syncthreads();

    const int seg = j * NKT + kt;
    const int n = nf;
    if (t < n) ipos[flist[t]] = (unsigned char)t;
    __syncthreads();
    if (t < 64) g_islot[seg * 64 + t] = ipos[t];

    const int c = t & 63;
    const float crc = fmaxf(plb[c], 0.f);
    const size_t segbase = (size_t)seg * 64 * 64;
    for (int idx = t >> 6; idx < n; idx += 4) {
        int row = flist[idx];
        float y = plb[c];
        const float* Hrow = Hs + row * 65;
#pragma unroll 16
        for (int m = 0; m < 64; m++) y += Hrow[m] * Ws[m * 64 + c];
        g_delta[segbase + (size_t)idx * 64 + c] = fmaxf(y, 0.f) - crc;
    }
    if (t == 0) g_scnt[seg] = n;
}

// ---------------- f32x2 GEMM phases ----------------
__device__ __forceinline__ void loadW4(float* Ws, const float* __restrict__ W, int nf4, int t) {
    const float4* src = (const float4*)W;
    float4* dst = (float4*)Ws;
    for (int idx = t; idx < nf4; idx += 256) dst[idx] = src[idx];
}

__device__ __forceinline__ void gemm64(
    const float* As, const float* Ws, const float* __restrict__ bias,
    float* Ps, int t, bool doRelu)
{
    const int r0 = (t >> 4) * 4;
    const int c0 = (t & 15) * 4;
    uint64_t b01 = *(const uint64_t*)(bias + c0);
    uint64_t b23 = *(const uint64_t*)(bias + c0 + 2);
    uint64_t acc[4][2];
#pragma unroll
    for (int r = 0; r < 4; r++) { acc[r][0] = b01; acc[r][1] = b23; }
#pragma unroll 4
    for (int m4 = 0; m4 < 64; m4 += 4) {
        float4 a4[4];
#pragma unroll
        for (int r = 0; r < 4; r++) a4[r] = *(const float4*)(As + (r0 + r) * HSTR + m4);
#pragma unroll
        for (int kk = 0; kk < 4; kk++) {
            uint64_t w0 = *(const uint64_t*)(Ws + (m4 + kk) * 64 + c0);
            uint64_t w1 = *(const uint64_t*)(Ws + (m4 + kk) * 64 + c0 + 2);
#pragma unroll
            for (int r = 0; r < 4; r++) {
                float av = (kk == 0) ? a4[r].x : (kk == 1) ? a4[r].y : (kk == 2) ? a4[r].z : a4[r].w;
                uint64_t aa = splat2(av);
                fma2(acc[r][0], aa, w0);
                fma2(acc[r][1], aa, w1);
            }
        }
    }
#pragma unroll
    for (int r = 0; r < 4; r++) {
        float4 v = make_float4(f2lo(acc[r][0]), f2hi(acc[r][0]),
                               f2lo(acc[r][1]), f2hi(acc[r][1]));
        if (doRelu) {
            v.x = fmaxf(v.x, 0.f); v.y = fmaxf(v.y, 0.f);
            v.z = fmaxf(v.z, 0.f); v.w = fmaxf(v.w, 0.f);
        }
        *(float4*)(Ps + (r0 + r) * HSTR + c0) = v;
    }
}

__device__ __forceinline__ void gemm32_out(
    const float* As, const float* Ws, const float* __restrict__ bias,
    float* outG, int t)
{
    const int r0 = (t >> 3) * 2;
    const int c0 = (t & 7) * 4;
    uint64_t b01 = *(const uint64_t*)(bias + c0);
    uint64_t b23 = *(const uint64_t*)(bias + c0 + 2);
    uint64_t acc[2][2];
#pragma unroll
    for (int r = 0; r < 2; r++) { acc[r][0] = b01; acc[r][1] = b23; }
#pragma unroll 4
    for (int m4 = 0; m4 < 64; m4 += 4) {
        float4 a4[2];
#pragma unroll
        for (int r = 0; r < 2; r++) a4[r] = *(const float4*)(As + (r0 + r) * HSTR + m4);
#pragma unroll
        for (int kk = 0; kk < 4; kk++) {
            uint64_t w0 = *(const uint64_t*)(Ws + (m4 + kk) * 32 + c0);
            uint64_t w1 = *(const uint64_t*)(Ws + (m4 + kk) * 32 + c0 + 2);
#pragma unroll
            for (int r = 0; r < 2; r++) {
                float av = (kk == 0) ? a4[r].x : (kk == 1) ? a4[r].y : (kk == 2) ? a4[r].z : a4[r].w;
                uint64_t aa = splat2(av);
                fma2(acc[r][0], aa, w0);
                fma2(acc[r][1], aa, w1);
            }
        }
    }
#pragma unroll
    for (int r = 0; r < 2; r++) {
        float4 v = make_float4(f2lo(acc[r][0]), f2hi(acc[r][0]),
                               f2lo(acc[r][1]), f2hi(acc[r][1]));
        *(float4*)(outG + (size_t)(r0 + r) * 32 + c0) = v;
    }
}

// ---------------- launch 5: layer 2 fused ----------------
__global__ __launch_bounds__(256) void k_layer2(
    const float* __restrict__ plb0,
    const float* __restrict__ plW, const float* __restrict__ plb,
    const float* __restrict__ oW1, const float* __restrict__ ob1,
    const float* __restrict__ oW2, const float* __restrict__ ob2,
    float* __restrict__ out)
{
    extern __shared__ float smem[];
    float* Hs = smem;                  // [64][HSTR]
    float* Gs = smem + 64 * HSTR;      // [64][HSTR]
    float* Ws = smem + 128 * HSTR;     // [64][64]

    const int i  = blockIdx.x;
    const int kt = blockIdx.y;
    const int t  = threadIdx.x;

    // Phase A: sync-free register gather via inverse slot map
    {
        const int kl  = t & 63;
        const int sub = (t >> 6) * 16;
        const float sI = g_srow[i];
        float4 acc[4];
#pragma unroll
        for (int q = 0; q < 4; q++) {
            float4 b = *(const float4*)(plb0 + sub + q * 4);
            acc[q] = make_float4(sI * fmaxf(b.x, 0.f), sI * fmaxf(b.y, 0.f),
                                 sI * fmaxf(b.z, 0.f), sI * fmaxf(b.w, 0.f));
        }
        const int rn = g_row_cnt[i];
        const int*   rc = g_row_col + i * 192;
        const float* rv = g_row_val + i * 192;
        for (int r = 0; r < rn; r++) {
            const int seg = rc[r] * NKT + kt;
            const unsigned slot = g_islot[seg * 64 + kl];
            if (slot != 0xFFu) {
                const float a = rv[r];
                const float4* dp = (const float4*)(g_delta + ((size_t)seg * 64 + slot) * 64 + sub);
#pragma unroll
                for (int q = 0; q < 4; q++) {
                    float4 v = dp[q];
                    acc[q].x += a * v.x; acc[q].y += a * v.y;
                    acc[q].z += a * v.z; acc[q].w += a * v.w;
                }
            }
        }
        float4* hp = (float4*)(Hs + kl * HSTR + sub);
#pragma unroll
        for (int q = 0; q < 4; q++) hp[q] = acc[q];
    }
    __syncthreads();

    // Phase B: Gs = relu(Hs @ plW1 + plb1)
    loadW4(Ws, plW, 1024, t);
    __syncthreads();
    gemm64(Hs, Ws, plb, Gs, t, true);
    __syncthreads();

    // Phase C: Hs = relu(Gs @ oW1 + ob1)
    loadW4(Ws, oW1, 1024, t);
    __syncthreads();
    gemm64(Gs, Ws, ob1, Hs, t, true);
    __syncthreads();

    // Phase D: out = Hs @ oW2 + ob2
    loadW4(Ws, oW2, 512, t);
    __syncthreads();
    gemm32_out(Hs, Ws, ob2, out + ((size_t)i * NTOT + (size_t)kt * 64) * 32, t);
}

// ---------------- launch ----------------
extern "C" void kernel_launch(void* const* d_in, const int* in_sizes, int n_in,
                              void* d_out, int out_size)
{
    const float* node_x = (const float*)d_in[0];
    const float* edge_x = (const float*)d_in[1];
    const float* face_x = (const float*)d_in[2];
    const float* nW1 = (const float*)d_in[3];  const float* nb1 = (const float*)d_in[4];
    const float* nW2 = (const float*)d_in[5];  const float* nb2 = (const float*)d_in[6];
    const float* eW1 = (const float*)d_in[7];  const float* eb1 = (const float*)d_in[8];
    const float* eW2 = (const float*)d_in[9];  const float* eb2 = (const float*)d_in[10];
    const float* fW1 = (const float*)d_in[11]; const float* fb1 = (const float*)d_in[12];
    const float* fW2 = (const float*)d_in[13]; const float* fb2 = (const float*)d_in[14];
    const float* oW1 = (const float*)d_in[15]; const float* ob1 = (const float*)d_in[16];
    const float* oW2 = (const float*)d_in[17]; const float* ob2 = (const float*)d_in[18];
    const float* plW = (const float*)d_in[19]; const float* plb = (const float*)d_in[20];
    const int* edge_index = (const int*)d_in[21];
    const int* face_nodes = (const int*)d_in[22];
    float* out = (float*)d_out;

    cudaFuncSetAttribute(k_layer1, cudaFuncAttributeMaxDynamicSharedMemorySize, SMEM_L1_BYTES);
    cudaFuncSetAttribute(k_layer2, cudaFuncAttributeMaxDynamicSharedMemorySize, SMEM_L2_BYTES);

    k_init<<<1472, 128>>>(node_x, edge_x, face_x, nW1, nb1, nW2, nb2,
                          eW1, eb1, eW2, eb2, fW1, fb1, fW2, fb2);
    k_edges<<<(ETOT + NTOT + 255) / 256, 256>>>(edge_index, face_nodes);
    k_scale_csr<<<NTOT, 256>>>();
    k_layer1<<<dim3(NKT, NTOT), 256, SMEM_L1_BYTES>>>(plW, plb);
    k_layer2<<<dim3(NTOT, NKT), 256, SMEM_L2_BYTES>>>(plb, plW + 4096, plb + 64,
                                                      oW1, ob1, oW2, ob2, out);
    (void)in_sizes; (void)n_in; (void)out_size;
}

// round 10
// speedup vs baseline: 1.0647x; 1.0647x over previous
#include <cuda_runtime.h>
#include <cstdint>

#define NNODES 768
#define NFACES 256
#define NTOT   1024
#define E0     6144
#define EF     1536
#define ETOT   9216
#define C      64
#define NKT    16
#define HSTR   68
#define SRCCAP 64
#define HCAP   128
#define SMEM_L2_BYTES ((64 * HSTR * 2 + 64 * 64) * 4)

// ---------------- device scratch ----------------
__device__ float g_feat[(NTOT + E0) * C];   // [0,1024): node_all; [1024,7168): edge conn
__device__ float g_adjn[NTOT * NTOT];
__device__ int   g_outcnt[NTOT];
__device__ float g_srow[NTOT];
__device__ int   g_row_cnt[NTOT];
__device__ int   g_row_col[NTOT * 192];
__device__ float g_row_val[NTOT * 192];
__device__ int   g_src_cnt[NTOT];
__device__ int   g_src_list[NTOT * SRCCAP];     // (d<<13)|cr
__device__ int   g_hcnt[NTOT * NKT];
__device__ int2  g_hits[NTOT * NKT * HCAP];     // {(kl<<13)|cr, bits(a)}
__device__ float g_delta[67108864];
__device__ unsigned char g_islot[NTOT * NKT * 64];

__device__ __forceinline__ float f2lo(uint64_t v) { return __uint_as_float((unsigned)v); }
__device__ __forceinline__ float f2hi(uint64_t v) { return __uint_as_float((unsigned)(v >> 32)); }
__device__ __forceinline__ void fma2(uint64_t& d, uint64_t a, uint64_t b) {
    asm("fma.rn.f32x2 %0, %1, %2, %0;" : "+l"(d) : "l"(a), "l"(b));
}
__device__ __forceinline__ uint64_t splat2(float a) {
    uint64_t v; asm("mov.b64 %0, {%1, %1};" : "=l"(v) : "f"(a)); return v;
}

// ---------------- embedding body ----------------
__device__ __forceinline__ void embed_body(
    const float* __restrict__ X, int blk, int R, int Din,
    const float* __restrict__ W1, const float* __restrict__ b1,
    const float* __restrict__ W2, const float* __restrict__ b2,
    float* __restrict__ Y, float* Xs, float* Hs)
{
    int r0 = blk * 16;
    int t = threadIdx.x;
    for (int idx = t; idx < 16 * Din; idx += 128) {
        int r = idx / Din, d = idx % Din;
        Xs[r * Din + d] = (r0 + r < R) ? X[(size_t)(r0 + r) * Din + d] : 0.f;
    }
    __syncthreads();
    int lr = t >> 3;
    int c0 = (t & 7) * 8;
    float h[8];
#pragma unroll
    for (int q = 0; q < 8; q++) h[q] = b1[c0 + q];
    for (int d = 0; d < Din; d++) {
        float x = Xs[lr * Din + d];
        const float* w = W1 + d * C + c0;
#pragma unroll
        for (int q = 0; q < 8; q++) h[q] += x * w[q];
    }
#pragma unroll
    for (int q = 0; q < 8; q++) Hs[lr * C + c0 + q] = fmaxf(h[q], 0.f);
    __syncthreads();
    float y[8];
#pragma unroll
    for (int q = 0; q < 8; q++) y[q] = b2[c0 + q];
    for (int m = 0; m < C; m++) {
        float hm = Hs[lr * C + m];
        const float* w = W2 + m * C + c0;
#pragma unroll
        for (int q = 0; q < 8; q++) y[q] += hm * w[q];
    }
    if (r0 + lr < R) {
        float* yo = Y + (size_t)(r0 + lr) * C + c0;
#pragma unroll
        for (int q = 0; q < 8; q++) yo[q] = fmaxf(y[q], 0.f);
    }
}

// ---------------- launch 1: embeds + zeroing ----------------
__global__ __launch_bounds__(128) void k_init(
    const float* __restrict__ node_x, const float* __restrict__ edge_x,
    const float* __restrict__ face_x,
    const float* __restrict__ nW1, const float* __restrict__ nb1,
    const float* __restrict__ nW2, const float* __restrict__ nb2,
    const float* __restrict__ eW1, const float* __restrict__ eb1,
    const float* __restrict__ eW2, const float* __restrict__ eb2,
    const float* __restrict__ fW1, const float* __restrict__ fb1,
    const float* __restrict__ fW2, const float* __restrict__ fb2)
{
    __shared__ float Xs[16 * 144];
    __shared__ float Hs[16 * C];
    int b = blockIdx.x;
    int t = threadIdx.x;
    if (b < 48) {
        embed_body(node_x, b, NNODES, 144, nW1, nb1, nW2, nb2, g_feat, Xs, Hs);
    } else if (b < 432) {
        embed_body(edge_x, b - 48, E0, 144, eW1, eb1, eW2, eb2, g_feat + NTOT * C, Xs, Hs);
    } else if (b < 448) {
        embed_body(face_x, b - 432, NFACES, 12, fW1, fb1, fW2, fb2, g_feat + NNODES * C, Xs, Hs);
    } else {
        int z = b - 448;  // 0..1023
        float4 zv = make_float4(0.f, 0.f, 0.f, 0.f);
        float4* ap = (float4*)(g_adjn) + (size_t)z * 256 + t * 2;
        ap[0] = zv; ap[1] = zv;
        if (z == 0) {
            for (int q = 0; q < 8; q++) g_src_cnt[t * 8 + q] = 0;
        } else if (z == 1) {
            for (int q = 0; q < 8; q++) g_outcnt[t * 8 + q] = 0;
        } else if (z >= 2 && z < 6) {
            int4 z4 = make_int4(0, 0, 0, 0);
            int4* hp = (int4*)g_hcnt + (z - 2) * 1024 + t * 8;
#pragma unroll
            for (int q = 0; q < 8; q++) hp[q] = z4;
        }
    }
}

// ---------------- launch 2: edges + diag + out-degree + src lists ----------------
__global__ void k_edges(const int* __restrict__ ei, const int* __restrict__ fn) {
    int e = blockIdx.x * blockDim.x + threadIdx.x;
    if (e >= ETOT + NTOT) return;
    if (e >= ETOT) {
        int i = e - ETOT;
        atomicAdd(&g_adjn[i * NTOT + i], 1.0f);
        return;
    }
    int s, d, cr;
    if (e < E0)            { s = ei[e]; d = ei[E0 + e]; cr = NTOT + e; }
    else if (e < E0 + EF)  { int q = e - E0; int f = q / 6; s = fn[q]; d = NNODES + f; cr = NNODES + f; }
    else                   { int r = e - (E0 + EF); int rr = 1535 - r; int f = rr / 6;
                             s = NNODES + f; d = fn[rr]; cr = NNODES + f; }
    atomicAdd(&g_adjn[s * NTOT + d], 1.0f);
    atomicAdd(&g_outcnt[s], 1);
    int p = atomicAdd(&g_src_cnt[s], 1);
    if (p < SRCCAP) g_src_list[s * SRCCAP + p] = (d << 13) | cr;
}

// ---------------- launch 3: scale + CSR + row sums (deg = outcnt + 1) ----------------
__global__ __launch_bounds__(256) void k_scale_csr() {
    int i = blockIdx.x;
    __shared__ int cnt;
    __shared__ float red[8];
    if (threadIdx.x == 0) cnt = 0;
    __syncthreads();
    float di = 1.f / sqrtf(1.f + (float)g_outcnt[i]);
    float sv = 0.f;
    for (int j = threadIdx.x; j < NTOT; j += 256) {
        float v = g_adjn[i * NTOT + j];
        if (v != 0.f) {
            float dj = 1.f / sqrtf(1.f + (float)g_outcnt[j]);
            v *= di * dj;
            sv += v;
            int p = atomicAdd(&cnt, 1);
            if (p < 192) { g_row_col[i * 192 + p] = j; g_row_val[i * 192 + p] = v; }
        }
    }
#pragma unroll
    for (int o = 16; o > 0; o >>= 1) sv += __shfl_down_sync(0xffffffffu, sv, o);
    if ((threadIdx.x & 31) == 0) red[threadIdx.x >> 5] = sv;
    __syncthreads();
    if (threadIdx.x == 0) {
        float tot = 0.f;
        for (int w = 0; w < 8; w++) tot += red[w];
        g_srow[i] = tot;
        g_row_cnt[i] = min(cnt, 192);
    }
}

// ---------------- launch 4: build per-(j,kt) hit lists ----------------
__global__ __launch_bounds__(256) void k_hits() {
    const int j = blockIdx.x;
    const int t = threadIdx.x;
    __shared__ int sc[NKT];
    if (t < NKT) sc[t] = 0;
    __syncthreads();
    const int rn = g_row_cnt[j];
    if (t < rn) {
        int s = g_row_col[j * 192 + t];
        int abits = __float_as_int(g_row_val[j * 192 + t]);
        // diagonal contribution: column s gets a * node_all[s]
        {
            int kt = s >> 6, kl = s & 63;
            int p = atomicAdd(&sc[kt], 1);
            if (p < HCAP) g_hits[(j * NKT + kt) * HCAP + p] = make_int2((kl << 13) | s, abits);
        }
        int oc = min(g_src_cnt[s], SRCCAP);
        for (int q = 0; q < oc; q++) {
            int packed = g_src_list[s * SRCCAP + q];
            int d = packed >> 13, cr = packed & 8191;
            int kt = d >> 6, kl = d & 63;
            int p = atomicAdd(&sc[kt], 1);
            if (p < HCAP) g_hits[(j * NKT + kt) * HCAP + p] = make_int2((kl << 13) | cr, abits);
        }
    }
    __syncthreads();
    if (t < NKT) g_hcnt[j * NKT + t] = min(sc[t], HCAP);
}

// ---------------- launch 5: layer-1 delta rows from hit lists ----------------
__global__ __launch_bounds__(256) void k_layer1(
    const float* __restrict__ plW, const float* __restrict__ plb)
{
    __shared__ float Hs[64 * 65];
    __shared__ int   sFlag[64];
    __shared__ int   flist[64];
    __shared__ unsigned char ipos[64];
    __shared__ int nf;

    const int kt = blockIdx.x;
    const int j  = blockIdx.y;
    const int t  = threadIdx.x;
    if (t == 0) nf = 0;
    if (t < 64) { sFlag[t] = 0; ipos[t] = 0xFF; }
    // zero Hs (scalar stores: stride-65 rows are not float4-aligned)
    for (int idx = t; idx < 64 * 65; idx += 256) Hs[idx] = 0.f;
    __syncthreads();

    const int seg = j * NKT + kt;
    const int ne = g_hcnt[seg];
    // scatter entries: 4 threads per entry, 16 channels each
    {
        const int sub = (t & 3) * 16;
        for (int idx = t >> 2; idx < ne; idx += 64) {
            int2 ent = g_hits[seg * HCAP + idx];
            int kl = ent.x >> 13, cr = ent.x & 8191;
            float a = __int_as_float(ent.y);
            const float4* fp = (const float4*)(g_feat + cr * C + sub);
            float* h = Hs + kl * 65 + sub;
#pragma unroll
            for (int q = 0; q < 4; q++) {
                float4 v = fp[q];
                atomicAdd(h + 4*q + 0, a * v.x);
                atomicAdd(h + 4*q + 1, a * v.y);
                atomicAdd(h + 4*q + 2, a * v.z);
                atomicAdd(h + 4*q + 3, a * v.w);
            }
            if ((t & 3) == 0) sFlag[kl] = 1;
        }
    }
    __syncthreads();
    if (t < 64 && sFlag[t]) { int p = atomicAdd(&nf, 1); flist[p] = t; }
    __syncthreads();
    const int n = nf;
    if (t < n) ipos[flist[t]] = (unsigned char)t;
    __syncthreads();
    if (t < 64) g_islot[seg * 64 + t] = ipos[t];

    const int c = t & 63;
    const float crc = fmaxf(plb[c], 0.f);
    const size_t segbase = (size_t)seg * 64 * 64;
    for (int idx = t >> 6; idx < n; idx += 4) {
        int row = flist[idx];
        float y = plb[c];
        const float* Hrow = Hs + row * 65;
#pragma unroll 16
        for (int m = 0; m < 64; m++) y += Hrow[m] * plW[m * 64 + c];
        g_delta[segbase + (size_t)idx * 64 + c] = fmaxf(y, 0.f) - crc;
    }
}

// ---------------- f32x2 GEMM phases ----------------
__device__ __forceinline__ void loadW4(float* Ws, const float* __restrict__ W, int nf4, int t) {
    const float4* src = (const float4*)W;
    float4* dst = (float4*)Ws;
    for (int idx = t; idx < nf4; idx += 256) dst[idx] = src[idx];
}

__device__ __forceinline__ void gemm64(
    const float* As, const float* Ws, const float* __restrict__ bias,
    float* Ps, int t, bool doRelu)
{
    const int r0 = (t >> 4) * 4;
    const int c0 = (t & 15) * 4;
    uint64_t b01 = *(const uint64_t*)(bias + c0);
    uint64_t b23 = *(const uint64_t*)(bias + c0 + 2);
    uint64_t acc[4][2];
#pragma unroll
    for (int r = 0; r < 4; r++) { acc[r][0] = b01; acc[r][1] = b23; }
#pragma unroll 4
    for (int m4 = 0; m4 < 64; m4 += 4) {
        float4 a4[4];
#pragma unroll
        for (int r = 0; r < 4; r++) a4[r] = *(const float4*)(As + (r0 + r) * HSTR + m4);
#pragma unroll
        for (int kk = 0; kk < 4; kk++) {
            uint64_t w0 = *(const uint64_t*)(Ws + (m4 + kk) * 64 + c0);
            uint64_t w1 = *(const uint64_t*)(Ws + (m4 + kk) * 64 + c0 + 2);
#pragma unroll
            for (int r = 0; r < 4; r++) {
                float av = (kk == 0) ? a4[r].x : (kk == 1) ? a4[r].y : (kk == 2) ? a4[r].z : a4[r].w;
                uint64_t aa = splat2(av);
                fma2(acc[r][0], aa, w0);
                fma2(acc[r][1], aa, w1);
            }
        }
    }
#pragma unroll
    for (int r = 0; r < 4; r++) {
        float4 v = make_float4(f2lo(acc[r][0]), f2hi(acc[r][0]),
                               f2lo(acc[r][1]), f2hi(acc[r][1]));
        if (doRelu) {
            v.x = fmaxf(v.x, 0.f); v.y = fmaxf(v.y, 0.f);
            v.z = fmaxf(v.z, 0.f); v.w = fmaxf(v.w, 0.f);
        }
        *(float4*)(Ps + (r0 + r) * HSTR + c0) = v;
    }
}

__device__ __forceinline__ void gemm32_out(
    const float* As, const float* Ws, const float* __restrict__ bias,
    float* outG, int t)
{
    const int r0 = (t >> 3) * 2;
    const int c0 = (t & 7) * 4;
    uint64_t b01 = *(const uint64_t*)(bias + c0);
    uint64_t b23 = *(const uint64_t*)(bias + c0 + 2);
    uint64_t acc[2][2];
#pragma unroll
    for (int r = 0; r < 2; r++) { acc[r][0] = b01; acc[r][1] = b23; }
#pragma unroll 4
    for (int m4 = 0; m4 < 64; m4 += 4) {
        float4 a4[2];
#pragma unroll
        for (int r = 0; r < 2; r++) a4[r] = *(const float4*)(As + (r0 + r) * HSTR + m4);
#pragma unroll
        for (int kk = 0; kk < 4; kk++) {
            uint64_t w0 = *(const uint64_t*)(Ws + (m4 + kk) * 32 + c0);
            uint64_t w1 = *(const uint64_t*)(Ws + (m4 + kk) * 32 + c0 + 2);
#pragma unroll
            for (int r = 0; r < 2; r++) {
                float av = (kk == 0) ? a4[r].x : (kk == 1) ? a4[r].y : (kk == 2) ? a4[r].z : a4[r].w;
                uint64_t aa = splat2(av);
                fma2(acc[r][0], aa, w0);
                fma2(acc[r][1], aa, w1);
            }
        }
    }
#pragma unroll
    for (int r = 0; r < 2; r++) {
        float4 v = make_float4(f2lo(acc[r][0]), f2hi(acc[r][0]),
                               f2lo(acc[r][1]), f2hi(acc[r][1]));
        *(float4*)(outG + (size_t)(r0 + r) * 32 + c0) = v;
    }
}

// ---------------- launch 6: layer 2 fused ----------------
__global__ __launch_bounds__(256) void k_layer2(
    const float* __restrict__ plb0,
    const float* __restrict__ plW, const float* __restrict__ plb,
    const float* __restrict__ oW1, const float* __restrict__ ob1,
    const float* __restrict__ oW2, const float* __restrict__ ob2,
    float* __restrict__ out)
{
    extern __shared__ float smem[];
    float* Hs = smem;                  // [64][HSTR]
    float* Gs = smem + 64 * HSTR;      // [64][HSTR]
    float* Ws = smem + 128 * HSTR;     // [64][64]

    const int i  = blockIdx.x;
    const int kt = blockIdx.y;
    const int t  = threadIdx.x;

    // Phase A: sync-free register gather via inverse slot map
    {
        const int kl  = t & 63;
        const int sub = (t >> 6) * 16;
        const float sI = g_srow[i];
        float4 acc[4];
#pragma unroll
        for (int q = 0; q < 4; q++) {
            float4 b = *(const float4*)(plb0 + sub + q * 4);
            acc[q] = make_float4(sI * fmaxf(b.x, 0.f), sI * fmaxf(b.y, 0.f),
                                 sI * fmaxf(b.z, 0.f), sI * fmaxf(b.w, 0.f));
        }
        const int rn = g_row_cnt[i];
        const int*   rc = g_row_col + i * 192;
        const float* rv = g_row_val + i * 192;
        for (int r = 0; r < rn; r++) {
            const int seg = rc[r] * NKT + kt;
            const unsigned slot = g_islot[seg * 64 + kl];
            if (slot != 0xFFu) {
                const float a = rv[r];
                const float4* dp = (const float4*)(g_delta + ((size_t)seg * 64 + slot) * 64 + sub);
#pragma unroll
                for (int q = 0; q < 4; q++) {
                    float4 v = dp[q];
                    acc[q].x += a * v.x; acc[q].y += a * v.y;
                    acc[q].z += a * v.z; acc[q].w += a * v.w;
                }
            }
        }
        float4* hp = (float4*)(Hs + kl * HSTR + sub);
#pragma unroll
        for (int q = 0; q < 4; q++) hp[q] = acc[q];
    }
    __syncthreads();

    // Phase B: Gs = relu(Hs @ plW1 + plb1)
    loadW4(Ws, plW, 1024, t);
    __syncthreads();
    gemm64(Hs, Ws, plb, Gs, t, true);
    __syncthreads();

    // Phase C: Hs = relu(Gs @ oW1 + ob1)
    loadW4(Ws, oW1, 1024, t);
    __syncthreads();
    gemm64(Gs, Ws, ob1, Hs, t, true);
    __syncthreads();

    // Phase D: out = Hs @ oW2 + ob2
    loadW4(Ws, oW2, 512, t);
    __syncthreads();
    gemm32_out(Hs, Ws, ob2, out + ((size_t)i * NTOT + (size_t)kt * 64) * 32, t);
}

// ---------------- launch ----------------
extern "C" void kernel_launch(void* const* d_in, const int* in_sizes, int n_in,
                              void* d_out, int out_size)
{
    const float* node_x = (const float*)d_in[0];
    const float* edge_x = (const float*)d_in[1];
    const float* face_x = (const float*)d_in[2];
    const float* nW1 = (const float*)d_in[3];  const float* nb1 = (const float*)d_in[4];
    const float* nW2 = (const float*)d_in[5];  const float* nb2 = (const float*)d_in[6];
    const float* eW1 = (const float*)d_in[7];  const float* eb1 = (const float*)d_in[8];
    const float* eW2 = (const float*)d_in[9];  const float* eb2 = (const float*)d_in[10];
    const float* fW1 = (const float*)d_in[11]; const float* fb1 = (const float*)d_in[12];
    const float* fW2 = (const float*)d_in[13]; const float* fb2 = (const float*)d_in[14];
    const float* oW1 = (const float*)d_in[15]; const float* ob1 = (const float*)d_in[16];
    const float* oW2 = (const float*)d_in[17]; const float* ob2 = (const float*)d_in[18];
    const float* plW = (const float*)d_in[19]; const float* plb = (const float*)d_in[20];
    const int* edge_index = (const int*)d_in[21];
    const int* face_nodes = (const int*)d_in[22];
    float* out = (float*)d_out;

    cudaFuncSetAttribute(k_layer2, cudaFuncAttributeMaxDynamicSharedMemorySize, SMEM_L2_BYTES);

    k_init<<<1472, 128>>>(node_x, edge_x, face_x, nW1, nb1, nW2, nb2,
                          eW1, eb1, eW2, eb2, fW1, fb1, fW2, fb2);
    k_edges<<<(ETOT + NTOT + 255) / 256, 256>>>(edge_index, face_nodes);
    k_scale_csr<<<NTOT, 256>>>();
    k_hits<<<NTOT, 256>>>();
    k_layer1<<<dim3(NKT, NTOT), 256>>>(plW, plb);
    k_layer2<<<dim3(NTOT, NKT), 256, SMEM_L2_BYTES>>>(plb, plW + 4096, plb + 64,
                                                      oW1, ob1, oW2, ob2, out);
    (void)in_sizes; (void)n_in; (void)out_size;
}

// round 11
// speedup vs baseline: 1.1906x; 1.1183x over previous
#include <cuda_runtime.h>
#include <cstdint>

#define NNODES 768
#define NFACES 256
#define NTOT   1024
#define E0     6144
#define EF     1536
#define ETOT   9216
#define C      64
#define NKT    16
#define SRCCAP 64
#define HCAP   128

// layer2 smem layout (floats)
#define L2_WF    0
#define L2_HS    20480
#define L2_GS    29184
#define L2_RV    37888
#define L2_RC    38080
#define L2_ISL   38272          // float index; 24576 bytes of uchar
#define SMEM_TC  (38272 * 4 + 24576)   // 177664 bytes

// ---------------- device scratch ----------------
__device__ float g_feat[(NTOT + E0) * C];
__device__ float g_adjn[NTOT * NTOT];
__device__ int   g_outcnt[NTOT];
__device__ float g_srow[NTOT];
__device__ int   g_row_cnt[NTOT];
__device__ int   g_row_col[NTOT * 192];
__device__ float g_row_val[NTOT * 192];
__device__ int   g_src_cnt[NTOT];
__device__ int   g_src_list[NTOT * SRCCAP];
__device__ int   g_hcnt[NTOT * NKT];
__device__ int2  g_hits[NTOT * NKT * HCAP];
__device__ float g_delta[67108864];
__device__ unsigned char g_islot[NTOT * NKT * 64];
__device__ float g_wfrag[20480];   // packed tf32 B-fragments: W1(hi,lo), oW1(hi,lo), oW2(hi,lo)

// ---------------- tf32 helpers ----------------
__device__ __forceinline__ uint32_t tf32h(float x) {
    uint32_t r; asm("cvt.rna.tf32.f32 %0, %1;" : "=r"(r) : "f"(x)); return r;
}
__device__ __forceinline__ void mma_tf32(float* d, uint32_t a0, uint32_t a1,
                                         uint32_t a2, uint32_t a3,
                                         uint32_t b0, uint32_t b1) {
    asm volatile(
        "mma.sync.aligned.m16n8k8.row.col.f32.tf32.tf32.f32 "
        "{%0,%1,%2,%3},{%4,%5,%6,%7},{%8,%9},{%0,%1,%2,%3};"
        : "+f"(d[0]), "+f"(d[1]), "+f"(d[2]), "+f"(d[3])
        : "r"(a0), "r"(a1), "r"(a2), "r"(a3), "r"(b0), "r"(b1));
}

// ---------------- embedding body ----------------
__device__ __forceinline__ void embed_body(
    const float* __restrict__ X, int blk, int R, int Din,
    const float* __restrict__ W1, const float* __restrict__ b1,
    const float* __restrict__ W2, const float* __restrict__ b2,
    float* __restrict__ Y, float* Xs, float* Hs)
{
    int r0 = blk * 16;
    int t = threadIdx.x;
    for (int idx = t; idx < 16 * Din; idx += 128) {
        int r = idx / Din, d = idx % Din;
        Xs[r * Din + d] = (r0 + r < R) ? X[(size_t)(r0 + r) * Din + d] : 0.f;
    }
    __syncthreads();
    int lr = t >> 3;
    int c0 = (t & 7) * 8;
    float h[8];
#pragma unroll
    for (int q = 0; q < 8; q++) h[q] = b1[c0 + q];
    for (int d = 0; d < Din; d++) {
        float x = Xs[lr * Din + d];
        const float* w = W1 + d * C + c0;
#pragma unroll
        for (int q = 0; q < 8; q++) h[q] += x * w[q];
    }
#pragma unroll
    for (int q = 0; q < 8; q++) Hs[lr * C + c0 + q] = fmaxf(h[q], 0.f);
    __syncthreads();
    float y[8];
#pragma unroll
    for (int q = 0; q < 8; q++) y[q] = b2[c0 + q];
    for (int m = 0; m < C; m++) {
        float hm = Hs[lr * C + m];
        const float* w = W2 + m * C + c0;
#pragma unroll
        for (int q = 0; q < 8; q++) y[q] += hm * w[q];
    }
    if (r0 + lr < R) {
        float* yo = Y + (size_t)(r0 + lr) * C + c0;
#pragma unroll
        for (int q = 0; q < 8; q++) yo[q] = fmaxf(y[q], 0.f);
    }
}

// ---------------- launch 1: embeds + zeroing + weight fragment prep ----------------
__global__ __launch_bounds__(128) void k_init(
    const float* __restrict__ node_x, const float* __restrict__ edge_x,
    const float* __restrict__ face_x,
    const float* __restrict__ nW1, const float* __restrict__ nb1,
    const float* __restrict__ nW2, const float* __restrict__ nb2,
    const float* __restrict__ eW1, const float* __restrict__ eb1,
    const float* __restrict__ eW2, const float* __restrict__ eb2,
    const float* __restrict__ fW1, const float* __restrict__ fb1,
    const float* __restrict__ fW2, const float* __restrict__ fb2,
    const float* __restrict__ plW1, const float* __restrict__ oW1,
    const float* __restrict__ oW2)
{
    __shared__ float Xs[16 * 144];
    __shared__ float Hs[16 * C];
    int b = blockIdx.x;
    int t = threadIdx.x;
    if (b < 48) {
        embed_body(node_x, b, NNODES, 144, nW1, nb1, nW2, nb2, g_feat, Xs, Hs);
    } else if (b < 432) {
        embed_body(edge_x, b - 48, E0, 144, eW1, eb1, eW2, eb2, g_feat + NTOT * C, Xs, Hs);
    } else if (b < 448) {
        embed_body(face_x, b - 432, NFACES, 12, fW1, fb1, fW2, fb2, g_feat + NNODES * C, Xs, Hs);
    } else {
        int z = b - 448;  // 0..1023
        float4 zv = make_float4(0.f, 0.f, 0.f, 0.f);
        float4* ap = (float4*)(g_adjn) + (size_t)z * 256 + t * 2;
        ap[0] = zv; ap[1] = zv;
        if (z == 0) {
            for (int q = 0; q < 8; q++) g_src_cnt[t * 8 + q] = 0;
        } else if (z == 1) {
            for (int q = 0; q < 8; q++) g_outcnt[t * 8 + q] = 0;
        } else if (z >= 2 && z < 6) {
            int4 z4 = make_int4(0, 0, 0, 0);
            int4* hp = (int4*)g_hcnt + (z - 2) * 1024 + t * 8;
#pragma unroll
            for (int q = 0; q < 8; q++) hp[q] = z4;
        } else if (z >= 6 && z < 9) {
            // pack weight w = z-6 into tf32 hi/lo B-fragment order
            int w = z - 6;
            const float* W = (w == 0) ? plW1 : (w == 1) ? oW1 : oW2;
            int Tn = (w == 2) ? 4 : 8;
            int Nd = Tn * 8;
            float* gh = g_wfrag + ((w == 0) ? 0 : (w == 1) ? 8192 : 16384);
            float* gl = gh + ((w == 2) ? 2048 : 4096);
            int total = 8 * Tn * 32;
            for (int idx = t; idx < total; idx += 128) {
                int kk = idx / (Tn * 32);
                int rem = idx - kk * Tn * 32;
                int tile = rem >> 5;
                int l = rem & 31;
                int k0 = kk * 8 + (l & 3);
                int n  = tile * 8 + (l >> 2);
                float v0 = W[k0 * Nd + n];
                float v1 = W[(k0 + 4) * Nd + n];
                uint32_t h0 = tf32h(v0);
                uint32_t h1 = tf32h(v1);
                uint32_t l0 = tf32h(v0 - __uint_as_float(h0));
                uint32_t l1 = tf32h(v1 - __uint_as_float(h1));
                gh[idx * 2]     = __uint_as_float(h0);
                gh[idx * 2 + 1] = __uint_as_float(h1);
                gl[idx * 2]     = __uint_as_float(l0);
                gl[idx * 2 + 1] = __uint_as_float(l1);
            }
        }
    }
}

// ---------------- launch 2: edges + diag + out-degree + src lists ----------------
__global__ void k_edges(const int* __restrict__ ei, const int* __restrict__ fn) {
    int e = blockIdx.x * blockDim.x + threadIdx.x;
    if (e >= ETOT + NTOT) return;
    if (e >= ETOT) {
        int i = e - ETOT;
        atomicAdd(&g_adjn[i * NTOT + i], 1.0f);
        return;
    }
    int s, d, cr;
    if (e < E0)            { s = ei[e]; d = ei[E0 + e]; cr = NTOT + e; }
    else if (e < E0 + EF)  { int q = e - E0; int f = q / 6; s = fn[q]; d = NNODES + f; cr = NNODES + f; }
    else                   { int r = e - (E0 + EF); int rr = 1535 - r; int f = rr / 6;
                             s = NNODES + f; d = fn[rr]; cr = NNODES + f; }
    atomicAdd(&g_adjn[s * NTOT + d], 1.0f);
    atomicAdd(&g_outcnt[s], 1);
    int p = atomicAdd(&g_src_cnt[s], 1);
    if (p < SRCCAP) g_src_list[s * SRCCAP + p] = (d << 13) | cr;
}

// ---------------- launch 3: scale + CSR + row sums ----------------
__global__ __launch_bounds__(256) void k_scale_csr() {
    int i = blockIdx.x;
    __shared__ int cnt;
    __shared__ float red[8];
    if (threadIdx.x == 0) cnt = 0;
    __syncthreads();
    float di = 1.f / sqrtf(1.f + (float)g_outcnt[i]);
    float sv = 0.f;
    for (int j = threadIdx.x; j < NTOT; j += 256) {
        float v = g_adjn[i * NTOT + j];
        if (v != 0.f) {
            float dj = 1.f / sqrtf(1.f + (float)g_outcnt[j]);
            v *= di * dj;
            sv += v;
            int p = atomicAdd(&cnt, 1);
            if (p < 192) { g_row_col[i * 192 + p] = j; g_row_val[i * 192 + p] = v; }
        }
    }
#pragma unroll
    for (int o = 16; o > 0; o >>= 1) sv += __shfl_down_sync(0xffffffffu, sv, o);
    if ((threadIdx.x & 31) == 0) red[threadIdx.x >> 5] = sv;
    __syncthreads();
    if (threadIdx.x == 0) {
        float tot = 0.f;
        for (int w = 0; w < 8; w++) tot += red[w];
        g_srow[i] = tot;
        g_row_cnt[i] = min(cnt, 192);
    }
}

// ---------------- launch 4: build per-(j,kt) hit lists ----------------
__global__ __launch_bounds__(256) void k_hits() {
    const int j = blockIdx.x;
    const int t = threadIdx.x;
    __shared__ int sc[NKT];
    if (t < NKT) sc[t] = 0;
    __syncthreads();
    const int rn = g_row_cnt[j];
    if (t < rn) {
        int s = g_row_col[j * 192 + t];
        int abits = __float_as_int(g_row_val[j * 192 + t]);
        {
            int kt = s >> 6, kl = s & 63;
            int p = atomicAdd(&sc[kt], 1);
            if (p < HCAP) g_hits[(j * NKT + kt) * HCAP + p] = make_int2((kl << 13) | s, abits);
        }
        int oc = min(g_src_cnt[s], SRCCAP);
        for (int q = 0; q < oc; q++) {
            int packed = g_src_list[s * SRCCAP + q];
            int d = packed >> 13, cr = packed & 8191;
            int kt = d >> 6, kl = d & 63;
            int p = atomicAdd(&sc[kt], 1);
            if (p < HCAP) g_hits[(j * NKT + kt) * HCAP + p] = make_int2((kl << 13) | cr, abits);
        }
    }
    __syncthreads();
    if (t < NKT) g_hcnt[j * NKT + t] = min(sc[t], HCAP);
}

// ---------------- launch 5: layer-1 delta rows from hit lists ----------------
__global__ __launch_bounds__(256) void k_layer1(
    const float* __restrict__ plW, const float* __restrict__ plb)
{
    __shared__ float Hs[64 * 65];
    __shared__ int   sFlag[64];
    __shared__ int   flist[64];
    __shared__ unsigned char ipos[64];
    __shared__ int nf;

    const int kt = blockIdx.x;
    const int j  = blockIdx.y;
    const int t  = threadIdx.x;
    if (t == 0) nf = 0;
    if (t < 64) { sFlag[t] = 0; ipos[t] = 0xFF; }
    for (int idx = t; idx < 64 * 65; idx += 256) Hs[idx] = 0.f;
    __syncthreads();

    const int seg = j * NKT + kt;
    const int ne = g_hcnt[seg];
    {
        const int sub = (t & 3) * 16;
        for (int idx = t >> 2; idx < ne; idx += 64) {
            int2 ent = g_hits[seg * HCAP + idx];
            int kl = ent.x >> 13, cr = ent.x & 8191;
            float a = __int_as_float(ent.y);
            const float4* fp = (const float4*)(g_feat + cr * C + sub);
            float* h = Hs + kl * 65 + sub;
#pragma unroll
            for (int q = 0; q < 4; q++) {
                float4 v = fp[q];
                atomicAdd(h + 4*q + 0, a * v.x);
                atomicAdd(h + 4*q + 1, a * v.y);
                atomicAdd(h + 4*q + 2, a * v.z);
                atomicAdd(h + 4*q + 3, a * v.w);
            }
            if ((t & 3) == 0) sFlag[kl] = 1;
        }
    }
    __syncthreads();
    if (t < 64 && sFlag[t]) { int p = atomicAdd(&nf, 1); flist[p] = t; }
    __syncthreads();
    const int n = nf;
    if (t < n) ipos[flist[t]] = (unsigned char)t;
    __syncthreads();
    if (t < 64) g_islot[seg * 64 + t] = ipos[t];

    const int c = t & 63;
    const float crc = fmaxf(plb[c], 0.f);
    const size_t segbase = (size_t)seg * 64 * 64;
    for (int idx = t >> 6; idx < n; idx += 4) {
        int row = flist[idx];
        float y = plb[c];
        const float* Hrow = Hs + row * 65;
#pragma unroll 16
        for (int m = 0; m < 64; m++) y += Hrow[m] * plW[m * 64 + c];
        g_delta[segbase + (size_t)idx * 64 + c] = fmaxf(y, 0.f) - crc;
    }
}

// ---------------- tensor-core GEMM phases (split-tf32, M=128) ----------------
__device__ __forceinline__ void gemm64_tc(
    const float* As, const float* Wh, const float* Wl,
    const float* __restrict__ bias, float* Ps, bool doRelu, int wid, int lane)
{
    const int wr = wid & 7;
    const int wc = wid >> 3;
    const int rbase = wr * 16 + (lane >> 2);
    const int cl = lane & 3;
    float acc[4][4];
#pragma unroll
    for (int a = 0; a < 4; a++)
#pragma unroll
        for (int b = 0; b < 4; b++) acc[a][b] = 0.f;
#pragma unroll
    for (int kk = 0; kk < 8; kk++) {
        int c0 = kk * 8 + cl;
        float a0f = As[rbase * 68 + c0];
        float a1f = As[(rbase + 8) * 68 + c0];
        float a2f = As[rbase * 68 + c0 + 4];
        float a3f = As[(rbase + 8) * 68 + c0 + 4];
        uint32_t ah0 = tf32h(a0f), ah1 = tf32h(a1f), ah2 = tf32h(a2f), ah3 = tf32h(a3f);
        uint32_t al0 = tf32h(a0f - __uint_as_float(ah0));
        uint32_t al1 = tf32h(a1f - __uint_as_float(ah1));
        uint32_t al2 = tf32h(a2f - __uint_as_float(ah2));
        uint32_t al3 = tf32h(a3f - __uint_as_float(ah3));
#pragma unroll
        for (int t4 = 0; t4 < 4; t4++) {
            int fo = ((kk * 8 + wc * 4 + t4) * 32 + lane) * 2;
            uint2 bh = *(const uint2*)(Wh + fo);
            uint2 bl = *(const uint2*)(Wl + fo);
            mma_tf32(acc[t4], ah0, ah1, ah2, ah3, bh.x, bh.y);
            mma_tf32(acc[t4], ah0, ah1, ah2, ah3, bl.x, bl.y);
            mma_tf32(acc[t4], al0, al1, al2, al3, bh.x, bh.y);
        }
    }
#pragma unroll
    for (int t4 = 0; t4 < 4; t4++) {
        int cg = (wc * 4 + t4) * 8 + cl * 2;
        float b0 = bias[cg], b1 = bias[cg + 1];
        float v0 = acc[t4][0] + b0, v1 = acc[t4][1] + b1;
        float v2 = acc[t4][2] + b0, v3 = acc[t4][3] + b1;
        if (doRelu) {
            v0 = fmaxf(v0, 0.f); v1 = fmaxf(v1, 0.f);
            v2 = fmaxf(v2, 0.f); v3 = fmaxf(v3, 0.f);
        }
        *(float2*)(Ps + rbase * 68 + cg)       = make_float2(v0, v1);
        *(float2*)(Ps + (rbase + 8) * 68 + cg) = make_float2(v2, v3);
    }
}

__device__ __forceinline__ void gemm32_tc(
    const float* As, const float* Wh, const float* Wl,
    const float* __restrict__ bias, float* outB, int wid, int lane)
{
    const int wr = wid & 7;
    const int wc = wid >> 3;
    const int rbase = wr * 16 + (lane >> 2);
    const int cl = lane & 3;
    float acc[2][4];
#pragma unroll
    for (int a = 0; a < 2; a++)
#pragma unroll
        for (int b = 0; b < 4; b++) acc[a][b] = 0.f;
#pragma unroll
    for (int kk = 0; kk < 8; kk++) {
        int c0 = kk * 8 + cl;
        float a0f = As[rbase * 68 + c0];
        float a1f = As[(rbase + 8) * 68 + c0];
        float a2f = As[rbase * 68 + c0 + 4];
        float a3f = As[(rbase + 8) * 68 + c0 + 4];
        uint32_t ah0 = tf32h(a0f), ah1 = tf32h(a1f), ah2 = tf32h(a2f), ah3 = tf32h(a3f);
        uint32_t al0 = tf32h(a0f - __uint_as_float(ah0));
        uint32_t al1 = tf32h(a1f - __uint_as_float(ah1));
        uint32_t al2 = tf32h(a2f - __uint_as_float(ah2));
        uint32_t al3 = tf32h(a3f - __uint_as_float(ah3));
#pragma unroll
        for (int t2 = 0; t2 < 2; t2++) {
            int fo = ((kk * 4 + wc * 2 + t2) * 32 + lane) * 2;
            uint2 bh = *(const uint2*)(Wh + fo);
            uint2 bl = *(const uint2*)(Wl + fo);
            mma_tf32(acc[t2], ah0, ah1, ah2, ah3, bh.x, bh.y);
            mma_tf32(acc[t2], ah0, ah1, ah2, ah3, bl.x, bl.y);
            mma_tf32(acc[t2], al0, al1, al2, al3, bh.x, bh.y);
        }
    }
#pragma unroll
    for (int t2 = 0; t2 < 2; t2++) {
        int cg = (wc * 2 + t2) * 8 + cl * 2;
        float b0 = bias[cg], b1 = bias[cg + 1];
        *(float2*)(outB + (size_t)rbase * 32 + cg) =
            make_float2(acc[t2][0] + b0, acc[t2][1] + b1);
        *(float2*)(outB + (size_t)(rbase + 8) * 32 + cg) =
            make_float2(acc[t2][2] + b0, acc[t2][3] + b1);
    }
}

// ---------------- launch 6: layer 2 (gather + split-tf32 tensor MLP) ----------------
__global__ __launch_bounds__(512) void k_layer2(
    const float* __restrict__ plb0,
    const float* __restrict__ plb1, const float* __restrict__ ob1,
    const float* __restrict__ ob2, float* __restrict__ out)
{
    extern __shared__ float sm[];
    float* Wf  = sm + L2_WF;
    float* Hs  = sm + L2_HS;
    float* Gs  = sm + L2_GS;
    float* rvS = sm + L2_RV;
    int*   rcS = (int*)(sm + L2_RC);
    unsigned char* islotS = (unsigned char*)(sm + L2_ISL);

    const int i    = blockIdx.x;
    const int half = blockIdx.y;
    const int t    = threadIdx.x;
    const int wid  = t >> 5;
    const int lane = t & 31;

    // copy packed weight fragments (20480 floats = 5120 float4)
    {
        const float4* src = (const float4*)g_wfrag;
        float4* dst = (float4*)Wf;
#pragma unroll
        for (int q = 0; q < 10; q++) dst[t + q * 512] = src[t + q * 512];
    }
    const int rn = g_row_cnt[i];
    if (t < rn) { rcS[t] = g_row_col[i * 192 + t]; rvS[t] = g_row_val[i * 192 + t]; }
    __syncthreads();

    const float sI = g_srow[i];

    for (int it = 0; it < 4; it++) {
        const int ktbase = half * 8 + it * 2;
        // stage islot bytes for the two kt tiles of this slab
        for (int idx = t; idx < rn * 32; idx += 512) {
            int r = idx >> 5, w = idx & 31;
            ((unsigned*)islotS)[r * 32 + w] =
                ((const unsigned*)g_islot)[(rcS[r] * 16 + ktbase) * 16 + w];
        }
        __syncthreads();

        // Phase A: Hs[row, :] (row 0..127)
        {
            const int row = t >> 2;
            const int sub = (t & 3) * 16;
            float4 acc[4];
#pragma unroll
            for (int q = 0; q < 4; q++) {
                float4 b = *(const float4*)(plb0 + sub + q * 4);
                acc[q] = make_float4(sI * fmaxf(b.x, 0.f), sI * fmaxf(b.y, 0.f),
                                     sI * fmaxf(b.z, 0.f), sI * fmaxf(b.w, 0.f));
            }
            const int ktoff = ktbase + (row >> 6);
            for (int r = 0; r < rn; r++) {
                unsigned slot = islotS[r * 128 + row];
                if (slot != 0xFFu) {
                    float a = rvS[r];
                    int seg = rcS[r] * 16 + ktoff;
                    const float4* dp = (const float4*)(g_delta + ((size_t)seg * 64 + slot) * 64 + sub);
#pragma unroll
                    for (int q = 0; q < 4; q++) {
                        float4 v = dp[q];
                        acc[q].x += a * v.x; acc[q].y += a * v.y;
                        acc[q].z += a * v.z; acc[q].w += a * v.w;
                    }
                }
            }
            float4* hp = (float4*)(Hs + row * 68 + sub);
#pragma unroll
            for (int q = 0; q < 4; q++) hp[q] = acc[q];
        }
        __syncthreads();

        // Phase B: Gs = relu(Hs @ plW1 + plb1)
        gemm64_tc(Hs, Wf, Wf + 4096, plb1, Gs, true, wid, lane);
        __syncthreads();
        // Phase C: Hs = relu(Gs @ oW1 + ob1)
        gemm64_tc(Gs, Wf + 8192, Wf + 12288, ob1, Hs, true, wid, lane);
        __syncthreads();
        // Phase D: out slab = Hs @ oW2 + ob2
        gemm32_tc(Hs, Wf + 16384, Wf + 18432, ob2,
                  out + ((size_t)i * NTOT + half * 512 + it * 128) * 32, wid, lane);
        __syncthreads();
    }
}

// ---------------- launch ----------------
extern "C" void kernel_launch(void* const* d_in, const int* in_sizes, int n_in,
                              void* d_out, int out_size)
{
    const float* node_x = (const float*)d_in[0];
    const float* edge_x = (const float*)d_in[1];
    const float* face_x = (const float*)d_in[2];
    const float* nW1 = (const float*)d_in[3];  const float* nb1 = (const float*)d_in[4];
    const float* nW2 = (const float*)d_in[5];  const float* nb2 = (const float*)d_in[6];
    const float* eW1 = (const float*)d_in[7];  const float* eb1 = (const float*)d_in[8];
    const float* eW2 = (const float*)d_in[9];  const float* eb2 = (const float*)d_in[10];
    const float* fW1 = (const float*)d_in[11]; const float* fb1 = (const float*)d_in[12];
    const float* fW2 = (const float*)d_in[13]; const float* fb2 = (const float*)d_in[14];
    const float* oW1 = (const float*)d_in[15]; const float* ob1 = (const float*)d_in[16];
    const float* oW2 = (const float*)d_in[17]; const float* ob2 = (const float*)d_in[18];
    const float* plW = (const float*)d_in[19]; const float* plb = (const float*)d_in[20];
    const int* edge_index = (const int*)d_in[21];
    const int* face_nodes = (const int*)d_in[22];
    float* out = (float*)d_out;

    cudaFuncSetAttribute(k_layer2, cudaFuncAttributeMaxDynamicSharedMemorySize, SMEM_TC);

    k_init<<<1472, 128>>>(node_x, edge_x, face_x, nW1, nb1, nW2, nb2,
                          eW1, eb1, eW2, eb2, fW1, fb1, fW2, fb2,
                          plW + 4096, oW1, oW2);
    k_edges<<<(ETOT + NTOT + 255) / 256, 256>>>(edge_index, face_nodes);
    k_scale_csr<<<NTOT, 256>>>();
    k_hits<<<NTOT, 256>>>();
    k_layer1<<<dim3(NKT, NTOT), 256>>>(plW, plb);
    k_layer2<<<dim3(NTOT, 2), 512, SMEM_TC>>>(plb, plb + 64, ob1, ob2, out);
    (void)in_sizes; (void)n_in; (void)out_size;
}

// round 12
// speedup vs baseline: 1.2011x; 1.0088x over previous
#include <cuda_runtime.h>
#include <cstdint>

#define NNODES 768
#define NFACES 256
#define NTOT   1024
#define E0     6144
#define EF     1536
#define ETOT   9216
#define C      64
#define NKT    16
#define SRCCAP 64
#define HCAP   128

// layer2 smem layout (floats)
#define L2_WF    0
#define L2_HS    20480
#define L2_GS    29184
#define L2_RV    37888
#define L2_RC    38080
#define L2_ISL   38272          // float index; 24576 bytes of uchar
#define SMEM_TC  (38272 * 4 + 24576)   // 177664 bytes

// ---------------- device scratch ----------------
__device__ float g_feat[(NTOT + E0) * C];
__device__ float g_adjn[NTOT * NTOT];
__device__ int   g_outcnt[NTOT];
__device__ float g_srow[NTOT];
__device__ int   g_row_cnt[NTOT];
__device__ int   g_row_col[NTOT * 192];
__device__ float g_row_val[NTOT * 192];
__device__ int   g_src_cnt[NTOT];
__device__ int   g_src_list[NTOT * SRCCAP];
__device__ int   g_hcnt[NTOT * NKT];
__device__ int2  g_hits[NTOT * NKT * HCAP];
__device__ float g_delta[67108864];
__device__ unsigned char g_islot[NTOT * NKT * 64];
// packed tf32 B-fragments: plW1(hi 0, lo 4096), oW1(8192,12288), oW2(16384,18432), plW0(20480,24576)
__device__ float g_wfrag[28672];

// ---------------- tf32 helpers ----------------
__device__ __forceinline__ uint32_t tf32h(float x) {
    uint32_t r; asm("cvt.rna.tf32.f32 %0, %1;" : "=r"(r) : "f"(x)); return r;
}
__device__ __forceinline__ void mma_tf32(float* d, uint32_t a0, uint32_t a1,
                                         uint32_t a2, uint32_t a3,
                                         uint32_t b0, uint32_t b1) {
    asm volatile(
        "mma.sync.aligned.m16n8k8.row.col.f32.tf32.tf32.f32 "
        "{%0,%1,%2,%3},{%4,%5,%6,%7},{%8,%9},{%0,%1,%2,%3};"
        : "+f"(d[0]), "+f"(d[1]), "+f"(d[2]), "+f"(d[3])
        : "r"(a0), "r"(a1), "r"(a2), "r"(a3), "r"(b0), "r"(b1));
}

// ---------------- embedding body ----------------
__device__ __forceinline__ void embed_body(
    const float* __restrict__ X, int blk, int R, int Din,
    const float* __restrict__ W1, const float* __restrict__ b1,
    const float* __restrict__ W2, const float* __restrict__ b2,
    float* __restrict__ Y, float* Xs, float* Hs)
{
    int r0 = blk * 16;
    int t = threadIdx.x;
    for (int idx = t; idx < 16 * Din; idx += 128) {
        int r = idx / Din, d = idx % Din;
        Xs[r * Din + d] = (r0 + r < R) ? X[(size_t)(r0 + r) * Din + d] : 0.f;
    }
    __syncthreads();
    int lr = t >> 3;
    int c0 = (t & 7) * 8;
    float h[8];
#pragma unroll
    for (int q = 0; q < 8; q++) h[q] = b1[c0 + q];
    for (int d = 0; d < Din; d++) {
        float x = Xs[lr * Din + d];
        const float* w = W1 + d * C + c0;
#pragma unroll
        for (int q = 0; q < 8; q++) h[q] += x * w[q];
    }
#pragma unroll
    for (int q = 0; q < 8; q++) Hs[lr * C + c0 + q] = fmaxf(h[q], 0.f);
    __syncthreads();
    float y[8];
#pragma unroll
    for (int q = 0; q < 8; q++) y[q] = b2[c0 + q];
    for (int m = 0; m < C; m++) {
        float hm = Hs[lr * C + m];
        const float* w = W2 + m * C + c0;
#pragma unroll
        for (int q = 0; q < 8; q++) y[q] += hm * w[q];
    }
    if (r0 + lr < R) {
        float* yo = Y + (size_t)(r0 + lr) * C + c0;
#pragma unroll
        for (int q = 0; q < 8; q++) yo[q] = fmaxf(y[q], 0.f);
    }
}

// ---------------- launch 1: embeds + zeroing + weight fragment prep ----------------
__global__ __launch_bounds__(128) void k_init(
    const float* __restrict__ node_x, const float* __restrict__ edge_x,
    const float* __restrict__ face_x,
    const float* __restrict__ nW1, const float* __restrict__ nb1,
    const float* __restrict__ nW2, const float* __restrict__ nb2,
    const float* __restrict__ eW1, const float* __restrict__ eb1,
    const float* __restrict__ eW2, const float* __restrict__ eb2,
    const float* __restrict__ fW1, const float* __restrict__ fb1,
    const float* __restrict__ fW2, const float* __restrict__ fb2,
    const float* __restrict__ plW0, const float* __restrict__ plW1,
    const float* __restrict__ oW1, const float* __restrict__ oW2)
{
    __shared__ float Xs[16 * 144];
    __shared__ float Hs[16 * C];
    int b = blockIdx.x;
    int t = threadIdx.x;
    if (b < 48) {
        embed_body(node_x, b, NNODES, 144, nW1, nb1, nW2, nb2, g_feat, Xs, Hs);
    } else if (b < 432) {
        embed_body(edge_x, b - 48, E0, 144, eW1, eb1, eW2, eb2, g_feat + NTOT * C, Xs, Hs);
    } else if (b < 448) {
        embed_body(face_x, b - 432, NFACES, 12, fW1, fb1, fW2, fb2, g_feat + NNODES * C, Xs, Hs);
    } else {
        int z = b - 448;  // 0..1023
        float4 zv = make_float4(0.f, 0.f, 0.f, 0.f);
        float4* ap = (float4*)(g_adjn) + (size_t)z * 256 + t * 2;
        ap[0] = zv; ap[1] = zv;
        if (z == 0) {
            for (int q = 0; q < 8; q++) g_src_cnt[t * 8 + q] = 0;
        } else if (z == 1) {
            for (int q = 0; q < 8; q++) g_outcnt[t * 8 + q] = 0;
        } else if (z >= 2 && z < 6) {
            int4 z4 = make_int4(0, 0, 0, 0);
            int4* hp = (int4*)g_hcnt + (z - 2) * 1024 + t * 8;
#pragma unroll
            for (int q = 0; q < 8; q++) hp[q] = z4;
        } else if (z >= 6 && z < 10) {
            // pack weight w = z-6 into tf32 hi/lo B-fragment order
            int w = z - 6;
            const float* W = (w == 0) ? plW1 : (w == 1) ? oW1 : (w == 2) ? oW2 : plW0;
            int Tn = (w == 2) ? 4 : 8;
            int Nd = Tn * 8;
            float* gh = g_wfrag + ((w == 0) ? 0 : (w == 1) ? 8192 : (w == 2) ? 16384 : 20480);
            float* gl = gh + ((w == 2) ? 2048 : 4096);
            int total = 8 * Tn * 32;
            for (int idx = t; idx < total; idx += 128) {
                int kk = idx / (Tn * 32);
                int rem = idx - kk * Tn * 32;
                int tile = rem >> 5;
                int l = rem & 31;
                int k0 = kk * 8 + (l & 3);
                int n  = tile * 8 + (l >> 2);
                float v0 = W[k0 * Nd + n];
                float v1 = W[(k0 + 4) * Nd + n];
                uint32_t h0 = tf32h(v0);
                uint32_t h1 = tf32h(v1);
                uint32_t l0 = tf32h(v0 - __uint_as_float(h0));
                uint32_t l1 = tf32h(v1 - __uint_as_float(h1));
                gh[idx * 2]     = __uint_as_float(h0);
                gh[idx * 2 + 1] = __uint_as_float(h1);
                gl[idx * 2]     = __uint_as_float(l0);
                gl[idx * 2 + 1] = __uint_as_float(l1);
            }
        }
    }
}

// ---------------- launch 2: edges + diag + out-degree + src lists ----------------
__global__ void k_edges(const int* __restrict__ ei, const int* __restrict__ fn) {
    int e = blockIdx.x * blockDim.x + threadIdx.x;
    if (e >= ETOT + NTOT) return;
    if (e >= ETOT) {
        int i = e - ETOT;
        atomicAdd(&g_adjn[i * NTOT + i], 1.0f);
        return;
    }
    int s, d, cr;
    if (e < E0)            { s = ei[e]; d = ei[E0 + e]; cr = NTOT + e; }
    else if (e < E0 + EF)  { int q = e - E0; int f = q / 6; s = fn[q]; d = NNODES + f; cr = NNODES + f; }
    else                   { int r = e - (E0 + EF); int rr = 1535 - r; int f = rr / 6;
                             s = NNODES + f; d = fn[rr]; cr = NNODES + f; }
    atomicAdd(&g_adjn[s * NTOT + d], 1.0f);
    atomicAdd(&g_outcnt[s], 1);
    int p = atomicAdd(&g_src_cnt[s], 1);
    if (p < SRCCAP) g_src_list[s * SRCCAP + p] = (d << 13) | cr;
}

// ---------------- launch 3: scale + CSR + row sums ----------------
__global__ __launch_bounds__(256) void k_scale_csr() {
    int i = blockIdx.x;
    __shared__ int cnt;
    __shared__ float red[8];
    if (threadIdx.x == 0) cnt = 0;
    __syncthreads();
    float di = 1.f / sqrtf(1.f + (float)g_outcnt[i]);
    float sv = 0.f;
    for (int j = threadIdx.x; j < NTOT; j += 256) {
        float v = g_adjn[i * NTOT + j];
        if (v != 0.f) {
            float dj = 1.f / sqrtf(1.f + (float)g_outcnt[j]);
            v *= di * dj;
            sv += v;
            int p = atomicAdd(&cnt, 1);
            if (p < 192) { g_row_col[i * 192 + p] = j; g_row_val[i * 192 + p] = v; }
        }
    }
#pragma unroll
    for (int o = 16; o > 0; o >>= 1) sv += __shfl_down_sync(0xffffffffu, sv, o);
    if ((threadIdx.x & 31) == 0) red[threadIdx.x >> 5] = sv;
    __syncthreads();
    if (threadIdx.x == 0) {
        float tot = 0.f;
        for (int w = 0; w < 8; w++) tot += red[w];
        g_srow[i] = tot;
        g_row_cnt[i] = min(cnt, 192);
    }
}

// ---------------- launch 4: build per-(j,kt) hit lists ----------------
__global__ __launch_bounds__(256) void k_hits() {
    const int j = blockIdx.x;
    const int t = threadIdx.x;
    __shared__ int sc[NKT];
    if (t < NKT) sc[t] = 0;
    __syncthreads();
    const int rn = g_row_cnt[j];
    if (t < rn) {
        int s = g_row_col[j * 192 + t];
        int abits = __float_as_int(g_row_val[j * 192 + t]);
        {
            int kt = s >> 6, kl = s & 63;
            int p = atomicAdd(&sc[kt], 1);
            if (p < HCAP) g_hits[(j * NKT + kt) * HCAP + p] = make_int2((kl << 13) | s, abits);
        }
        int oc = min(g_src_cnt[s], SRCCAP);
        for (int q = 0; q < oc; q++) {
            int packed = g_src_list[s * SRCCAP + q];
            int d = packed >> 13, cr = packed & 8191;
            int kt = d >> 6, kl = d & 63;
            int p = atomicAdd(&sc[kt], 1);
            if (p < HCAP) g_hits[(j * NKT + kt) * HCAP + p] = make_int2((kl << 13) | cr, abits);
        }
    }
    __syncthreads();
    if (t < NKT) g_hcnt[j * NKT + t] = min(sc[t], HCAP);
}

// ---------------- launch 5: layer-1 deltas (scatter + split-tf32 mma epilogue) ----------------
__global__ __launch_bounds__(256) void k_layer1(const float* __restrict__ plb)
{
    __shared__ float Hs[64 * 65];
    __shared__ int   sFlag[64];
    __shared__ int   flist[64];
    __shared__ unsigned char ipos[64];
    __shared__ int nf;

    const int kt = blockIdx.x;
    const int j  = blockIdx.y;
    const int t  = threadIdx.x;
    if (t == 0) nf = 0;
    if (t < 64) { sFlag[t] = 0; ipos[t] = 0xFF; }
    for (int idx = t; idx < 64 * 65; idx += 256) Hs[idx] = 0.f;
    __syncthreads();

    const int seg = j * NKT + kt;
    const int ne = g_hcnt[seg];
    {
        const int sub = (t & 3) * 16;
        for (int idx = t >> 2; idx < ne; idx += 64) {
            int2 ent = g_hits[seg * HCAP + idx];
            int kl = ent.x >> 13, cr = ent.x & 8191;
            float a = __int_as_float(ent.y);
            const float4* fp = (const float4*)(g_feat + cr * C + sub);
            float* h = Hs + kl * 65 + sub;
#pragma unroll
            for (int q = 0; q < 4; q++) {
                float4 v = fp[q];
                atomicAdd(h + 4*q + 0, a * v.x);
                atomicAdd(h + 4*q + 1, a * v.y);
                atomicAdd(h + 4*q + 2, a * v.z);
                atomicAdd(h + 4*q + 3, a * v.w);
            }
            if ((t & 3) == 0) sFlag[kl] = 1;
        }
    }
    __syncthreads();
    if (t < 64 && sFlag[t]) { int p = atomicAdd(&nf, 1); flist[p] = t; }
    __syncthreads();
    const int n = nf;
    if (t < n) ipos[flist[t]] = (unsigned char)t;
    __syncthreads();
    if (t < 64) g_islot[seg * 64 + t] = ipos[t];

    // ---- split-tf32 mma epilogue: D[m,:] = relu(Hs[flist[m],:] @ plW0 + plb0) - crc ----
    const int wid = t >> 5, lane = t & 31;
    const int mt = wid >> 1;          // m-tile 0..3 (16 rows each)
    const int ch = wid & 1;           // N half (32 cols)
    if (mt * 16 < n) {
        const int r0 = lane >> 2;
        const int cl = lane & 3;
        const int m0 = mt * 16 + r0;
        const int m1 = m0 + 8;
        const int fr0 = (m0 < n) ? flist[m0] : -1;
        const int fr1 = (m1 < n) ? flist[m1] : -1;
        const float* Wh = g_wfrag + 20480;
        const float* Wl = g_wfrag + 24576;
        float acc[4][4];
#pragma unroll
        for (int a = 0; a < 4; a++)
#pragma unroll
            for (int b2 = 0; b2 < 4; b2++) acc[a][b2] = 0.f;
#pragma unroll
        for (int kk = 0; kk < 8; kk++) {
            int c0 = kk * 8 + cl;
            float a0f = (fr0 >= 0) ? Hs[fr0 * 65 + c0] : 0.f;
            float a1f = (fr1 >= 0) ? Hs[fr1 * 65 + c0] : 0.f;
            float a2f = (fr0 >= 0) ? Hs[fr0 * 65 + c0 + 4] : 0.f;
            float a3f = (fr1 >= 0) ? Hs[fr1 * 65 + c0 + 4] : 0.f;
            uint32_t ah0 = tf32h(a0f), ah1 = tf32h(a1f), ah2 = tf32h(a2f), ah3 = tf32h(a3f);
            uint32_t al0 = tf32h(a0f - __uint_as_float(ah0));
            uint32_t al1 = tf32h(a1f - __uint_as_float(ah1));
            uint32_t al2 = tf32h(a2f - __uint_as_float(ah2));
            uint32_t al3 = tf32h(a3f - __uint_as_float(ah3));
#pragma unroll
            for (int t4 = 0; t4 < 4; t4++) {
                int fo = ((kk * 8 + ch * 4 + t4) * 32 + lane) * 2;
                uint2 bh = *(const uint2*)(Wh + fo);
                uint2 bl = *(const uint2*)(Wl + fo);
                mma_tf32(acc[t4], ah0, ah1, ah2, ah3, bh.x, bh.y);
                mma_tf32(acc[t4], ah0, ah1, ah2, ah3, bl.x, bl.y);
                mma_tf32(acc[t4], al0, al1, al2, al3, bh.x, bh.y);
            }
        }
        const size_t segbase = (size_t)seg * 4096;
#pragma unroll
        for (int t4 = 0; t4 < 4; t4++) {
            int cg = (ch * 4 + t4) * 8 + cl * 2;
            float b0 = plb[cg], b1 = plb[cg + 1];
            float crc0 = fmaxf(b0, 0.f), crc1 = fmaxf(b1, 0.f);
            if (m0 < n) {
                *(float2*)(g_delta + segbase + (size_t)m0 * 64 + cg) =
                    make_float2(fmaxf(acc[t4][0] + b0, 0.f) - crc0,
                                fmaxf(acc[t4][1] + b1, 0.f) - crc1);
            }
            if (m1 < n) {
                *(float2*)(g_delta + segbase + (size_t)m1 * 64 + cg) =
                    make_float2(fmaxf(acc[t4][2] + b0, 0.f) - crc0,
                                fmaxf(acc[t4][3] + b1, 0.f) - crc1);
            }
        }
    }
}

// ---------------- tensor-core GEMM phases (split-tf32, M=128) ----------------
__device__ __forceinline__ void gemm64_tc(
    const float* As, const float* Wh, const float* Wl,
    const float* __restrict__ bias, float* Ps, bool doRelu, int wid, int lane)
{
    const int wr = wid & 7;
    const int wc = wid >> 3;
    const int rbase = wr * 16 + (lane >> 2);
    const int cl = lane & 3;
    float acc[4][4];
#pragma unroll
    for (int a = 0; a < 4; a++)
#pragma unroll
        for (int b = 0; b < 4; b++) acc[a][b] = 0.f;
#pragma unroll
    for (int kk = 0; kk < 8; kk++) {
        int c0 = kk * 8 + cl;
        float a0f = As[rbase * 68 + c0];
        float a1f = As[(rbase + 8) * 68 + c0];
        float a2f = As[rbase * 68 + c0 + 4];
        float a3f = As[(rbase + 8) * 68 + c0 + 4];
        uint32_t ah0 = tf32h(a0f), ah1 = tf32h(a1f), ah2 = tf32h(a2f), ah3 = tf32h(a3f);
        uint32_t al0 = tf32h(a0f - __uint_as_float(ah0));
        uint32_t al1 = tf32h(a1f - __uint_as_float(ah1));
        uint32_t al2 = tf32h(a2f - __uint_as_float(ah2));
        uint32_t al3 = tf32h(a3f - __uint_as_float(ah3));
#pragma unroll
        for (int t4 = 0; t4 < 4; t4++) {
            int fo = ((kk * 8 + wc * 4 + t4) * 32 + lane) * 2;
            uint2 bh = *(const uint2*)(Wh + fo);
            uint2 bl = *(const uint2*)(Wl + fo);
            mma_tf32(acc[t4], ah0, ah1, ah2, ah3, bh.x, bh.y);
            mma_tf32(acc[t4], ah0, ah1, ah2, ah3, bl.x, bl.y);
            mma_tf32(acc[t4], al0, al1, al2, al3, bh.x, bh.y);
        }
    }
#pragma unroll
    for (int t4 = 0; t4 < 4; t4++) {
        int cg = (wc * 4 + t4) * 8 + cl * 2;
        float b0 = bias[cg], b1 = bias[cg + 1];
        float v0 = acc[t4][0] + b0, v1 = acc[t4][1] + b1;
        float v2 = acc[t4][2] + b0, v3 = acc[t4][3] + b1;
        if (doRelu) {
            v0 = fmaxf(v0, 0.f); v1 = fmaxf(v1, 0.f);
            v2 = fmaxf(v2, 0.f); v3 = fmaxf(v3, 0.f);
        }
        *(float2*)(Ps + rbase * 68 + cg)       = make_float2(v0, v1);
        *(float2*)(Ps + (rbase + 8) * 68 + cg) = make_float2(v2, v3);
    }
}

__device__ __forceinline__ void gemm32_tc(
    const float* As, const float* Wh, const float* Wl,
    const float* __restrict__ bias, float* outB, int wid, int lane)
{
    const int wr = wid & 7;
    const int wc = wid >> 3;
    const int rbase = wr * 16 + (lane >> 2);
    const int cl = lane & 3;
    float acc[2][4];
#pragma unroll
    for (int a = 0; a < 2; a++)
#pragma unroll
        for (int b = 0; b < 4; b++) acc[a][b] = 0.f;
#pragma unroll
    for (int kk = 0; kk < 8; kk++) {
        int c0 = kk * 8 + cl;
        float a0f = As[rbase * 68 + c0];
        float a1f = As[(rbase + 8) * 68 + c0];
        float a2f = As[rbase * 68 + c0 + 4];
        float a3f = As[(rbase + 8) * 68 + c0 + 4];
        uint32_t ah0 = tf32h(a0f), ah1 = tf32h(a1f), ah2 = tf32h(a2f), ah3 = tf32h(a3f);
        uint32_t al0 = tf32h(a0f - __uint_as_float(ah0));
        uint32_t al1 = tf32h(a1f - __uint_as_float(ah1));
        uint32_t al2 = tf32h(a2f - __uint_as_float(ah2));
        uint32_t al3 = tf32h(a3f - __uint_as_float(ah3));
#pragma unroll
        for (int t2 = 0; t2 < 2; t2++) {
            int fo = ((kk * 4 + wc * 2 + t2) * 32 + lane) * 2;
            uint2 bh = *(const uint2*)(Wh + fo);
            uint2 bl = *(const uint2*)(Wl + fo);
            mma_tf32(acc[t2], ah0, ah1, ah2, ah3, bh.x, bh.y);
            mma_tf32(acc[t2], ah0, ah1, ah2, ah3, bl.x, bl.y);
            mma_tf32(acc[t2], al0, al1, al2, al3, bh.x, bh.y);
        }
    }
#pragma unroll
    for (int t2 = 0; t2 < 2; t2++) {
        int cg = (wc * 2 + t2) * 8 + cl * 2;
        float b0 = bias[cg], b1 = bias[cg + 1];
        *(float2*)(outB + (size_t)rbase * 32 + cg) =
            make_float2(acc[t2][0] + b0, acc[t2][1] + b1);
        *(float2*)(outB + (size_t)(rbase + 8) * 32 + cg) =
            make_float2(acc[t2][2] + b0, acc[t2][3] + b1);
    }
}

// ---------------- launch 6: layer 2 (gather + split-tf32 tensor MLP) ----------------
__global__ __launch_bounds__(512) void k_layer2(
    const float* __restrict__ plb0,
    const float* __restrict__ plb1, const float* __restrict__ ob1,
    const float* __restrict__ ob2, float* __restrict__ out)
{
    extern __shared__ float sm[];
    float* Wf  = sm + L2_WF;
    float* Hs  = sm + L2_HS;
    float* Gs  = sm + L2_GS;
    float* rvS = sm + L2_RV;
    int*   rcS = (int*)(sm + L2_RC);
    unsigned char* islotS = (unsigned char*)(sm + L2_ISL);

    const int i    = blockIdx.x;
    const int half = blockIdx.y;
    const int t    = threadIdx.x;
    const int wid  = t >> 5;
    const int lane = t & 31;

    // copy packed weight fragments (20480 floats = 5120 float4)
    {
        const float4* src = (const float4*)g_wfrag;
        float4* dst = (float4*)Wf;
#pragma unroll
        for (int q = 0; q < 10; q++) dst[t + q * 512] = src[t + q * 512];
    }
    const int rn = g_row_cnt[i];
    if (t < rn) { rcS[t] = g_row_col[i * 192 + t]; rvS[t] = g_row_val[i * 192 + t]; }
    __syncthreads();

    const float sI = g_srow[i];

    for (int it = 0; it < 4; it++) {
        const int ktbase = half * 8 + it * 2;
        for (int idx = t; idx < rn * 32; idx += 512) {
            int r = idx >> 5, w = idx & 31;
            ((unsigned*)islotS)[r * 32 + w] =
                ((const unsigned*)g_islot)[(rcS[r] * 16 + ktbase) * 16 + w];
        }
        __syncthreads();

        // Phase A: Hs[row, :] (row 0..127)
        {
            const int row = t >> 2;
            const int sub = (t & 3) * 16;
            float4 acc[4];
#pragma unroll
            for (int q = 0; q < 4; q++) {
                float4 b = *(const float4*)(plb0 + sub + q * 4);
                acc[q] = make_float4(sI * fmaxf(b.x, 0.f), sI * fmaxf(b.y, 0.f),
                                     sI * fmaxf(b.z, 0.f), sI * fmaxf(b.w, 0.f));
            }
            const int ktoff = ktbase + (row >> 6);
            for (int r = 0; r < rn; r++) {
                unsigned slot = islotS[r * 128 + row];
                if (slot != 0xFFu) {
                    float a = rvS[r];
                    int seg = rcS[r] * 16 + ktoff;
                    const float4* dp = (const float4*)(g_delta + ((size_t)seg * 64 + slot) * 64 + sub);
#pragma unroll
                    for (int q = 0; q < 4; q++) {
                        float4 v = dp[q];
                        acc[q].x += a * v.x; acc[q].y += a * v.y;
                        acc[q].z += a * v.z; acc[q].w += a * v.w;
                    }
                }
            }
            float4* hp = (float4*)(Hs + row * 68 + sub);
#pragma unroll
            for (int q = 0; q < 4; q++) hp[q] = acc[q];
        }
        __syncthreads();

        gemm64_tc(Hs, Wf, Wf + 4096, plb1, Gs, true, wid, lane);
        __syncthreads();
        gemm64_tc(Gs, Wf + 8192, Wf + 12288, ob1, Hs, true, wid, lane);
        __syncthreads();
        gemm32_tc(Hs, Wf + 16384, Wf + 18432, ob2,
                  out + ((size_t)i * NTOT + half * 512 + it * 128) * 32, wid, lane);
        __syncthreads();
    }
}

// ---------------- launch ----------------
extern "C" void kernel_launch(void* const* d_in, const int* in_sizes, int n_in,
                              void* d_out, int out_size)
{
    const float* node_x = (const float*)d_in[0];
    const float* edge_x = (const float*)d_in[1];
    const float* face_x = (const float*)d_in[2];
    const float* nW1 = (const float*)d_in[3];  const float* nb1 = (const float*)d_in[4];
    const float* nW2 = (const float*)d_in[5];  const float* nb2 = (const float*)d_in[6];
    const float* eW1 = (const float*)d_in[7];  const float* eb1 = (const float*)d_in[8];
    const float* eW2 = (const float*)d_in[9];  const float* eb2 = (const float*)d_in[10];
    const float* fW1 = (const float*)d_in[11]; const float* fb1 = (const float*)d_in[12];
    const float* fW2 = (const float*)d_in[13]; const float* fb2 = (const float*)d_in[14];
    const float* oW1 = (const float*)d_in[15]; const float* ob1 = (const float*)d_in[16];
    const float* oW2 = (const float*)d_in[17]; const float* ob2 = (const float*)d_in[18];
    const float* plW = (const float*)d_in[19]; const float* plb = (const float*)d_in[20];
    const int* edge_index = (const int*)d_in[21];
    const int* face_nodes = (const int*)d_in[22];
    float* out = (float*)d_out;

    cudaFuncSetAttribute(k_layer2, cudaFuncAttributeMaxDynamicSharedMemorySize, SMEM_TC);

    k_init<<<1472, 128>>>(node_x, edge_x, face_x, nW1, nb1, nW2, nb2,
                          eW1, eb1, eW2, eb2, fW1, fb1, fW2, fb2,
                          plW, plW + 4096, oW1, oW2);
    k_edges<<<(ETOT + NTOT + 255) / 256, 256>>>(edge_index, face_nodes);
    k_scale_csr<<<NTOT, 256>>>();
    k_hits<<<NTOT, 256>>>();
    k_layer1<<<dim3(NKT, NTOT), 256>>>(plb);
    k_layer2<<<dim3(NTOT, 2), 512, SMEM_TC>>>(plb, plb + 64, ob1, ob2, out);
    (void)in_sizes; (void)n_in; (void)out_size;
}

// round 13
// speedup vs baseline: 1.4552x; 1.2115x over previous
#include <cuda_runtime.h>
#include <cuda_bf16.h>
#include <cstdint>

#define NNODES 768
#define NFACES 256
#define NTOT   1024
#define E0     6144
#define EF     1536
#define ETOT   9216
#define C      64
#define NKT    16
#define SRCCAP 64
#define HCAP   128

typedef uint32_t U32;

// layer2 smem layout (u32 units)
#define L2U_W    0        // 10240 u32 bf16 fragments
#define L2U_AHI  10240    // 128 x 36
#define L2U_ALO  14848
#define L2U_BHI  19456
#define L2U_BLO  24064
#define L2U_RV   28672    // 192 floats
#define L2U_RC   28864    // 192 ints
#define L2U_ISL  29056    // 6144 u32 = 24576 bytes uchar
#define SMEM_TC  ((29056 + 6144) * 4)   // 140800 bytes

// ---------------- device scratch ----------------
__device__ float g_feat[(NTOT + E0) * C];
__device__ float g_adjn[NTOT * NTOT];
__device__ int   g_outcnt[NTOT];
__device__ float g_srow[NTOT];
__device__ int   g_row_cnt[NTOT];
__device__ int   g_row_col[NTOT * 192];
__device__ float g_row_val[NTOT * 192];
__device__ int   g_src_cnt[NTOT];
__device__ int   g_src_list[NTOT * SRCCAP];
__device__ int   g_hcnt[NTOT * NKT];
__device__ int2  g_hits[NTOT * NKT * HCAP];
__device__ float g_delta[67108864];
__device__ unsigned char g_islot[NTOT * NKT * 64];
// bf16 B-fragments: plW1 hi 0 / lo 2048, oW1 4096/6144, oW2 8192/9216 (u32 units)
// tf32 B-fragments for plW0 (layer1): hi 10240, lo 14336
__device__ float g_wfrag[18432];

// ---------------- helpers ----------------
__device__ __forceinline__ uint32_t tf32h(float x) {
    uint32_t r; asm("cvt.rna.tf32.f32 %0, %1;" : "=r"(r) : "f"(x)); return r;
}
__device__ __forceinline__ void mma_tf32(float* d, uint32_t a0, uint32_t a1,
                                         uint32_t a2, uint32_t a3,
                                         uint32_t b0, uint32_t b1) {
    asm volatile(
        "mma.sync.aligned.m16n8k8.row.col.f32.tf32.tf32.f32 "
        "{%0,%1,%2,%3},{%4,%5,%6,%7},{%8,%9},{%0,%1,%2,%3};"
        : "+f"(d[0]), "+f"(d[1]), "+f"(d[2]), "+f"(d[3])
        : "r"(a0), "r"(a1), "r"(a2), "r"(a3), "r"(b0), "r"(b1));
}
__device__ __forceinline__ void mma_bf16(float* d, U32 a0, U32 a1, U32 a2, U32 a3,
                                         U32 b0, U32 b1) {
    asm volatile(
        "mma.sync.aligned.m16n8k16.row.col.f32.bf16.bf16.f32 "
        "{%0,%1,%2,%3},{%4,%5,%6,%7},{%8,%9},{%0,%1,%2,%3};"
        : "+f"(d[0]), "+f"(d[1]), "+f"(d[2]), "+f"(d[3])
        : "r"(a0), "r"(a1), "r"(a2), "r"(a3), "r"(b0), "r"(b1));
}
__device__ __forceinline__ void packpair(float x, float y, U32& h, U32& l) {
    __nv_bfloat16 hx = __float2bfloat16(x);
    __nv_bfloat16 hy = __float2bfloat16(y);
    h = (U32)__bfloat16_as_ushort(hx) | ((U32)__bfloat16_as_ushort(hy) << 16);
    float rx = x - __bfloat162float(hx);
    float ry = y - __bfloat162float(hy);
    __nv_bfloat16 lx = __float2bfloat16(rx);
    __nv_bfloat16 ly = __float2bfloat16(ry);
    l = (U32)__bfloat16_as_ushort(lx) | ((U32)__bfloat16_as_ushort(ly) << 16);
}

// ---------------- embedding body ----------------
__device__ __forceinline__ void embed_body(
    const float* __restrict__ X, int blk, int R, int Din,
    const float* __restrict__ W1, const float* __restrict__ b1,
    const float* __restrict__ W2, const float* __restrict__ b2,
    float* __restrict__ Y, float* Xs, float* Hs)
{
    int r0 = blk * 16;
    int t = threadIdx.x;
    for (int idx = t; idx < 16 * Din; idx += 128) {
        int r = idx / Din, d = idx % Din;
        Xs[r * Din + d] = (r0 + r < R) ? X[(size_t)(r0 + r) * Din + d] : 0.f;
    }
    __syncthreads();
    int lr = t >> 3;
    int c0 = (t & 7) * 8;
    float h[8];
#pragma unroll
    for (int q = 0; q < 8; q++) h[q] = b1[c0 + q];
    for (int d = 0; d < Din; d++) {
        float x = Xs[lr * Din + d];
        const float* w = W1 + d * C + c0;
#pragma unroll
        for (int q = 0; q < 8; q++) h[q] += x * w[q];
    }
#pragma unroll
    for (int q = 0; q < 8; q++) Hs[lr * C + c0 + q] = fmaxf(h[q], 0.f);
    __syncthreads();
    float y[8];
#pragma unroll
    for (int q = 0; q < 8; q++) y[q] = b2[c0 + q];
    for (int m = 0; m < C; m++) {
        float hm = Hs[lr * C + m];
        const float* w = W2 + m * C + c0;
#pragma unroll
        for (int q = 0; q < 8; q++) y[q] += hm * w[q];
    }
    if (r0 + lr < R) {
        float* yo = Y + (size_t)(r0 + lr) * C + c0;
#pragma unroll
        for (int q = 0; q < 8; q++) yo[q] = fmaxf(y[q], 0.f);
    }
}

// ---------------- launch 1: embeds + zeroing + weight fragment prep ----------------
__global__ __launch_bounds__(128) void k_init(
    const float* __restrict__ node_x, const float* __restrict__ edge_x,
    const float* __restrict__ face_x,
    const float* __restrict__ nW1, const float* __restrict__ nb1,
    const float* __restrict__ nW2, const float* __restrict__ nb2,
    const float* __restrict__ eW1, const float* __restrict__ eb1,
    const float* __restrict__ eW2, const float* __restrict__ eb2,
    const float* __restrict__ fW1, const float* __restrict__ fb1,
    const float* __restrict__ fW2, const float* __restrict__ fb2,
    const float* __restrict__ plW0, const float* __restrict__ plW1,
    const float* __restrict__ oW1, const float* __restrict__ oW2)
{
    __shared__ float Xs[16 * 144];
    __shared__ float Hs[16 * C];
    int b = blockIdx.x;
    int t = threadIdx.x;
    if (b < 48) {
        embed_body(node_x, b, NNODES, 144, nW1, nb1, nW2, nb2, g_feat, Xs, Hs);
    } else if (b < 432) {
        embed_body(edge_x, b - 48, E0, 144, eW1, eb1, eW2, eb2, g_feat + NTOT * C, Xs, Hs);
    } else if (b < 448) {
        embed_body(face_x, b - 432, NFACES, 12, fW1, fb1, fW2, fb2, g_feat + NNODES * C, Xs, Hs);
    } else {
        int z = b - 448;  // 0..1023
        float4 zv = make_float4(0.f, 0.f, 0.f, 0.f);
        float4* ap = (float4*)(g_adjn) + (size_t)z * 256 + t * 2;
        ap[0] = zv; ap[1] = zv;
        if (z == 0) {
            for (int q = 0; q < 8; q++) g_src_cnt[t * 8 + q] = 0;
        } else if (z == 1) {
            for (int q = 0; q < 8; q++) g_outcnt[t * 8 + q] = 0;
        } else if (z >= 2 && z < 6) {
            int4 z4 = make_int4(0, 0, 0, 0);
            int4* hp = (int4*)g_hcnt + (z - 2) * 1024 + t * 8;
#pragma unroll
            for (int q = 0; q < 8; q++) hp[q] = z4;
        } else if (z >= 6 && z < 9) {
            // bf16 hi/lo fragment pack for layer-2 weights (m16n8k16)
            int w = z - 6;
            const float* W = (w == 0) ? plW1 : (w == 1) ? oW1 : oW2;
            int Tn = (w == 2) ? 4 : 8;
            int Nd = Tn * 8;
            U32* gh = (U32*)g_wfrag + ((w == 0) ? 0 : (w == 1) ? 4096 : 8192);
            U32* gl = gh + ((w == 2) ? 1024 : 2048);
            int total = 4 * Tn * 32;
            for (int idx = t; idx < total; idx += 128) {
                int kk = idx / (Tn * 32);
                int rem = idx - kk * Tn * 32;
                int tile = rem >> 5;
                int l = rem & 31;
                int n  = tile * 8 + (l >> 2);
                int k0 = kk * 16 + (l & 3) * 2;
                U32 h0, l0, h1, l1;
                packpair(W[k0 * Nd + n], W[(k0 + 1) * Nd + n], h0, l0);
                packpair(W[(k0 + 8) * Nd + n], W[(k0 + 9) * Nd + n], h1, l1);
                gh[idx * 2] = h0; gh[idx * 2 + 1] = h1;
                gl[idx * 2] = l0; gl[idx * 2 + 1] = l1;
            }
        } else if (z == 9) {
            // tf32 hi/lo fragment pack for plW0 (layer-1 epilogue, m16n8k8)
            const float* W = plW0;
            float* gh = g_wfrag + 10240;
            float* gl = g_wfrag + 14336;
            for (int idx = t; idx < 2048; idx += 128) {
                int kk = idx >> 8;               // /256
                int rem = idx & 255;
                int tile = rem >> 5;
                int l = rem & 31;
                int k0 = kk * 8 + (l & 3);
                int n  = tile * 8 + (l >> 2);
                float v0 = W[k0 * 64 + n];
                float v1 = W[(k0 + 4) * 64 + n];
                uint32_t h0 = tf32h(v0);
                uint32_t h1 = tf32h(v1);
                uint32_t l0 = tf32h(v0 - __uint_as_float(h0));
                uint32_t l1 = tf32h(v1 - __uint_as_float(h1));
                gh[idx * 2]     = __uint_as_float(h0);
                gh[idx * 2 + 1] = __uint_as_float(h1);
                gl[idx * 2]     = __uint_as_float(l0);
                gl[idx * 2 + 1] = __uint_as_float(l1);
            }
        }
    }
}

// ---------------- launch 2: edges + diag + out-degree + src lists ----------------
__global__ void k_edges(const int* __restrict__ ei, const int* __restrict__ fn) {
    int e = blockIdx.x * blockDim.x + threadIdx.x;
    if (e >= ETOT + NTOT) return;
    if (e >= ETOT) {
        int i = e - ETOT;
        atomicAdd(&g_adjn[i * NTOT + i], 1.0f);
        return;
    }
    int s, d, cr;
    if (e < E0)            { s = ei[e]; d = ei[E0 + e]; cr = NTOT + e; }
    else if (e < E0 + EF)  { int q = e - E0; int f = q / 6; s = fn[q]; d = NNODES + f; cr = NNODES + f; }
    else                   { int r = e - (E0 + EF); int rr = 1535 - r; int f = rr / 6;
                             s = NNODES + f; d = fn[rr]; cr = NNODES + f; }
    atomicAdd(&g_adjn[s * NTOT + d], 1.0f);
    atomicAdd(&g_outcnt[s], 1);
    int p = atomicAdd(&g_src_cnt[s], 1);
    if (p < SRCCAP) g_src_list[s * SRCCAP + p] = (d << 13) | cr;
}

// ---------------- launch 3: scale + CSR + row sums ----------------
__global__ __launch_bounds__(256) void k_scale_csr() {
    int i = blockIdx.x;
    __shared__ int cnt;
    __shared__ float red[8];
    if (threadIdx.x == 0) cnt = 0;
    __syncthreads();
    float di = 1.f / sqrtf(1.f + (float)g_outcnt[i]);
    float sv = 0.f;
    for (int j = threadIdx.x; j < NTOT; j += 256) {
        float v = g_adjn[i * NTOT + j];
        if (v != 0.f) {
            float dj = 1.f / sqrtf(1.f + (float)g_outcnt[j]);
            v *= di * dj;
            sv += v;
            int p = atomicAdd(&cnt, 1);
            if (p < 192) { g_row_col[i * 192 + p] = j; g_row_val[i * 192 + p] = v; }
        }
    }
#pragma unroll
    for (int o = 16; o > 0; o >>= 1) sv += __shfl_down_sync(0xffffffffu, sv, o);
    if ((threadIdx.x & 31) == 0) red[threadIdx.x >> 5] = sv;
    __syncthreads();
    if (threadIdx.x == 0) {
        float tot = 0.f;
        for (int w = 0; w < 8; w++) tot += red[w];
        g_srow[i] = tot;
        g_row_cnt[i] = min(cnt, 192);
    }
}

// ---------------- launch 4: build per-(j,kt) hit lists ----------------
__global__ __launch_bounds__(256) void k_hits() {
    const int j = blockIdx.x;
    const int t = threadIdx.x;
    __shared__ int sc[NKT];
    if (t < NKT) sc[t] = 0;
    __syncthreads();
    const int rn = g_row_cnt[j];
    if (t < rn) {
        int s = g_row_col[j * 192 + t];
        int abits = __float_as_int(g_row_val[j * 192 + t]);
        {
            int kt = s >> 6, kl = s & 63;
            int p = atomicAdd(&sc[kt], 1);
            if (p < HCAP) g_hits[(j * NKT + kt) * HCAP + p] = make_int2((kl << 13) | s, abits);
        }
        int oc = min(g_src_cnt[s], SRCCAP);
        for (int q = 0; q < oc; q++) {
            int packed = g_src_list[s * SRCCAP + q];
            int d = packed >> 13, cr = packed & 8191;
            int kt = d >> 6, kl = d & 63;
            int p = atomicAdd(&sc[kt], 1);
            if (p < HCAP) g_hits[(j * NKT + kt) * HCAP + p] = make_int2((kl << 13) | cr, abits);
        }
    }
    __syncthreads();
    if (t < NKT) g_hcnt[j * NKT + t] = min(sc[t], HCAP);
}

// ---------------- launch 5: layer-1 deltas (scatter + split-tf32 mma epilogue) ----------------
__global__ __launch_bounds__(256) void k_layer1(const float* __restrict__ plb)
{
    __shared__ float Hs[64 * 65];
    __shared__ int   sFlag[64];
    __shared__ int   flist[64];
    __shared__ unsigned char ipos[64];
    __shared__ int nf;

    const int kt = blockIdx.x;
    const int j  = blockIdx.y;
    const int t  = threadIdx.x;
    if (t == 0) nf = 0;
    if (t < 64) { sFlag[t] = 0; ipos[t] = 0xFF; }
    for (int idx = t; idx < 64 * 65; idx += 256) Hs[idx] = 0.f;
    __syncthreads();

    const int seg = j * NKT + kt;
    const int ne = g_hcnt[seg];
    {
        const int sub = (t & 3) * 16;
        for (int idx = t >> 2; idx < ne; idx += 64) {
            int2 ent = g_hits[seg * HCAP + idx];
            int kl = ent.x >> 13, cr = ent.x & 8191;
            float a = __int_as_float(ent.y);
            const float4* fp = (const float4*)(g_feat + cr * C + sub);
            float* h = Hs + kl * 65 + sub;
#pragma unroll
            for (int q = 0; q < 4; q++) {
                float4 v = fp[q];
                atomicAdd(h + 4*q + 0, a * v.x);
                atomicAdd(h + 4*q + 1, a * v.y);
                atomicAdd(h + 4*q + 2, a * v.z);
                atomicAdd(h + 4*q + 3, a * v.w);
            }
            if ((t & 3) == 0) sFlag[kl] = 1;
        }
    }
    __syncthreads();
    if (t < 64 && sFlag[t]) { int p = atomicAdd(&nf, 1); flist[p] = t; }
    __syncthreads();
    const int n = nf;
    if (t < n) ipos[flist[t]] = (unsigned char)t;
    __syncthreads();
    if (t < 64) g_islot[seg * 64 + t] = ipos[t];

    // split-tf32 mma epilogue
    const int wid = t >> 5, lane = t & 31;
    const int mt = wid >> 1;
    const int ch = wid & 1;
    if (mt * 16 < n) {
        const int r0 = lane >> 2;
        const int cl = lane & 3;
        const int m0 = mt * 16 + r0;
        const int m1 = m0 + 8;
        const int fr0 = (m0 < n) ? flist[m0] : -1;
        const int fr1 = (m1 < n) ? flist[m1] : -1;
        const float* Wh = g_wfrag + 10240;
        const float* Wl = g_wfrag + 14336;
        float acc[4][4];
#pragma unroll
        for (int a = 0; a < 4; a++)
#pragma unroll
            for (int b2 = 0; b2 < 4; b2++) acc[a][b2] = 0.f;
#pragma unroll
        for (int kk = 0; kk < 8; kk++) {
            int c0 = kk * 8 + cl;
            float a0f = (fr0 >= 0) ? Hs[fr0 * 65 + c0] : 0.f;
            float a1f = (fr1 >= 0) ? Hs[fr1 * 65 + c0] : 0.f;
            float a2f = (fr0 >= 0) ? Hs[fr0 * 65 + c0 + 4] : 0.f;
            float a3f = (fr1 >= 0) ? Hs[fr1 * 65 + c0 + 4] : 0.f;
            uint32_t ah0 = tf32h(a0f), ah1 = tf32h(a1f), ah2 = tf32h(a2f), ah3 = tf32h(a3f);
            uint32_t al0 = tf32h(a0f - __uint_as_float(ah0));
            uint32_t al1 = tf32h(a1f - __uint_as_float(ah1));
            uint32_t al2 = tf32h(a2f - __uint_as_float(ah2));
            uint32_t al3 = tf32h(a3f - __uint_as_float(ah3));
#pragma unroll
            for (int t4 = 0; t4 < 4; t4++) {
                int fo = ((kk * 8 + ch * 4 + t4) * 32 + lane) * 2;
                uint2 bh = *(const uint2*)(Wh + fo);
                uint2 bl = *(const uint2*)(Wl + fo);
                mma_tf32(acc[t4], ah0, ah1, ah2, ah3, bh.x, bh.y);
                mma_tf32(acc[t4], ah0, ah1, ah2, ah3, bl.x, bl.y);
                mma_tf32(acc[t4], al0, al1, al2, al3, bh.x, bh.y);
            }
        }
        const size_t segbase = (size_t)seg * 4096;
#pragma unroll
        for (int t4 = 0; t4 < 4; t4++) {
            int cg = (ch * 4 + t4) * 8 + cl * 2;
            float b0 = plb[cg], b1 = plb[cg + 1];
            float crc0 = fmaxf(b0, 0.f), crc1 = fmaxf(b1, 0.f);
            if (m0 < n) {
                *(float2*)(g_delta + segbase + (size_t)m0 * 64 + cg) =
                    make_float2(fmaxf(acc[t4][0] + b0, 0.f) - crc0,
                                fmaxf(acc[t4][1] + b1, 0.f) - crc1);
            }
            if (m1 < n) {
                *(float2*)(g_delta + segbase + (size_t)m1 * 64 + cg) =
                    make_float2(fmaxf(acc[t4][2] + b0, 0.f) - crc0,
                                fmaxf(acc[t4][3] + b1, 0.f) - crc1);
            }
        }
    }
}

// ---------------- bf16 split GEMM phases (M=128, packed operands) ----------------
__device__ __forceinline__ void gemm64_bf(
    const U32* AHi, const U32* ALo, const U32* WHi, const U32* WLo,
    const float* __restrict__ bias, U32* PHi, U32* PLo, int wid, int lane)
{
    const int wr = wid & 7;
    const int wc = wid >> 3;
    const int rb = wr * 16 + (lane >> 2);
    const int cl = lane & 3;
    float acc[4][4];
#pragma unroll
    for (int a = 0; a < 4; a++)
#pragma unroll
        for (int b = 0; b < 4; b++) acc[a][b] = 0.f;
#pragma unroll
    for (int kk = 0; kk < 4; kk++) {
        const int ai = kk * 8 + cl;
        U32 ah0 = AHi[rb * 36 + ai],       ah1 = AHi[(rb + 8) * 36 + ai];
        U32 ah2 = AHi[rb * 36 + ai + 4],   ah3 = AHi[(rb + 8) * 36 + ai + 4];
        U32 al0 = ALo[rb * 36 + ai],       al1 = ALo[(rb + 8) * 36 + ai];
        U32 al2 = ALo[rb * 36 + ai + 4],   al3 = ALo[(rb + 8) * 36 + ai + 4];
#pragma unroll
        for (int t4 = 0; t4 < 4; t4++) {
            int fo = ((kk * 8 + wc * 4 + t4) * 32 + lane) * 2;
            uint2 bh = *(const uint2*)(WHi + fo);
            uint2 bl = *(const uint2*)(WLo + fo);
            mma_bf16(acc[t4], ah0, ah1, ah2, ah3, bh.x, bh.y);
            mma_bf16(acc[t4], ah0, ah1, ah2, ah3, bl.x, bl.y);
            mma_bf16(acc[t4], al0, al1, al2, al3, bh.x, bh.y);
        }
    }
#pragma unroll
    for (int t4 = 0; t4 < 4; t4++) {
        int cg = (wc * 4 + t4) * 8 + cl * 2;
        int pi = (wc * 4 + t4) * 4 + cl;
        float b0 = bias[cg], b1 = bias[cg + 1];
        float v0 = fmaxf(acc[t4][0] + b0, 0.f), v1 = fmaxf(acc[t4][1] + b1, 0.f);
        float v2 = fmaxf(acc[t4][2] + b0, 0.f), v3 = fmaxf(acc[t4][3] + b1, 0.f);
        U32 h, l;
        packpair(v0, v1, h, l);
        PHi[rb * 36 + pi] = h; PLo[rb * 36 + pi] = l;
        packpair(v2, v3, h, l);
        PHi[(rb + 8) * 36 + pi] = h; PLo[(rb + 8) * 36 + pi] = l;
    }
}

__device__ __forceinline__ void gemm32_bf(
    const U32* AHi, const U32* ALo, const U32* WHi, const U32* WLo,
    const float* __restrict__ bias, float* outB, int wid, int lane)
{
    const int wr = wid & 7;
    const int wc = wid >> 3;
    const int rb = wr * 16 + (lane >> 2);
    const int cl = lane & 3;
    float acc[2][4];
#pragma unroll
    for (int a = 0; a < 2; a++)
#pragma unroll
        for (int b = 0; b < 4; b++) acc[a][b] = 0.f;
#pragma unroll
    for (int kk = 0; kk < 4; kk++) {
        const int ai = kk * 8 + cl;
        U32 ah0 = AHi[rb * 36 + ai],       ah1 = AHi[(rb + 8) * 36 + ai];
        U32 ah2 = AHi[rb * 36 + ai + 4],   ah3 = AHi[(rb + 8) * 36 + ai + 4];
        U32 al0 = ALo[rb * 36 + ai],       al1 = ALo[(rb + 8) * 36 + ai];
        U32 al2 = ALo[rb * 36 + ai + 4],   al3 = ALo[(rb + 8) * 36 + ai + 4];
#pragma unroll
        for (int t2 = 0; t2 < 2; t2++) {
            int fo = ((kk * 4 + wc * 2 + t2) * 32 + lane) * 2;
            uint2 bh = *(const uint2*)(WHi + fo);
            uint2 bl = *(const uint2*)(WLo + fo);
            mma_bf16(acc[t2], ah0, ah1, ah2, ah3, bh.x, bh.y);
            mma_bf16(acc[t2], ah0, ah1, ah2, ah3, bl.x, bl.y);
            mma_bf16(acc[t2], al0, al1, al2, al3, bh.x, bh.y);
        }
    }
#pragma unroll
    for (int t2 = 0; t2 < 2; t2++) {
        int cg = (wc * 2 + t2) * 8 + cl * 2;
        float b0 = bias[cg], b1 = bias[cg + 1];
        *(float2*)(outB + (size_t)rb * 32 + cg) =
            make_float2(acc[t2][0] + b0, acc[t2][1] + b1);
        *(float2*)(outB + (size_t)(rb + 8) * 32 + cg) =
            make_float2(acc[t2][2] + b0, acc[t2][3] + b1);
    }
}

// ---------------- launch 6: layer 2 (gather + split-bf16 tensor MLP) ----------------
__global__ __launch_bounds__(512) void k_layer2(
    const float* __restrict__ plb0,
    const float* __restrict__ plb1, const float* __restrict__ ob1,
    const float* __restrict__ ob2, float* __restrict__ out)
{
    extern __shared__ U32 su[];
    U32* Wf  = su + L2U_W;
    U32* AHi = su + L2U_AHI;
    U32* ALo = su + L2U_ALO;
    U32* BHi = su + L2U_BHI;
    U32* BLo = su + L2U_BLO;
    float* rvS = (float*)(su + L2U_RV);
    int*   rcS = (int*)(su + L2U_RC);
    unsigned char* islotS = (unsigned char*)(su + L2U_ISL);

    const int i    = blockIdx.x;
    const int half = blockIdx.y;
    const int t    = threadIdx.x;
    const int wid  = t >> 5;
    const int lane = t & 31;

    // copy bf16 weight fragments (10240 u32 = 2560 uint4)
    {
        const uint4* src = (const uint4*)g_wfrag;
        uint4* dst = (uint4*)Wf;
#pragma unroll
        for (int q = 0; q < 5; q++) dst[t + q * 512] = src[t + q * 512];
    }
    const int rn = g_row_cnt[i];
    if (t < rn) { rcS[t] = g_row_col[i * 192 + t]; rvS[t] = g_row_val[i * 192 + t]; }
    __syncthreads();

    const float sI = g_srow[i];

    for (int it = 0; it < 4; it++) {
        const int ktbase = half * 8 + it * 2;
        for (int idx = t; idx < rn * 32; idx += 512) {
            int r = idx >> 5, w = idx & 31;
            ((unsigned*)islotS)[r * 32 + w] =
                ((const unsigned*)g_islot)[(rcS[r] * 16 + ktbase) * 16 + w];
        }
        __syncthreads();

        // Phase A: gather fp32, pack hi/lo bf16 pairs into AHi/ALo
        {
            const int row = t >> 2;
            const int sub = (t & 3) * 16;
            float4 acc[4];
#pragma unroll
            for (int q = 0; q < 4; q++) {
                float4 b = *(const float4*)(plb0 + sub + q * 4);
                acc[q] = make_float4(sI * fmaxf(b.x, 0.f), sI * fmaxf(b.y, 0.f),
                                     sI * fmaxf(b.z, 0.f), sI * fmaxf(b.w, 0.f));
            }
            const int ktoff = ktbase + (row >> 6);
            for (int r = 0; r < rn; r++) {
                unsigned slot = islotS[r * 128 + row];
                if (slot != 0xFFu) {
                    float a = rvS[r];
                    int seg = rcS[r] * 16 + ktoff;
                    const float4* dp = (const float4*)(g_delta + ((size_t)seg * 64 + slot) * 64 + sub);
#pragma unroll
                    for (int q = 0; q < 4; q++) {
                        float4 v = dp[q];
                        acc[q].x += a * v.x; acc[q].y += a * v.y;
                        acc[q].z += a * v.z; acc[q].w += a * v.w;
                    }
                }
            }
            U32* hp = AHi + row * 36 + (sub >> 1);
            U32* lp = ALo + row * 36 + (sub >> 1);
#pragma unroll
            for (int q = 0; q < 4; q++) {
                U32 h, l;
                packpair(acc[q].x, acc[q].y, h, l);
                hp[2 * q] = h; lp[2 * q] = l;
                packpair(acc[q].z, acc[q].w, h, l);
                hp[2 * q + 1] = h; lp[2 * q + 1] = l;
            }
        }
        __syncthreads();

        // Phase B: Bbuf = relu(A @ plW1 + plb1)
        gemm64_bf(AHi, ALo, Wf, Wf + 2048, plb1, BHi, BLo, wid, lane);
        __syncthreads();
        // Phase C: Abuf = relu(Bbuf @ oW1 + ob1)
        gemm64_bf(BHi, BLo, Wf + 4096, Wf + 6144, ob1, AHi, ALo, wid, lane);
        __syncthreads();
        // Phase D: out slab = Abuf @ oW2 + ob2
        gemm32_bf(AHi, ALo, Wf + 8192, Wf + 9216, ob2,
                  out + ((size_t)i * NTOT + half * 512 + it * 128) * 32, wid, lane);
        __syncthreads();
    }
}

// ---------------- launch ----------------
extern "C" void kernel_launch(void* const* d_in, const int* in_sizes, int n_in,
                              void* d_out, int out_size)
{
    const float* node_x = (const float*)d_in[0];
    const float* edge_x = (const float*)d_in[1];
    const float* face_x = (const float*)d_in[2];
    const float* nW1 = (const float*)d_in[3];  const float* nb1 = (const float*)d_in[4];
    const float* nW2 = (const float*)d_in[5];  const float* nb2 = (const float*)d_in[6];
    const float* eW1 = (const float*)d_in[7];  const float* eb1 = (const float*)d_in[8];
    const float* eW2 = (const float*)d_in[9];  const float* eb2 = (const float*)d_in[10];
    const float* fW1 = (const float*)d_in[11]; const float* fb1 = (const float*)d_in[12];
    const float* fW2 = (const float*)d_in[13]; const float* fb2 = (const float*)d_in[14];
    const float* oW1 = (const float*)d_in[15]; const float* ob1 = (const float*)d_in[16];
    const float* oW2 = (const float*)d_in[17]; const float* ob2 = (const float*)d_in[18];
    const float* plW = (const float*)d_in[19]; const float* plb = (const float*)d_in[20];
    const int* edge_index = (const int*)d_in[21];
    const int* face_nodes = (const int*)d_in[22];
    float* out = (float*)d_out;

    cudaFuncSetAttribute(k_layer2, cudaFuncAttributeMaxDynamicSharedMemorySize, SMEM_TC);

    k_init<<<1472, 128>>>(node_x, edge_x, face_x, nW1, nb1, nW2, nb2,
                          eW1, eb1, eW2, eb2, fW1, fb1, fW2, fb2,
                          plW, plW + 4096, oW1, oW2);
    k_edges<<<(ETOT + NTOT + 255) / 256, 256>>>(edge_index, face_nodes);
    k_scale_csr<<<NTOT, 256>>>();
    k_hits<<<NTOT, 256>>>();
    k_layer1<<<dim3(NKT, NTOT), 256>>>(plb);
    k_layer2<<<dim3(NTOT, 2), 512, SMEM_TC>>>(plb, plb + 64, ob1, ob2, out);
    (void)in_sizes; (void)n_in; (void)out_size;
}

// round 14
// speedup vs baseline: 1.8287x; 1.2567x over previous
#include <cuda_runtime.h>
#include <cuda_bf16.h>
#include <cstdint>

#define NNODES 768
#define NFACES 256
#define NTOT   1024
#define E0     6144
#define EF     1536
#define ETOT   9216
#define C      64
#define NKT    16
#define SRCCAP 64
#define HCAP   128

typedef uint32_t U32;

// layer2 smem layout (u32 units) — in-place GEMMs, no B buffers
#define L2U_W    0        // 10240 u32 bf16 fragments
#define L2U_AHI  10240    // 128 x 36
#define L2U_ALO  14848    // 128 x 36
#define L2U_RV   19456    // 192 floats
#define L2U_RC   19648    // 192 ints
#define L2U_ISL  19840    // 6144 u32 = 24576 bytes uchar
#define SMEM_TC  ((19840 + 6144) * 4)   // 103936 bytes -> 2 blocks/SM

// ---------------- device scratch ----------------
__device__ float g_feat[(NTOT + E0) * C];
__device__ float g_adjn[NTOT * NTOT];
__device__ int   g_outcnt[NTOT];
__device__ float g_srow[NTOT];
__device__ int   g_row_cnt[NTOT];
__device__ int   g_row_col[NTOT * 192];
__device__ float g_row_val[NTOT * 192];
__device__ int   g_src_cnt[NTOT];
__device__ int   g_src_list[NTOT * SRCCAP];
__device__ int   g_hcnt[NTOT * NKT];
__device__ int2  g_hits[NTOT * NKT * HCAP];
__device__ float g_delta[67108864];
__device__ unsigned char g_islot[NTOT * NKT * 64];
// bf16 B-fragments: plW1 hi 0 / lo 2048, oW1 4096/6144, oW2 8192/9216 (u32 units)
// tf32 B-fragments for plW0 (layer1): hi 10240, lo 14336
__device__ float g_wfrag[18432];

// ---------------- helpers ----------------
__device__ __forceinline__ uint32_t tf32h(float x) {
    uint32_t r; asm("cvt.rna.tf32.f32 %0, %1;" : "=r"(r) : "f"(x)); return r;
}
__device__ __forceinline__ void mma_tf32(float* d, uint32_t a0, uint32_t a1,
                                         uint32_t a2, uint32_t a3,
                                         uint32_t b0, uint32_t b1) {
    asm volatile(
        "mma.sync.aligned.m16n8k8.row.col.f32.tf32.tf32.f32 "
        "{%0,%1,%2,%3},{%4,%5,%6,%7},{%8,%9},{%0,%1,%2,%3};"
        : "+f"(d[0]), "+f"(d[1]), "+f"(d[2]), "+f"(d[3])
        : "r"(a0), "r"(a1), "r"(a2), "r"(a3), "r"(b0), "r"(b1));
}
__device__ __forceinline__ void mma_bf16(float* d, U32 a0, U32 a1, U32 a2, U32 a3,
                                         U32 b0, U32 b1) {
    asm volatile(
        "mma.sync.aligned.m16n8k16.row.col.f32.bf16.bf16.f32 "
        "{%0,%1,%2,%3},{%4,%5,%6,%7},{%8,%9},{%0,%1,%2,%3};"
        : "+f"(d[0]), "+f"(d[1]), "+f"(d[2]), "+f"(d[3])
        : "r"(a0), "r"(a1), "r"(a2), "r"(a3), "r"(b0), "r"(b1));
}
__device__ __forceinline__ void packpair(float x, float y, U32& h, U32& l) {
    __nv_bfloat16 hx = __float2bfloat16(x);
    __nv_bfloat16 hy = __float2bfloat16(y);
    h = (U32)__bfloat16_as_ushort(hx) | ((U32)__bfloat16_as_ushort(hy) << 16);
    float rx = x - __bfloat162float(hx);
    float ry = y - __bfloat162float(hy);
    __nv_bfloat16 lx = __float2bfloat16(rx);
    __nv_bfloat16 ly = __float2bfloat16(ry);
    l = (U32)__bfloat16_as_ushort(lx) | ((U32)__bfloat16_as_ushort(ly) << 16);
}

// ---------------- embedding body ----------------
__device__ __forceinline__ void embed_body(
    const float* __restrict__ X, int blk, int R, int Din,
    const float* __restrict__ W1, const float* __restrict__ b1,
    const float* __restrict__ W2, const float* __restrict__ b2,
    float* __restrict__ Y, float* Xs, float* Hs)
{
    int r0 = blk * 16;
    int t = threadIdx.x;
    for (int idx = t; idx < 16 * Din; idx += 128) {
        int r = idx / Din, d = idx % Din;
        Xs[r * Din + d] = (r0 + r < R) ? X[(size_t)(r0 + r) * Din + d] : 0.f;
    }
    __syncthreads();
    int lr = t >> 3;
    int c0 = (t & 7) * 8;
    float h[8];
#pragma unroll
    for (int q = 0; q < 8; q++) h[q] = b1[c0 + q];
    for (int d = 0; d < Din; d++) {
        float x = Xs[lr * Din + d];
        const float* w = W1 + d * C + c0;
#pragma unroll
        for (int q = 0; q < 8; q++) h[q] += x * w[q];
    }
#pragma unroll
    for (int q = 0; q < 8; q++) Hs[lr * C + c0 + q] = fmaxf(h[q], 0.f);
    __syncthreads();
    float y[8];
#pragma unroll
    for (int q = 0; q < 8; q++) y[q] = b2[c0 + q];
    for (int m = 0; m < C; m++) {
        float hm = Hs[lr * C + m];
        const float* w = W2 + m * C + c0;
#pragma unroll
        for (int q = 0; q < 8; q++) y[q] += hm * w[q];
    }
    if (r0 + lr < R) {
        float* yo = Y + (size_t)(r0 + lr) * C + c0;
#pragma unroll
        for (int q = 0; q < 8; q++) yo[q] = fmaxf(y[q], 0.f);
    }
}

// ---------------- launch 1: embeds + zeroing + weight fragment prep ----------------
__global__ __launch_bounds__(128) void k_init(
    const float* __restrict__ node_x, const float* __restrict__ edge_x,
    const float* __restrict__ face_x,
    const float* __restrict__ nW1, const float* __restrict__ nb1,
    const float* __restrict__ nW2, const float* __restrict__ nb2,
    const float* __restrict__ eW1, const float* __restrict__ eb1,
    const float* __restrict__ eW2, const float* __restrict__ eb2,
    const float* __restrict__ fW1, const float* __restrict__ fb1,
    const float* __restrict__ fW2, const float* __restrict__ fb2,
    const float* __restrict__ plW0, const float* __restrict__ plW1,
    const float* __restrict__ oW1, const float* __restrict__ oW2)
{
    __shared__ float Xs[16 * 144];
    __shared__ float Hs[16 * C];
    int b = blockIdx.x;
    int t = threadIdx.x;
    if (b < 48) {
        embed_body(node_x, b, NNODES, 144, nW1, nb1, nW2, nb2, g_feat, Xs, Hs);
    } else if (b < 432) {
        embed_body(edge_x, b - 48, E0, 144, eW1, eb1, eW2, eb2, g_feat + NTOT * C, Xs, Hs);
    } else if (b < 448) {
        embed_body(face_x, b - 432, NFACES, 12, fW1, fb1, fW2, fb2, g_feat + NNODES * C, Xs, Hs);
    } else {
        int z = b - 448;  // 0..1023
        float4 zv = make_float4(0.f, 0.f, 0.f, 0.f);
        float4* ap = (float4*)(g_adjn) + (size_t)z * 256 + t * 2;
        ap[0] = zv; ap[1] = zv;
        if (z == 0) {
            for (int q = 0; q < 8; q++) g_src_cnt[t * 8 + q] = 0;
        } else if (z == 1) {
            for (int q = 0; q < 8; q++) g_outcnt[t * 8 + q] = 0;
        } else if (z >= 2 && z < 6) {
            int4 z4 = make_int4(0, 0, 0, 0);
            int4* hp = (int4*)g_hcnt + (z - 2) * 1024 + t * 8;
#pragma unroll
            for (int q = 0; q < 8; q++) hp[q] = z4;
        } else if (z >= 6 && z < 9) {
            // bf16 hi/lo fragment pack for layer-2 weights (m16n8k16)
            int w = z - 6;
            const float* W = (w == 0) ? plW1 : (w == 1) ? oW1 : oW2;
            int Tn = (w == 2) ? 4 : 8;
            int Nd = Tn * 8;
            U32* gh = (U32*)g_wfrag + ((w == 0) ? 0 : (w == 1) ? 4096 : 8192);
            U32* gl = gh + ((w == 2) ? 1024 : 2048);
            int total = 4 * Tn * 32;
            for (int idx = t; idx < total; idx += 128) {
                int kk = idx / (Tn * 32);
                int rem = idx - kk * Tn * 32;
                int tile = rem >> 5;
                int l = rem & 31;
                int n  = tile * 8 + (l >> 2);
                int k0 = kk * 16 + (l & 3) * 2;
                U32 h0, l0, h1, l1;
                packpair(W[k0 * Nd + n], W[(k0 + 1) * Nd + n], h0, l0);
                packpair(W[(k0 + 8) * Nd + n], W[(k0 + 9) * Nd + n], h1, l1);
                gh[idx * 2] = h0; gh[idx * 2 + 1] = h1;
                gl[idx * 2] = l0; gl[idx * 2 + 1] = l1;
            }
        } else if (z == 9) {
            // tf32 hi/lo fragment pack for plW0 (layer-1 epilogue, m16n8k8)
            const float* W = plW0;
            float* gh = g_wfrag + 10240;
            float* gl = g_wfrag + 14336;
            for (int idx = t; idx < 2048; idx += 128) {
                int kk = idx >> 8;
                int rem = idx & 255;
                int tile = rem >> 5;
                int l = rem & 31;
                int k0 = kk * 8 + (l & 3);
                int n  = tile * 8 + (l >> 2);
                float v0 = W[k0 * 64 + n];
                float v1 = W[(k0 + 4) * 64 + n];
                uint32_t h0 = tf32h(v0);
                uint32_t h1 = tf32h(v1);
                uint32_t l0 = tf32h(v0 - __uint_as_float(h0));
                uint32_t l1 = tf32h(v1 - __uint_as_float(h1));
                gh[idx * 2]     = __uint_as_float(h0);
                gh[idx * 2 + 1] = __uint_as_float(h1);
                gl[idx * 2]     = __uint_as_float(l0);
                gl[idx * 2 + 1] = __uint_as_float(l1);
            }
        }
    }
}

// ---------------- launch 2: edges + diag + out-degree + src lists ----------------
__global__ void k_edges(const int* __restrict__ ei, const int* __restrict__ fn) {
    int e = blockIdx.x * blockDim.x + threadIdx.x;
    if (e >= ETOT + NTOT) return;
    if (e >= ETOT) {
        int i = e - ETOT;
        atomicAdd(&g_adjn[i * NTOT + i], 1.0f);
        return;
    }
    int s, d, cr;
    if (e < E0)            { s = ei[e]; d = ei[E0 + e]; cr = NTOT + e; }
    else if (e < E0 + EF)  { int q = e - E0; int f = q / 6; s = fn[q]; d = NNODES + f; cr = NNODES + f; }
    else                   { int r = e - (E0 + EF); int rr = 1535 - r; int f = rr / 6;
                             s = NNODES + f; d = fn[rr]; cr = NNODES + f; }
    atomicAdd(&g_adjn[s * NTOT + d], 1.0f);
    atomicAdd(&g_outcnt[s], 1);
    int p = atomicAdd(&g_src_cnt[s], 1);
    if (p < SRCCAP) g_src_list[s * SRCCAP + p] = (d << 13) | cr;
}

// ---------------- launch 3: scale + CSR + row sums ----------------
__global__ __launch_bounds__(256) void k_scale_csr() {
    int i = blockIdx.x;
    __shared__ int cnt;
    __shared__ float red[8];
    if (threadIdx.x == 0) cnt = 0;
    __syncthreads();
    float di = 1.f / sqrtf(1.f + (float)g_outcnt[i]);
    float sv = 0.f;
    for (int j = threadIdx.x; j < NTOT; j += 256) {
        float v = g_adjn[i * NTOT + j];
        if (v != 0.f) {
            float dj = 1.f / sqrtf(1.f + (float)g_outcnt[j]);
            v *= di * dj;
            sv += v;
            int p = atomicAdd(&cnt, 1);
            if (p < 192) { g_row_col[i * 192 + p] = j; g_row_val[i * 192 + p] = v; }
        }
    }
#pragma unroll
    for (int o = 16; o > 0; o >>= 1) sv += __shfl_down_sync(0xffffffffu, sv, o);
    if ((threadIdx.x & 31) == 0) red[threadIdx.x >> 5] = sv;
    __syncthreads();
    if (threadIdx.x == 0) {
        float tot = 0.f;
        for (int w = 0; w < 8; w++) tot += red[w];
        g_srow[i] = tot;
        g_row_cnt[i] = min(cnt, 192);
    }
}

// ---------------- launch 4: build per-(j,kt) hit lists ----------------
__global__ __launch_bounds__(256) void k_hits() {
    const int j = blockIdx.x;
    const int t = threadIdx.x;
    __shared__ int sc[NKT];
    if (t < NKT) sc[t] = 0;
    __syncthreads();
    const int rn = g_row_cnt[j];
    if (t < rn) {
        int s = g_row_col[j * 192 + t];
        int abits = __float_as_int(g_row_val[j * 192 + t]);
        {
            int kt = s >> 6, kl = s & 63;
            int p = atomicAdd(&sc[kt], 1);
            if (p < HCAP) g_hits[(j * NKT + kt) * HCAP + p] = make_int2((kl << 13) | s, abits);
        }
        int oc = min(g_src_cnt[s], SRCCAP);
        for (int q = 0; q < oc; q++) {
            int packed = g_src_list[s * SRCCAP + q];
            int d = packed >> 13, cr = packed & 8191;
            int kt = d >> 6, kl = d & 63;
            int p = atomicAdd(&sc[kt], 1);
            if (p < HCAP) g_hits[(j * NKT + kt) * HCAP + p] = make_int2((kl << 13) | cr, abits);
        }
    }
    __syncthreads();
    if (t < NKT) g_hcnt[j * NKT + t] = min(sc[t], HCAP);
}

// ---------------- launch 5: layer-1 deltas (scatter + rebalanced tf32 mma epilogue) ----------------
__global__ __launch_bounds__(256) void k_layer1(const float* __restrict__ plb)
{
    __shared__ float Hs[64 * 65];
    __shared__ int   sFlag[64];
    __shared__ int   flist[64];
    __shared__ unsigned char ipos[64];
    __shared__ int nf;

    const int kt = blockIdx.x;
    const int j  = blockIdx.y;
    const int t  = threadIdx.x;
    if (t == 0) nf = 0;
    if (t < 64) { sFlag[t] = 0; ipos[t] = 0xFF; }
    for (int idx = t; idx < 64 * 65; idx += 256) Hs[idx] = 0.f;
    __syncthreads();

    const int seg = j * NKT + kt;
    const int ne = g_hcnt[seg];
    {
        const int sub = (t & 3) * 16;
        for (int idx = t >> 2; idx < ne; idx += 64) {
            int2 ent = g_hits[seg * HCAP + idx];
            int kl = ent.x >> 13, cr = ent.x & 8191;
            float a = __int_as_float(ent.y);
            const float4* fp = (const float4*)(g_feat + cr * C + sub);
            float* h = Hs + kl * 65 + sub;
#pragma unroll
            for (int q = 0; q < 4; q++) {
                float4 v = fp[q];
                atomicAdd(h + 4*q + 0, a * v.x);
                atomicAdd(h + 4*q + 1, a * v.y);
                atomicAdd(h + 4*q + 2, a * v.z);
                atomicAdd(h + 4*q + 3, a * v.w);
            }
            if ((t & 3) == 0) sFlag[kl] = 1;
        }
    }
    __syncthreads();
    if (t < 64 && sFlag[t]) { int p = atomicAdd(&nf, 1); flist[p] = t; }
    __syncthreads();
    const int n = nf;
    if (t < n) ipos[flist[t]] = (unsigned char)t;
    __syncthreads();
    if (t < 64) g_islot[seg * 64 + t] = ipos[t];

    // split-tf32 mma epilogue: warp = col-tile (8 warps x 8 cols), loop m-tiles
    const int wid = t >> 5, lane = t & 31;
    const int r0l = lane >> 2;
    const int cl = lane & 3;
    const float* Wh = g_wfrag + 10240;
    const float* Wl = g_wfrag + 14336;
    const size_t segbase = (size_t)seg * 4096;
    for (int mt = 0; mt * 16 < n; mt++) {
        const int m0 = mt * 16 + r0l;
        const int m1 = m0 + 8;
        const int fr0 = (m0 < n) ? flist[m0] : -1;
        const int fr1 = (m1 < n) ? flist[m1] : -1;
        float acc[4] = {0.f, 0.f, 0.f, 0.f};
#pragma unroll
        for (int kk = 0; kk < 8; kk++) {
            int c0 = kk * 8 + cl;
            float a0f = (fr0 >= 0) ? Hs[fr0 * 65 + c0] : 0.f;
            float a1f = (fr1 >= 0) ? Hs[fr1 * 65 + c0] : 0.f;
            float a2f = (fr0 >= 0) ? Hs[fr0 * 65 + c0 + 4] : 0.f;
            float a3f = (fr1 >= 0) ? Hs[fr1 * 65 + c0 + 4] : 0.f;
            uint32_t ah0 = tf32h(a0f), ah1 = tf32h(a1f), ah2 = tf32h(a2f), ah3 = tf32h(a3f);
            uint32_t al0 = tf32h(a0f - __uint_as_float(ah0));
            uint32_t al1 = tf32h(a1f - __uint_as_float(ah1));
            uint32_t al2 = tf32h(a2f - __uint_as_float(ah2));
            uint32_t al3 = tf32h(a3f - __uint_as_float(ah3));
            int fo = ((kk * 8 + wid) * 32 + lane) * 2;
            uint2 bh = *(const uint2*)(Wh + fo);
            uint2 bl = *(const uint2*)(Wl + fo);
            mma_tf32(acc, ah0, ah1, ah2, ah3, bh.x, bh.y);
            mma_tf32(acc, ah0, ah1, ah2, ah3, bl.x, bl.y);
            mma_tf32(acc, al0, al1, al2, al3, bh.x, bh.y);
        }
        int cg = wid * 8 + cl * 2;
        float b0 = plb[cg], b1 = plb[cg + 1];
        float crc0 = fmaxf(b0, 0.f), crc1 = fmaxf(b1, 0.f);
        if (m0 < n) {
            *(float2*)(g_delta + segbase + (size_t)m0 * 64 + cg) =
                make_float2(fmaxf(acc[0] + b0, 0.f) - crc0,
                            fmaxf(acc[1] + b1, 0.f) - crc1);
        }
        if (m1 < n) {
            *(float2*)(g_delta + segbase + (size_t)m1 * 64 + cg) =
                make_float2(fmaxf(acc[2] + b0, 0.f) - crc0,
                            fmaxf(acc[3] + b1, 0.f) - crc1);
        }
    }
}

// ---------------- bf16 split GEMM phases (M=128, packed operands, IN-PLACE) ----------------
__device__ __forceinline__ void gemm64_bf(
    U32* AHi, U32* ALo, const U32* WHi, const U32* WLo,
    const float* __restrict__ bias, int wid, int lane)
{
    const int wr = wid & 7;
    const int wc = wid >> 3;
    const int rb = wr * 16 + (lane >> 2);
    const int cl = lane & 3;
    float acc[4][4];
#pragma unroll
    for (int a = 0; a < 4; a++)
#pragma unroll
        for (int b = 0; b < 4; b++) acc[a][b] = 0.f;
#pragma unroll
    for (int kk = 0; kk < 4; kk++) {
        const int ai = kk * 8 + cl;
        U32 ah0 = AHi[rb * 36 + ai],       ah1 = AHi[(rb + 8) * 36 + ai];
        U32 ah2 = AHi[rb * 36 + ai + 4],   ah3 = AHi[(rb + 8) * 36 + ai + 4];
        U32 al0 = ALo[rb * 36 + ai],       al1 = ALo[(rb + 8) * 36 + ai];
        U32 al2 = ALo[rb * 36 + ai + 4],   al3 = ALo[(rb + 8) * 36 + ai + 4];
#pragma unroll
        for (int t4 = 0; t4 < 4; t4++) {
            int fo = ((kk * 8 + wc * 4 + t4) * 32 + lane) * 2;
            uint2 bh = *(const uint2*)(WHi + fo);
            uint2 bl = *(const uint2*)(WLo + fo);
            mma_bf16(acc[t4], ah0, ah1, ah2, ah3, bh.x, bh.y);
            mma_bf16(acc[t4], ah0, ah1, ah2, ah3, bl.x, bl.y);
            mma_bf16(acc[t4], al0, al1, al2, al3, bh.x, bh.y);
        }
    }
    __syncthreads();   // all mainloop reads done before in-place overwrite
#pragma unroll
    for (int t4 = 0; t4 < 4; t4++) {
        int cg = (wc * 4 + t4) * 8 + cl * 2;
        int pi = (wc * 4 + t4) * 4 + cl;
        float b0 = bias[cg], b1 = bias[cg + 1];
        float v0 = fmaxf(acc[t4][0] + b0, 0.f), v1 = fmaxf(acc[t4][1] + b1, 0.f);
        float v2 = fmaxf(acc[t4][2] + b0, 0.f), v3 = fmaxf(acc[t4][3] + b1, 0.f);
        U32 h, l;
        packpair(v0, v1, h, l);
        AHi[rb * 36 + pi] = h; ALo[rb * 36 + pi] = l;
        packpair(v2, v3, h, l);
        AHi[(rb + 8) * 36 + pi] = h; ALo[(rb + 8) * 36 + pi] = l;
    }
}

__device__ __forceinline__ void gemm32_bf(
    const U32* AHi, const U32* ALo, const U32* WHi, const U32* WLo,
    const float* __restrict__ bias, float* outB, int wid, int lane)
{
    const int wr = wid & 7;
    const int wc = wid >> 3;
    const int rb = wr * 16 + (lane >> 2);
    const int cl = lane & 3;
    float acc[2][4];
#pragma unroll
    for (int a = 0; a < 2; a++)
#pragma unroll
        for (int b = 0; b < 4; b++) acc[a][b] = 0.f;
#pragma unroll
    for (int kk = 0; kk < 4; kk++) {
        const int ai = kk * 8 + cl;
        U32 ah0 = AHi[rb * 36 + ai],       ah1 = AHi[(rb + 8) * 36 + ai];
        U32 ah2 = AHi[rb * 36 + ai + 4],   ah3 = AHi[(rb + 8) * 36 + ai + 4];
        U32 al0 = ALo[rb * 36 + ai],       al1 = ALo[(rb + 8) * 36 + ai];
        U32 al2 = ALo[rb * 36 + ai + 4],   al3 = ALo[(rb + 8) * 36 + ai + 4];
#pragma unroll
        for (int t2 = 0; t2 < 2; t2++) {
            int fo = ((kk * 4 + wc * 2 + t2) * 32 + lane) * 2;
            uint2 bh = *(const uint2*)(WHi + fo);
            uint2 bl = *(const uint2*)(WLo + fo);
            mma_bf16(acc[t2], ah0, ah1, ah2, ah3, bh.x, bh.y);
            mma_bf16(acc[t2], ah0, ah1, ah2, ah3, bl.x, bl.y);
            mma_bf16(acc[t2], al0, al1, al2, al3, bh.x, bh.y);
        }
    }
#pragma unroll
    for (int t2 = 0; t2 < 2; t2++) {
        int cg = (wc * 2 + t2) * 8 + cl * 2;
        float b0 = bias[cg], b1 = bias[cg + 1];
        *(float2*)(outB + (size_t)rb * 32 + cg) =
            make_float2(acc[t2][0] + b0, acc[t2][1] + b1);
        *(float2*)(outB + (size_t)(rb + 8) * 32 + cg) =
            make_float2(acc[t2][2] + b0, acc[t2][3] + b1);
    }
}

// ---------------- launch 6: layer 2 (gather + split-bf16 tensor MLP) ----------------
__global__ __launch_bounds__(512, 2) void k_layer2(
    const float* __restrict__ plb0,
    const float* __restrict__ plb1, const float* __restrict__ ob1,
    const float* __restrict__ ob2, float* __restrict__ out)
{
    extern __shared__ U32 su[];
    U32* Wf  = su + L2U_W;
    U32* AHi = su + L2U_AHI;
    U32* ALo = su + L2U_ALO;
    float* rvS = (float*)(su + L2U_RV);
    int*   rcS = (int*)(su + L2U_RC);
    unsigned char* islotS = (unsigned char*)(su + L2U_ISL);

    const int i    = blockIdx.x;
    const int half = blockIdx.y;
    const int t    = threadIdx.x;
    const int wid  = t >> 5;
    const int lane = t & 31;

    // copy bf16 weight fragments (10240 u32 = 2560 uint4)
    {
        const uint4* src = (const uint4*)g_wfrag;
        uint4* dst = (uint4*)Wf;
#pragma unroll
        for (int q = 0; q < 5; q++) dst[t + q * 512] = src[t + q * 512];
    }
    const int rn = g_row_cnt[i];
    if (t < rn) { rcS[t] = g_row_col[i * 192 + t]; rvS[t] = g_row_val[i * 192 + t]; }
    __syncthreads();

    const float sI = g_srow[i];

    for (int it = 0; it < 4; it++) {
        const int ktbase = half * 8 + it * 2;
        for (int idx = t; idx < rn * 32; idx += 512) {
            int r = idx >> 5, w = idx & 31;
            ((unsigned*)islotS)[r * 32 + w] =
                ((const unsigned*)g_islot)[(rcS[r] * 16 + ktbase) * 16 + w];
        }
        __syncthreads();

        // Phase A: gather fp32, pack hi/lo bf16 pairs into AHi/ALo
        {
            const int row = t >> 2;
            const int sub = (t & 3) * 16;
            float4 acc[4];
#pragma unroll
            for (int q = 0; q < 4; q++) {
                float4 b = *(const float4*)(plb0 + sub + q * 4);
                acc[q] = make_float4(sI * fmaxf(b.x, 0.f), sI * fmaxf(b.y, 0.f),
                                     sI * fmaxf(b.z, 0.f), sI * fmaxf(b.w, 0.f));
            }
            const int ktoff = ktbase + (row >> 6);
            for (int r = 0; r < rn; r++) {
                unsigned slot = islotS[r * 128 + row];
                if (slot != 0xFFu) {
                    float a = rvS[r];
                    int seg = rcS[r] * 16 + ktoff;
                    const float4* dp = (const float4*)(g_delta + ((size_t)seg * 64 + slot) * 64 + sub);
#pragma unroll
                    for (int q = 0; q < 4; q++) {
                        float4 v = dp[q];
                        acc[q].x += a * v.x; acc[q].y += a * v.y;
                        acc[q].z += a * v.z; acc[q].w += a * v.w;
                    }
                }
            }
            U32* hp = AHi + row * 36 + (sub >> 1);
            U32* lp = ALo + row * 36 + (sub >> 1);
#pragma unroll
            for (int q = 0; q < 4; q++) {
                U32 h, l;
                packpair(acc[q].x, acc[q].y, h, l);
                hp[2 * q] = h; lp[2 * q] = l;
                packpair(acc[q].z, acc[q].w, h, l);
                hp[2 * q + 1] = h; lp[2 * q + 1] = l;
            }
        }
        __syncthreads();

        // Phase B (in-place): A = relu(A @ plW1 + plb1)
        gemm64_bf(AHi, ALo, Wf, Wf + 2048, plb1, wid, lane);
        __syncthreads();
        // Phase C (in-place): A = relu(A @ oW1 + ob1)
        gemm64_bf(AHi, ALo, Wf + 4096, Wf + 6144, ob1, wid, lane);
        __syncthreads();
        // Phase D: out slab = A @ oW2 + ob2
        gemm32_bf(AHi, ALo, Wf + 8192, Wf + 9216, ob2,
                  out + ((size_t)i * NTOT + half * 512 + it * 128) * 32, wid, lane);
        __syncthreads();
    }
}

// ---------------- launch ----------------
extern "C" void kernel_launch(void* const* d_in, const int* in_sizes, int n_in,
                              void* d_out, int out_size)
{
    const float* node_x = (const float*)d_in[0];
    const float* edge_x = (const float*)d_in[1];
    const float* face_x = (const float*)d_in[2];
    const float* nW1 = (const float*)d_in[3];  const float* nb1 = (const float*)d_in[4];
    const float* nW2 = (const float*)d_in[5];  const float* nb2 = (const float*)d_in[6];
    const float* eW1 = (const float*)d_in[7];  const float* eb1 = (const float*)d_in[8];
    const float* eW2 = (const float*)d_in[9];  const float* eb2 = (const float*)d_in[10];
    const float* fW1 = (const float*)d_in[11]; const float* fb1 = (const float*)d_in[12];
    const float* fW2 = (const float*)d_in[13]; const float* fb2 = (const float*)d_in[14];
    const float* oW1 = (const float*)d_in[15]; const float* ob1 = (const float*)d_in[16];
    const float* oW2 = (const float*)d_in[17]; const float* ob2 = (const float*)d_in[18];
    const float* plW = (const float*)d_in[19]; const float* plb = (const float*)d_in[20];
    const int* edge_index = (const int*)d_in[21];
    const int* face_nodes = (const int*)d_in[22];
    float* out = (float*)d_out;

    cudaFuncSetAttribute(k_layer2, cudaFuncAttributeMaxDynamicSharedMemorySize, SMEM_TC);

    k_init<<<1472, 128>>>(node_x, edge_x, face_x, nW1, nb1, nW2, nb2,
                          eW1, eb1, eW2, eb2, fW1, fb1, fW2, fb2,
                          plW, plW + 4096, oW1, oW2);
    k_edges<<<(ETOT + NTOT + 255) / 256, 256>>>(edge_index, face_nodes);
    k_scale_csr<<<NTOT, 256>>>();
    k_hits<<<NTOT, 256>>>();
    k_layer1<<<dim3(NKT, NTOT), 256>>>(plb);
    k_layer2<<<dim3(NTOT, 2), 512, SMEM_TC>>>(plb, plb + 64, ob1, ob2, out);
    (void)in_sizes; (void)n_in; (void)out_size;
}

// round 15
// speedup vs baseline: 1.8555x; 1.0147x over previous
#include <cuda_runtime.h>
#include <cuda_bf16.h>
#include <cstdint>

#define NNODES 768
#define NFACES 256
#define NTOT   1024
#define E0     6144
#define EF     1536
#define ETOT   9216
#define C      64
#define NKT    16
#define SRCCAP 64
#define HCAP   128

typedef uint32_t U32;

// layer2 smem layout (u32 units) — in-place GEMMs, no B buffers
#define L2U_W    0        // 10240 u32 bf16 fragments
#define L2U_AHI  10240    // 128 x 36
#define L2U_ALO  14848    // 128 x 36
#define L2U_RV   19456    // 192 floats
#define L2U_RC   19648    // 192 ints
#define L2U_ISL  19840    // 6144 u32 = 24576 bytes uchar
#define SMEM_TC  ((19840 + 6144) * 4)   // 103936 bytes -> 2 blocks/SM

// ---------------- device scratch ----------------
__device__ float g_feat[(NTOT + E0) * C];
__device__ float g_adjn[NTOT * NTOT];
__device__ int   g_outcnt[NTOT];
__device__ float g_srow[NTOT];
__device__ int   g_row_cnt[NTOT];
__device__ int   g_row_col[NTOT * 192];
__device__ float g_row_val[NTOT * 192];
__device__ int   g_src_cnt[NTOT];
__device__ int   g_src_list[NTOT * SRCCAP];
__device__ int   g_hcnt[NTOT * NKT];
__device__ int   g_dcnt[NTOT * NKT];
__device__ int2  g_hits[NTOT * NKT * HCAP];     // {(slot<<13)|cr, bits(a)}
__device__ float g_delta[67108864];
__device__ unsigned char g_islot[NTOT * NKT * 64];
// bf16 B-fragments: plW1 hi 0 / lo 2048, oW1 4096/6144, oW2 8192/9216 (u32 units)
// tf32 B-fragments for plW0 (layer1): hi 10240, lo 14336
__device__ float g_wfrag[18432];

// ---------------- helpers ----------------
__device__ __forceinline__ uint32_t tf32h(float x) {
    uint32_t r; asm("cvt.rna.tf32.f32 %0, %1;" : "=r"(r) : "f"(x)); return r;
}
__device__ __forceinline__ void mma_tf32(float* d, uint32_t a0, uint32_t a1,
                                         uint32_t a2, uint32_t a3,
                                         uint32_t b0, uint32_t b1) {
    asm volatile(
        "mma.sync.aligned.m16n8k8.row.col.f32.tf32.tf32.f32 "
        "{%0,%1,%2,%3},{%4,%5,%6,%7},{%8,%9},{%0,%1,%2,%3};"
        : "+f"(d[0]), "+f"(d[1]), "+f"(d[2]), "+f"(d[3])
        : "r"(a0), "r"(a1), "r"(a2), "r"(a3), "r"(b0), "r"(b1));
}
__device__ __forceinline__ void mma_bf16(float* d, U32 a0, U32 a1, U32 a2, U32 a3,
                                         U32 b0, U32 b1) {
    asm volatile(
        "mma.sync.aligned.m16n8k16.row.col.f32.bf16.bf16.f32 "
        "{%0,%1,%2,%3},{%4,%5,%6,%7},{%8,%9},{%0,%1,%2,%3};"
        : "+f"(d[0]), "+f"(d[1]), "+f"(d[2]), "+f"(d[3])
        : "r"(a0), "r"(a1), "r"(a2), "r"(a3), "r"(b0), "r"(b1));
}
__device__ __forceinline__ void packpair(float x, float y, U32& h, U32& l) {
    __nv_bfloat16 hx = __float2bfloat16(x);
    __nv_bfloat16 hy = __float2bfloat16(y);
    h = (U32)__bfloat16_as_ushort(hx) | ((U32)__bfloat16_as_ushort(hy) << 16);
    float rx = x - __bfloat162float(hx);
    float ry = y - __bfloat162float(hy);
    __nv_bfloat16 lx = __float2bfloat16(rx);
    __nv_bfloat16 ly = __float2bfloat16(ry);
    l = (U32)__bfloat16_as_ushort(lx) | ((U32)__bfloat16_as_ushort(ly) << 16);
}

// ---------------- embedding body ----------------
__device__ __forceinline__ void embed_body(
    const float* __restrict__ X, int blk, int R, int Din,
    const float* __restrict__ W1, const float* __restrict__ b1,
    const float* __restrict__ W2, const float* __restrict__ b2,
    float* __restrict__ Y, float* Xs, float* Hs)
{
    int r0 = blk * 16;
    int t = threadIdx.x;
    for (int idx = t; idx < 16 * Din; idx += 128) {
        int r = idx / Din, d = idx % Din;
        Xs[r * Din + d] = (r0 + r < R) ? X[(size_t)(r0 + r) * Din + d] : 0.f;
    }
    __syncthreads();
    int lr = t >> 3;
    int c0 = (t & 7) * 8;
    float h[8];
#pragma unroll
    for (int q = 0; q < 8; q++) h[q] = b1[c0 + q];
    for (int d = 0; d < Din; d++) {
        float x = Xs[lr * Din + d];
        const float* w = W1 + d * C + c0;
#pragma unroll
        for (int q = 0; q < 8; q++) h[q] += x * w[q];
    }
#pragma unroll
    for (int q = 0; q < 8; q++) Hs[lr * C + c0 + q] = fmaxf(h[q], 0.f);
    __syncthreads();
    float y[8];
#pragma unroll
    for (int q = 0; q < 8; q++) y[q] = b2[c0 + q];
    for (int m = 0; m < C; m++) {
        float hm = Hs[lr * C + m];
        const float* w = W2 + m * C + c0;
#pragma unroll
        for (int q = 0; q < 8; q++) y[q] += hm * w[q];
    }
    if (r0 + lr < R) {
        float* yo = Y + (size_t)(r0 + lr) * C + c0;
#pragma unroll
        for (int q = 0; q < 8; q++) yo[q] = fmaxf(y[q], 0.f);
    }
}

// ---------------- launch 1: embeds + zeroing + weight fragment prep ----------------
__global__ __launch_bounds__(128) void k_init(
    const float* __restrict__ node_x, const float* __restrict__ edge_x,
    const float* __restrict__ face_x,
    const float* __restrict__ nW1, const float* __restrict__ nb1,
    const float* __restrict__ nW2, const float* __restrict__ nb2,
    const float* __restrict__ eW1, const float* __restrict__ eb1,
    const float* __restrict__ eW2, const float* __restrict__ eb2,
    const float* __restrict__ fW1, const float* __restrict__ fb1,
    const float* __restrict__ fW2, const float* __restrict__ fb2,
    const float* __restrict__ plW0, const float* __restrict__ plW1,
    const float* __restrict__ oW1, const float* __restrict__ oW2)
{
    __shared__ float Xs[16 * 144];
    __shared__ float Hs[16 * C];
    int b = blockIdx.x;
    int t = threadIdx.x;
    if (b < 48) {
        embed_body(node_x, b, NNODES, 144, nW1, nb1, nW2, nb2, g_feat, Xs, Hs);
    } else if (b < 432) {
        embed_body(edge_x, b - 48, E0, 144, eW1, eb1, eW2, eb2, g_feat + NTOT * C, Xs, Hs);
    } else if (b < 448) {
        embed_body(face_x, b - 432, NFACES, 12, fW1, fb1, fW2, fb2, g_feat + NNODES * C, Xs, Hs);
    } else {
        int z = b - 448;  // 0..1023
        float4 zv = make_float4(0.f, 0.f, 0.f, 0.f);
        float4* ap = (float4*)(g_adjn) + (size_t)z * 256 + t * 2;
        ap[0] = zv; ap[1] = zv;
        if (z == 0) {
            for (int q = 0; q < 8; q++) g_src_cnt[t * 8 + q] = 0;
        } else if (z == 1) {
            for (int q = 0; q < 8; q++) g_outcnt[t * 8 + q] = 0;
        } else if (z >= 6 && z < 9) {
            // bf16 hi/lo fragment pack for layer-2 weights (m16n8k16)
            int w = z - 6;
            const float* W = (w == 0) ? plW1 : (w == 1) ? oW1 : oW2;
            int Tn = (w == 2) ? 4 : 8;
            int Nd = Tn * 8;
            U32* gh = (U32*)g_wfrag + ((w == 0) ? 0 : (w == 1) ? 4096 : 8192);
            U32* gl = gh + ((w == 2) ? 1024 : 2048);
            int total = 4 * Tn * 32;
            for (int idx = t; idx < total; idx += 128) {
                int kk = idx / (Tn * 32);
                int rem = idx - kk * Tn * 32;
                int tile = rem >> 5;
                int l = rem & 31;
                int n  = tile * 8 + (l >> 2);
                int k0 = kk * 16 + (l & 3) * 2;
                U32 h0, l0, h1, l1;
                packpair(W[k0 * Nd + n], W[(k0 + 1) * Nd + n], h0, l0);
                packpair(W[(k0 + 8) * Nd + n], W[(k0 + 9) * Nd + n], h1, l1);
                gh[idx * 2] = h0; gh[idx * 2 + 1] = h1;
                gl[idx * 2] = l0; gl[idx * 2 + 1] = l1;
            }
        } else if (z == 9) {
            // tf32 hi/lo fragment pack for plW0 (layer-1 epilogue, m16n8k8)
            const float* W = plW0;
            float* gh = g_wfrag + 10240;
            float* gl = g_wfrag + 14336;
            for (int idx = t; idx < 2048; idx += 128) {
                int kk = idx >> 8;
                int rem = idx & 255;
                int tile = rem >> 5;
                int l = rem & 31;
                int k0 = kk * 8 + (l & 3);
                int n  = tile * 8 + (l >> 2);
                float v0 = W[k0 * 64 + n];
                float v1 = W[(k0 + 4) * 64 + n];
                uint32_t h0 = tf32h(v0);
                uint32_t h1 = tf32h(v1);
                uint32_t l0 = tf32h(v0 - __uint_as_float(h0));
                uint32_t l1 = tf32h(v1 - __uint_as_float(h1));
                gh[idx * 2]     = __uint_as_float(h0);
                gh[idx * 2 + 1] = __uint_as_float(h1);
                gl[idx * 2]     = __uint_as_float(l0);
                gl[idx * 2 + 1] = __uint_as_float(l1);
            }
        }
    }
}

// ---------------- launch 2: edges + diag + out-degree + src lists ----------------
__global__ void k_edges(const int* __restrict__ ei, const int* __restrict__ fn) {
    int e = blockIdx.x * blockDim.x + threadIdx.x;
    if (e >= ETOT + NTOT) return;
    if (e >= ETOT) {
        int i = e - ETOT;
        atomicAdd(&g_adjn[i * NTOT + i], 1.0f);
        return;
    }
    int s, d, cr;
    if (e < E0)            { s = ei[e]; d = ei[E0 + e]; cr = NTOT + e; }
    else if (e < E0 + EF)  { int q = e - E0; int f = q / 6; s = fn[q]; d = NNODES + f; cr = NNODES + f; }
    else                   { int r = e - (E0 + EF); int rr = 1535 - r; int f = rr / 6;
                             s = NNODES + f; d = fn[rr]; cr = NNODES + f; }
    atomicAdd(&g_adjn[s * NTOT + d], 1.0f);
    atomicAdd(&g_outcnt[s], 1);
    int p = atomicAdd(&g_src_cnt[s], 1);
    if (p < SRCCAP) g_src_list[s * SRCCAP + p] = (d << 13) | cr;
}

// ---------------- launch 3: scale + CSR + row sums ----------------
__global__ __launch_bounds__(256) void k_scale_csr() {
    int i = blockIdx.x;
    __shared__ int cnt;
    __shared__ float red[8];
    if (threadIdx.x == 0) cnt = 0;
    __syncthreads();
    float di = 1.f / sqrtf(1.f + (float)g_outcnt[i]);
    float sv = 0.f;
    for (int j = threadIdx.x; j < NTOT; j += 256) {
        float v = g_adjn[i * NTOT + j];
        if (v != 0.f) {
            float dj = 1.f / sqrtf(1.f + (float)g_outcnt[j]);
            v *= di * dj;
            sv += v;
            int p = atomicAdd(&cnt, 1);
            if (p < 192) { g_row_col[i * 192 + p] = j; g_row_val[i * 192 + p] = v; }
        }
    }
#pragma unroll
    for (int o = 16; o > 0; o >>= 1) sv += __shfl_down_sync(0xffffffffu, sv, o);
    if ((threadIdx.x & 31) == 0) red[threadIdx.x >> 5] = sv;
    __syncthreads();
    if (threadIdx.x == 0) {
        float tot = 0.f;
        for (int w = 0; w < 8; w++) tot += red[w];
        g_srow[i] = tot;
        g_row_cnt[i] = min(cnt, 192);
    }
}

// ---------------- launch 4: hit lists with precomputed slots + islot ----------------
__global__ __launch_bounds__(256) void k_hits() {
    const int j = blockIdx.x;
    const int t = threadIdx.x;
    __shared__ U32 dmask[32];            // 1024-bit presence bitmap
    __shared__ int sc[NKT];
    __shared__ unsigned char map[NTOT];  // entity -> slot within its kt
    if (t < 32) dmask[t] = 0;
    if (t < NKT) sc[t] = 0;
    __syncthreads();

    const int rn = g_row_cnt[j];
    int s = -1, oc = 0;
    if (t < rn) {
        s = g_row_col[j * 192 + t];
        atomicOr(&dmask[s >> 5], 1u << (s & 31));
        oc = min(g_src_cnt[s], SRCCAP);
        for (int q = 0; q < oc; q++) {
            int d = g_src_list[s * SRCCAP + q] >> 13;
            atomicOr(&dmask[d >> 5], 1u << (d & 31));
        }
    }
    __syncthreads();

    // slot assignment via popcount prefix within each kt (64-bit window)
#pragma unroll
    for (int q = 0; q < 4; q++) {
        int idx = t + q * 256;           // 0..1023
        int kt = idx >> 6, kl = idx & 63;
        U32 lo = dmask[kt * 2], hi = dmask[kt * 2 + 1];
        int set, below;
        if (kl < 32) {
            set = (lo >> kl) & 1;
            below = __popc(lo & ((1u << kl) - 1u));
        } else {
            set = (hi >> (kl - 32)) & 1;
            below = __popc(lo) + __popc(hi & ((kl == 32) ? 0u : ((1u << (kl - 32)) - 1u)));
        }
        unsigned char slot = set ? (unsigned char)below : (unsigned char)0xFF;
        map[idx] = slot;
        g_islot[(j * NKT + kt) * 64 + kl] = slot;
        if (kl == 63) g_dcnt[j * NKT + kt] = __popc(lo) + __popc(hi);
    }
    __syncthreads();

    // emit hits (slot-indexed)
    if (t < rn) {
        int abits = __float_as_int(g_row_val[j * 192 + t]);
        {
            int kt = s >> 6;
            int p = atomicAdd(&sc[kt], 1);
            if (p < HCAP)
                g_hits[(j * NKT + kt) * HCAP + p] = make_int2(((int)map[s] << 13) | s, abits);
        }
        for (int q = 0; q < oc; q++) {
            int packed = g_src_list[s * SRCCAP + q];
            int d = packed >> 13, cr = packed & 8191;
            int kt = d >> 6;
            int p = atomicAdd(&sc[kt], 1);
            if (p < HCAP)
                g_hits[(j * NKT + kt) * HCAP + p] = make_int2(((int)map[d] << 13) | cr, abits);
        }
    }
    __syncthreads();
    if (t < NKT) g_hcnt[j * NKT + t] = min(sc[t], HCAP);
}

// ---------------- launch 5: layer-1 deltas (slot scatter + tf32 mma epilogue) ----------------
__global__ __launch_bounds__(256) void k_layer1(const float* __restrict__ plb)
{
    __shared__ float Hs[64 * 65];

    const int kt = blockIdx.x;
    const int j  = blockIdx.y;
    const int t  = threadIdx.x;
    const int seg = j * NKT + kt;
    const int n = g_dcnt[seg];
    if (n == 0) return;
    const int ne = g_hcnt[seg];

    for (int idx = t; idx < n * 65; idx += 256) Hs[idx] = 0.f;
    __syncthreads();

    // scatter: 4 threads per hit, rows indexed by precomputed slot
    {
        const int sub = (t & 3) * 16;
        for (int idx = t >> 2; idx < ne; idx += 64) {
            int2 ent = g_hits[seg * HCAP + idx];
            int slot = ent.x >> 13, cr = ent.x & 8191;
            float a = __int_as_float(ent.y);
            const float4* fp = (const float4*)(g_feat + cr * C + sub);
            float* h = Hs + slot * 65 + sub;
#pragma unroll
            for (int q = 0; q < 4; q++) {
                float4 v = fp[q];
                atomicAdd(h + 4*q + 0, a * v.x);
                atomicAdd(h + 4*q + 1, a * v.y);
                atomicAdd(h + 4*q + 2, a * v.z);
                atomicAdd(h + 4*q + 3, a * v.w);
            }
        }
    }
    __syncthreads();

    // split-tf32 mma epilogue: warp = col-tile (8 warps x 8 cols), loop m-tiles
    const int wid = t >> 5, lane = t & 31;
    const int r0l = lane >> 2;
    const int cl = lane & 3;
    const float* Wh = g_wfrag + 10240;
    const float* Wl = g_wfrag + 14336;
    const size_t segbase = (size_t)seg * 4096;
    for (int mt = 0; mt * 16 < n; mt++) {
        const int m0 = mt * 16 + r0l;
        const int m1 = m0 + 8;
        float acc[4] = {0.f, 0.f, 0.f, 0.f};
#pragma unroll
        for (int kk = 0; kk < 8; kk++) {
            int c0 = kk * 8 + cl;
            float a0f = (m0 < n) ? Hs[m0 * 65 + c0] : 0.f;
            float a1f = (m1 < n) ? Hs[m1 * 65 + c0] : 0.f;
            float a2f = (m0 < n) ? Hs[m0 * 65 + c0 + 4] : 0.f;
            float a3f = (m1 < n) ? Hs[m1 * 65 + c0 + 4] : 0.f;
            uint32_t ah0 = tf32h(a0f), ah1 = tf32h(a1f), ah2 = tf32h(a2f), ah3 = tf32h(a3f);
            uint32_t al0 = tf32h(a0f - __uint_as_float(ah0));
            uint32_t al1 = tf32h(a1f - __uint_as_float(ah1));
            uint32_t al2 = tf32h(a2f - __uint_as_float(ah2));
            uint32_t al3 = tf32h(a3f - __uint_as_float(ah3));
            int fo = ((kk * 8 + wid) * 32 + lane) * 2;
            uint2 bh = *(const uint2*)(Wh + fo);
            uint2 bl = *(const uint2*)(Wl + fo);
            mma_tf32(acc, ah0, ah1, ah2, ah3, bh.x, bh.y);
            mma_tf32(acc, ah0, ah1, ah2, ah3, bl.x, bl.y);
            mma_tf32(acc, al0, al1, al2, al3, bh.x, bh.y);
        }
        int cg = wid * 8 + cl * 2;
        float b0 = plb[cg], b1 = plb[cg + 1];
        float crc0 = fmaxf(b0, 0.f), crc1 = fmaxf(b1, 0.f);
        if (m0 < n) {
            *(float2*)(g_delta + segbase + (size_t)m0 * 64 + cg) =
                make_float2(fmaxf(acc[0] + b0, 0.f) - crc0,
                            fmaxf(acc[1] + b1, 0.f) - crc1);
        }
        if (m1 < n) {
            *(float2*)(g_delta + segbase + (size_t)m1 * 64 + cg) =
                make_float2(fmaxf(acc[2] + b0, 0.f) - crc0,
                            fmaxf(acc[3] + b1, 0.f) - crc1);
        }
    }
}

// ---------------- bf16 split GEMM phases (M=128, packed operands, IN-PLACE) ----------------
__device__ __forceinline__ void gemm64_bf(
    U32* AHi, U32* ALo, const U32* WHi, const U32* WLo,
    const float* __restrict__ bias, int wid, int lane)
{
    const int wr = wid & 7;
    const int wc = wid >> 3;
    const int rb = wr * 16 + (lane >> 2);
    const int cl = lane & 3;
    float acc[4][4];
#pragma unroll
    for (int a = 0; a < 4; a++)
#pragma unroll
        for (int b = 0; b < 4; b++) acc[a][b] = 0.f;
#pragma unroll
    for (int kk = 0; kk < 4; kk++) {
        const int ai = kk * 8 + cl;
        U32 ah0 = AHi[rb * 36 + ai],       ah1 = AHi[(rb + 8) * 36 + ai];
        U32 ah2 = AHi[rb * 36 + ai + 4],   ah3 = AHi[(rb + 8) * 36 + ai + 4];
        U32 al0 = ALo[rb * 36 + ai],       al1 = ALo[(rb + 8) * 36 + ai];
        U32 al2 = ALo[rb * 36 + ai + 4],   al3 = ALo[(rb + 8) * 36 + ai + 4];
#pragma unroll
        for (int t4 = 0; t4 < 4; t4++) {
            int fo = ((kk * 8 + wc * 4 + t4) * 32 + lane) * 2;
            uint2 bh = *(const uint2*)(WHi + fo);
            uint2 bl = *(const uint2*)(WLo + fo);
            mma_bf16(acc[t4], ah0, ah1, ah2, ah3, bh.x, bh.y);
            mma_bf16(acc[t4], ah0, ah1, ah2, ah3, bl.x, bl.y);
            mma_bf16(acc[t4], al0, al1, al2, al3, bh.x, bh.y);
        }
    }
    __syncthreads();   // all mainloop reads done before in-place overwrite
#pragma unroll
    for (int t4 = 0; t4 < 4; t4++) {
        int cg = (wc * 4 + t4) * 8 + cl * 2;
        int pi = (wc * 4 + t4) * 4 + cl;
        float b0 = bias[cg], b1 = bias[cg + 1];
        float v0 = fmaxf(acc[t4][0] + b0, 0.f), v1 = fmaxf(acc[t4][1] + b1, 0.f);
        float v2 = fmaxf(acc[t4][2] + b0, 0.f), v3 = fmaxf(acc[t4][3] + b1, 0.f);
        U32 h, l;
        packpair(v0, v1, h, l);
        AHi[rb * 36 + pi] = h; ALo[rb * 36 + pi] = l;
        packpair(v2, v3, h, l);
        AHi[(rb + 8) * 36 + pi] = h; ALo[(rb + 8) * 36 + pi] = l;
    }
}

__device__ __forceinline__ void gemm32_bf(
    const U32* AHi, const U32* ALo, const U32* WHi, const U32* WLo,
    const float* __restrict__ bias, float* outB, int wid, int lane)
{
    const int wr = wid & 7;
    const int wc = wid >> 3;
    const int rb = wr * 16 + (lane >> 2);
    const int cl = lane & 3;
    float acc[2][4];
#pragma unroll
    for (int a = 0; a < 2; a++)
#pragma unroll
        for (int b = 0; b < 4; b++) acc[a][b] = 0.f;
#pragma unroll
    for (int kk = 0; kk < 4; kk++) {
        const int ai = kk * 8 + cl;
        U32 ah0 = AHi[rb * 36 + ai],       ah1 = AHi[(rb + 8) * 36 + ai];
        U32 ah2 = AHi[rb * 36 + ai + 4],   ah3 = AHi[(rb + 8) * 36 + ai + 4];
        U32 al0 = ALo[rb * 36 + ai],       al1 = ALo[(rb + 8) * 36 + ai];
        U32 al2 = ALo[rb * 36 + ai + 4],   al3 = ALo[(rb + 8) * 36 + ai + 4];
#pragma unroll
        for (int t2 = 0; t2 < 2; t2++) {
            int fo = ((kk * 4 + wc * 2 + t2) * 32 + lane) * 2;
            uint2 bh = *(const uint2*)(WHi + fo);
            uint2 bl = *(const uint2*)(WLo + fo);
            mma_bf16(acc[t2], ah0, ah1, ah2, ah3, bh.x, bh.y);
            mma_bf16(acc[t2], ah0, ah1, ah2, ah3, bl.x, bl.y);
            mma_bf16(acc[t2], al0, al1, al2, al3, bh.x, bh.y);
        }
    }
#pragma unroll
    for (int t2 = 0; t2 < 2; t2++) {
        int cg = (wc * 2 + t2) * 8 + cl * 2;
        float b0 = bias[cg], b1 = bias[cg + 1];
        *(float2*)(outB + (size_t)rb * 32 + cg) =
            make_float2(acc[t2][0] + b0, acc[t2][1] + b1);
        *(float2*)(outB + (size_t)(rb + 8) * 32 + cg) =
            make_float2(acc[t2][2] + b0, acc[t2][3] + b1);
    }
}

// ---------------- launch 6: layer 2 (gather + split-bf16 tensor MLP) ----------------
__global__ __launch_bounds__(512, 2) void k_layer2(
    const float* __restrict__ plb0,
    const float* __restrict__ plb1, const float* __restrict__ ob1,
    const float* __restrict__ ob2, float* __restrict__ out)
{
    extern __shared__ U32 su[];
    U32* Wf  = su + L2U_W;
    U32* AHi = su + L2U_AHI;
    U32* ALo = su + L2U_ALO;
    float* rvS = (float*)(su + L2U_RV);
    int*   rcS = (int*)(su + L2U_RC);
    unsigned char* islotS = (unsigned char*)(su + L2U_ISL);

    const int i    = blockIdx.x;
    const int half = blockIdx.y;
    const int t    = threadIdx.x;
    const int wid  = t >> 5;
    const int lane = t & 31;

    // copy bf16 weight fragments (10240 u32 = 2560 uint4)
    {
        const uint4* src = (const uint4*)g_wfrag;
        uint4* dst = (uint4*)Wf;
#pragma unroll
        for (int q = 0; q < 5; q++) dst[t + q * 512] = src[t + q * 512];
    }
    const int rn = g_row_cnt[i];
    if (t < rn) { rcS[t] = g_row_col[i * 192 + t]; rvS[t] = g_row_val[i * 192 + t]; }
    __syncthreads();

    const float sI = g_srow[i];

    for (int it = 0; it < 4; it++) {
        const int ktbase = half * 8 + it * 2;
        for (int idx = t; idx < rn * 32; idx += 512) {
            int r = idx >> 5, w = idx & 31;
            ((unsigned*)islotS)[r * 32 + w] =
                ((const unsigned*)g_islot)[(rcS[r] * 16 + ktbase) * 16 + w];
        }
        __syncthreads();

        // Phase A: gather fp32, pack hi/lo bf16 pairs into AHi/ALo
        {
            const int row = t >> 2;
            const int sub = (t & 3) * 16;
            float4 acc[4];
#pragma unroll
            for (int q = 0; q < 4; q++) {
                float4 b = *(const float4*)(plb0 + sub + q * 4);
                acc[q] = make_float4(sI * fmaxf(b.x, 0.f), sI * fmaxf(b.y, 0.f),
                                     sI * fmaxf(b.z, 0.f), sI * fmaxf(b.w, 0.f));
            }
            const int ktoff = ktbase + (row >> 6);
            for (int r = 0; r < rn; r++) {
                unsigned slot = islotS[r * 128 + row];
                if (slot != 0xFFu) {
                    float a = rvS[r];
                    int seg = rcS[r] * 16 + ktoff;
                    const float4* dp = (const float4*)(g_delta + ((size_t)seg * 64 + slot) * 64 + sub);
#pragma unroll
                    for (int q = 0; q < 4; q++) {
                        float4 v = dp[q];
                        acc[q].x += a * v.x; acc[q].y += a * v.y;
                        acc[q].z += a * v.z; acc[q].w += a * v.w;
                    }
                }
            }
            U32* hp = AHi + row * 36 + (sub >> 1);
            U32* lp = ALo + row * 36 + (sub >> 1);
#pragma unroll
            for (int q = 0; q < 4; q++) {
                U32 h, l;
                packpair(acc[q].x, acc[q].y, h, l);
                hp[2 * q] = h; lp[2 * q] = l;
                packpair(acc[q].z, acc[q].w, h, l);
                hp[2 * q + 1] = h; lp[2 * q + 1] = l;
            }
        }
        __syncthreads();

        // Phase B (in-place): A = relu(A @ plW1 + plb1)
        gemm64_bf(AHi, ALo, Wf, Wf + 2048, plb1, wid, lane);
        __syncthreads();
        // Phase C (in-place): A = relu(A @ oW1 + ob1)
        gemm64_bf(AHi, ALo, Wf + 4096, Wf + 6144, ob1, wid, lane);
        __syncthreads();
        // Phase D: out slab = A @ oW2 + ob2
        gemm32_bf(AHi, ALo, Wf + 8192, Wf + 9216, ob2,
                  out + ((size_t)i * NTOT + half * 512 + it * 128) * 32, wid, lane);
        __syncthreads();
    }
}

// ---------------- launch ----------------
extern "C" void kernel_launch(void* const* d_in, const int* in_sizes, int n_in,
                              void* d_out, int out_size)
{
    const float* node_x = (const float*)d_in[0];
    const float* edge_x = (const float*)d_in[1];
    const float* face_x = (const float*)d_in[2];
    const float* nW1 = (const float*)d_in[3];  const float* nb1 = (const float*)d_in[4];
    const float* nW2 = (const float*)d_in[5];  const float* nb2 = (const float*)d_in[6];
    const float* eW1 = (const float*)d_in[7];  const float* eb1 = (const float*)d_in[8];
    const float* eW2 = (const float*)d_in[9];  const float* eb2 = (const float*)d_in[10];
    const float* fW1 = (const float*)d_in[11]; const float* fb1 = (const float*)d_in[12];
    const float* fW2 = (const float*)d_in[13]; const float* fb2 = (const float*)d_in[14];
    const float* oW1 = (const float*)d_in[15]; const float* ob1 = (const float*)d_in[16];
    const float* oW2 = (const float*)d_in[17]; const float* ob2 = (const float*)d_in[18];
    const float* plW = (const float*)d_in[19]; const float* plb = (const float*)d_in[20];
    const int* edge_index = (const int*)d_in[21];
    const int* face_nodes = (const int*)d_in[22];
    float* out = (float*)d_out;

    cudaFuncSetAttribute(k_layer2, cudaFuncAttributeMaxDynamicSharedMemorySize, SMEM_TC);

    k_init<<<1472, 128>>>(node_x, edge_x, face_x, nW1, nb1, nW2, nb2,
                          eW1, eb1, eW2, eb2, fW1, fb1, fW2, fb2,
                          plW, plW + 4096, oW1, oW2);
    k_edges<<<(ETOT + NTOT + 255) / 256, 256>>>(edge_index, face_nodes);
    k_scale_csr<<<NTOT, 256>>>();
    k_hits<<<NTOT, 256>>>();
    k_layer1<<<dim3(NKT, NTOT), 256>>>(plb);
    k_layer2<<<dim3(NTOT, 2), 512, SMEM_TC>>>(plb, plb + 64, ob1, ob2, out);
    (void)in_sizes; (void)n_in; (void)out_size;
}

// round 16
// speedup vs baseline: 1.8605x; 1.0027x over previous
#include <cuda_runtime.h>
#include <cuda_bf16.h>
#include <cuda_fp16.h>
#include <cstdint>

#define NNODES 768
#define NFACES 256
#define NTOT   1024
#define E0     6144
#define EF     1536
#define ETOT   9216
#define C      64
#define NKT    16
#define SRCCAP 64
#define HCAP   128

typedef uint32_t U32;

// layer2 smem layout (u32 units) — in-place GEMMs, no B buffers
#define L2U_W    0        // 10240 u32 bf16 fragments
#define L2U_AHI  10240    // 128 x 36
#define L2U_ALO  14848    // 128 x 36
#define L2U_RV   19456    // 192 floats
#define L2U_RC   19648    // 192 ints
#define L2U_ISL  19840    // 6144 u32 = 24576 bytes uchar
#define SMEM_TC  ((19840 + 6144) * 4)   // 103936 bytes -> 2 blocks/SM

// ---------------- device scratch ----------------
__device__ float g_feat[(NTOT + E0) * C];
__device__ float g_adjn[NTOT * NTOT];
__device__ int   g_outcnt[NTOT];
__device__ float g_srow[NTOT];
__device__ int   g_row_cnt[NTOT];
__device__ int   g_row_col[NTOT * 192];
__device__ float g_row_val[NTOT * 192];
__device__ int   g_src_cnt[NTOT];
__device__ int   g_src_list[NTOT * SRCCAP];
__device__ int   g_hcnt[NTOT * NKT];
__device__ int   g_dcnt[NTOT * NKT];
__device__ int2  g_hits[NTOT * NKT * HCAP];     // {(slot<<13)|cr, bits(a)}
__device__ __half g_delta_h[67108864];          // fp16 delta pool (134MB)
__device__ unsigned char g_islot[NTOT * NKT * 64];
// bf16 B-fragments: plW1 hi 0 / lo 2048, oW1 4096/6144, oW2 8192/9216 (u32 units)
// tf32 B-fragments for plW0 (layer1): hi 10240, lo 14336
__device__ float g_wfrag[18432];

// ---------------- helpers ----------------
__device__ __forceinline__ uint32_t tf32h(float x) {
    uint32_t r; asm("cvt.rna.tf32.f32 %0, %1;" : "=r"(r) : "f"(x)); return r;
}
__device__ __forceinline__ void mma_tf32(float* d, uint32_t a0, uint32_t a1,
                                         uint32_t a2, uint32_t a3,
                                         uint32_t b0, uint32_t b1) {
    asm volatile(
        "mma.sync.aligned.m16n8k8.row.col.f32.tf32.tf32.f32 "
        "{%0,%1,%2,%3},{%4,%5,%6,%7},{%8,%9},{%0,%1,%2,%3};"
        : "+f"(d[0]), "+f"(d[1]), "+f"(d[2]), "+f"(d[3])
        : "r"(a0), "r"(a1), "r"(a2), "r"(a3), "r"(b0), "r"(b1));
}
__device__ __forceinline__ void mma_bf16(float* d, U32 a0, U32 a1, U32 a2, U32 a3,
                                         U32 b0, U32 b1) {
    asm volatile(
        "mma.sync.aligned.m16n8k16.row.col.f32.bf16.bf16.f32 "
        "{%0,%1,%2,%3},{%4,%5,%6,%7},{%8,%9},{%0,%1,%2,%3};"
        : "+f"(d[0]), "+f"(d[1]), "+f"(d[2]), "+f"(d[3])
        : "r"(a0), "r"(a1), "r"(a2), "r"(a3), "r"(b0), "r"(b1));
}
__device__ __forceinline__ void packpair(float x, float y, U32& h, U32& l) {
    __nv_bfloat16 hx = __float2bfloat16(x);
    __nv_bfloat16 hy = __float2bfloat16(y);
    h = (U32)__bfloat16_as_ushort(hx) | ((U32)__bfloat16_as_ushort(hy) << 16);
    float rx = x - __bfloat162float(hx);
    float ry = y - __bfloat162float(hy);
    __nv_bfloat16 lx = __float2bfloat16(rx);
    __nv_bfloat16 ly = __float2bfloat16(ry);
    l = (U32)__bfloat16_as_ushort(lx) | ((U32)__bfloat16_as_ushort(ly) << 16);
}

// ---------------- embedding body ----------------
__device__ __forceinline__ void embed_body(
    const float* __restrict__ X, int blk, int R, int Din,
    const float* __restrict__ W1, const float* __restrict__ b1,
    const float* __restrict__ W2, const float* __restrict__ b2,
    float* __restrict__ Y, float* Xs, float* Hs)
{
    int r0 = blk * 16;
    int t = threadIdx.x;
    for (int idx = t; idx < 16 * Din; idx += 128) {
        int r = idx / Din, d = idx % Din;
        Xs[r * Din + d] = (r0 + r < R) ? X[(size_t)(r0 + r) * Din + d] : 0.f;
    }
    __syncthreads();
    int lr = t >> 3;
    int c0 = (t & 7) * 8;
    float h[8];
#pragma unroll
    for (int q = 0; q < 8; q++) h[q] = b1[c0 + q];
    for (int d = 0; d < Din; d++) {
        float x = Xs[lr * Din + d];
        const float* w = W1 + d * C + c0;
#pragma unroll
        for (int q = 0; q < 8; q++) h[q] += x * w[q];
    }
#pragma unroll
    for (int q = 0; q < 8; q++) Hs[lr * C + c0 + q] = fmaxf(h[q], 0.f);
    __syncthreads();
    float y[8];
#pragma unroll
    for (int q = 0; q < 8; q++) y[q] = b2[c0 + q];
    for (int m = 0; m < C; m++) {
        float hm = Hs[lr * C + m];
        const float* w = W2 + m * C + c0;
#pragma unroll
        for (int q = 0; q < 8; q++) y[q] += hm * w[q];
    }
    if (r0 + lr < R) {
        float* yo = Y + (size_t)(r0 + lr) * C + c0;
#pragma unroll
        for (int q = 0; q < 8; q++) yo[q] = fmaxf(y[q], 0.f);
    }
}

// ---------------- launch 1: embeds + zeroing + weight fragment prep ----------------
__global__ __launch_bounds__(128) void k_init(
    const float* __restrict__ node_x, const float* __restrict__ edge_x,
    const float* __restrict__ face_x,
    const float* __restrict__ nW1, const float* __restrict__ nb1,
    const float* __restrict__ nW2, const float* __restrict__ nb2,
    const float* __restrict__ eW1, const float* __restrict__ eb1,
    const float* __restrict__ eW2, const float* __restrict__ eb2,
    const float* __restrict__ fW1, const float* __restrict__ fb1,
    const float* __restrict__ fW2, const float* __restrict__ fb2,
    const float* __restrict__ plW0, const float* __restrict__ plW1,
    const float* __restrict__ oW1, const float* __restrict__ oW2)
{
    __shared__ float Xs[16 * 144];
    __shared__ float Hs[16 * C];
    int b = blockIdx.x;
    int t = threadIdx.x;
    if (b < 48) {
        embed_body(node_x, b, NNODES, 144, nW1, nb1, nW2, nb2, g_feat, Xs, Hs);
    } else if (b < 432) {
        embed_body(edge_x, b - 48, E0, 144, eW1, eb1, eW2, eb2, g_feat + NTOT * C, Xs, Hs);
    } else if (b < 448) {
        embed_body(face_x, b - 432, NFACES, 12, fW1, fb1, fW2, fb2, g_feat + NNODES * C, Xs, Hs);
    } else {
        int z = b - 448;  // 0..1023
        float4 zv = make_float4(0.f, 0.f, 0.f, 0.f);
        float4* ap = (float4*)(g_adjn) + (size_t)z * 256 + t * 2;
        ap[0] = zv; ap[1] = zv;
        if (z == 0) {
            for (int q = 0; q < 8; q++) g_src_cnt[t * 8 + q] = 0;
        } else if (z == 1) {
            for (int q = 0; q < 8; q++) g_outcnt[t * 8 + q] = 0;
        } else if (z >= 6 && z < 9) {
            // bf16 hi/lo fragment pack for layer-2 weights (m16n8k16)
            int w = z - 6;
            const float* W = (w == 0) ? plW1 : (w == 1) ? oW1 : oW2;
            int Tn = (w == 2) ? 4 : 8;
            int Nd = Tn * 8;
            U32* gh = (U32*)g_wfrag + ((w == 0) ? 0 : (w == 1) ? 4096 : 8192);
            U32* gl = gh + ((w == 2) ? 1024 : 2048);
            int total = 4 * Tn * 32;
            for (int idx = t; idx < total; idx += 128) {
                int kk = idx / (Tn * 32);
                int rem = idx - kk * Tn * 32;
                int tile = rem >> 5;
                int l = rem & 31;
                int n  = tile * 8 + (l >> 2);
                int k0 = kk * 16 + (l & 3) * 2;
                U32 h0, l0, h1, l1;
                packpair(W[k0 * Nd + n], W[(k0 + 1) * Nd + n], h0, l0);
                packpair(W[(k0 + 8) * Nd + n], W[(k0 + 9) * Nd + n], h1, l1);
                gh[idx * 2] = h0; gh[idx * 2 + 1] = h1;
                gl[idx * 2] = l0; gl[idx * 2 + 1] = l1;
            }
        } else if (z == 9) {
            // tf32 hi/lo fragment pack for plW0 (layer-1 epilogue, m16n8k8)
            const float* W = plW0;
            float* gh = g_wfrag + 10240;
            float* gl = g_wfrag + 14336;
            for (int idx = t; idx < 2048; idx += 128) {
                int kk = idx >> 8;
                int rem = idx & 255;
                int tile = rem >> 5;
                int l = rem & 31;
                int k0 = kk * 8 + (l & 3);
                int n  = tile * 8 + (l >> 2);
                float v0 = W[k0 * 64 + n];
                float v1 = W[(k0 + 4) * 64 + n];
                uint32_t h0 = tf32h(v0);
                uint32_t h1 = tf32h(v1);
                uint32_t l0 = tf32h(v0 - __uint_as_float(h0));
                uint32_t l1 = tf32h(v1 - __uint_as_float(h1));
                gh[idx * 2]     = __uint_as_float(h0);
                gh[idx * 2 + 1] = __uint_as_float(h1);
                gl[idx * 2]     = __uint_as_float(l0);
                gl[idx * 2 + 1] = __uint_as_float(l1);
            }
        }
    }
}

// ---------------- launch 2: edges + diag + out-degree + src lists ----------------
__global__ void k_edges(const int* __restrict__ ei, const int* __restrict__ fn) {
    int e = blockIdx.x * blockDim.x + threadIdx.x;
    if (e >= ETOT + NTOT) return;
    if (e >= ETOT) {
        int i = e - ETOT;
        atomicAdd(&g_adjn[i * NTOT + i], 1.0f);
        return;
    }
    int s, d, cr;
    if (e < E0)            { s = ei[e]; d = ei[E0 + e]; cr = NTOT + e; }
    else if (e < E0 + EF)  { int q = e - E0; int f = q / 6; s = fn[q]; d = NNODES + f; cr = NNODES + f; }
    else                   { int r = e - (E0 + EF); int rr = 1535 - r; int f = rr / 6;
                             s = NNODES + f; d = fn[rr]; cr = NNODES + f; }
    atomicAdd(&g_adjn[s * NTOT + d], 1.0f);
    atomicAdd(&g_outcnt[s], 1);
    int p = atomicAdd(&g_src_cnt[s], 1);
    if (p < SRCCAP) g_src_list[s * SRCCAP + p] = (d << 13) | cr;
}

// ---------------- launch 3: scale + CSR + row sums ----------------
__global__ __launch_bounds__(256) void k_scale_csr() {
    int i = blockIdx.x;
    __shared__ int cnt;
    __shared__ float red[8];
    if (threadIdx.x == 0) cnt = 0;
    __syncthreads();
    float di = 1.f / sqrtf(1.f + (float)g_outcnt[i]);
    float sv = 0.f;
    for (int j = threadIdx.x; j < NTOT; j += 256) {
        float v = g_adjn[i * NTOT + j];
        if (v != 0.f) {
            float dj = 1.f / sqrtf(1.f + (float)g_outcnt[j]);
            v *= di * dj;
            sv += v;
            int p = atomicAdd(&cnt, 1);
            if (p < 192) { g_row_col[i * 192 + p] = j; g_row_val[i * 192 + p] = v; }
        }
    }
#pragma unroll
    for (int o = 16; o > 0; o >>= 1) sv += __shfl_down_sync(0xffffffffu, sv, o);
    if ((threadIdx.x & 31) == 0) red[threadIdx.x >> 5] = sv;
    __syncthreads();
    if (threadIdx.x == 0) {
        float tot = 0.f;
        for (int w = 0; w < 8; w++) tot += red[w];
        g_srow[i] = tot;
        g_row_cnt[i] = min(cnt, 192);
    }
}

// ---------------- launch 4: hit lists with precomputed slots + islot ----------------
__global__ __launch_bounds__(256) void k_hits() {
    const int j = blockIdx.x;
    const int t = threadIdx.x;
    __shared__ U32 dmask[32];
    __shared__ int sc[NKT];
    __shared__ unsigned char map[NTOT];
    if (t < 32) dmask[t] = 0;
    if (t < NKT) sc[t] = 0;
    __syncthreads();

    const int rn = g_row_cnt[j];
    int s = -1, oc = 0;
    if (t < rn) {
        s = g_row_col[j * 192 + t];
        atomicOr(&dmask[s >> 5], 1u << (s & 31));
        oc = min(g_src_cnt[s], SRCCAP);
        for (int q = 0; q < oc; q++) {
            int d = g_src_list[s * SRCCAP + q] >> 13;
            atomicOr(&dmask[d >> 5], 1u << (d & 31));
        }
    }
    __syncthreads();

#pragma unroll
    for (int q = 0; q < 4; q++) {
        int idx = t + q * 256;
        int kt = idx >> 6, kl = idx & 63;
        U32 lo = dmask[kt * 2], hi = dmask[kt * 2 + 1];
        int set, below;
        if (kl < 32) {
            set = (lo >> kl) & 1;
            below = __popc(lo & ((1u << kl) - 1u));
        } else {
            set = (hi >> (kl - 32)) & 1;
            below = __popc(lo) + __popc(hi & ((kl == 32) ? 0u : ((1u << (kl - 32)) - 1u)));
        }
        unsigned char slot = set ? (unsigned char)below : (unsigned char)0xFF;
        map[idx] = slot;
        g_islot[(j * NKT + kt) * 64 + kl] = slot;
        if (kl == 63) g_dcnt[j * NKT + kt] = __popc(lo) + __popc(hi);
    }
    __syncthreads();

    if (t < rn) {
        int abits = __float_as_int(g_row_val[j * 192 + t]);
        {
            int kt = s >> 6;
            int p = atomicAdd(&sc[kt], 1);
            if (p < HCAP)
                g_hits[(j * NKT + kt) * HCAP + p] = make_int2(((int)map[s] << 13) | s, abits);
        }
        for (int q = 0; q < oc; q++) {
            int packed = g_src_list[s * SRCCAP + q];
            int d = packed >> 13, cr = packed & 8191;
            int kt = d >> 6;
            int p = atomicAdd(&sc[kt], 1);
            if (p < HCAP)
                g_hits[(j * NKT + kt) * HCAP + p] = make_int2(((int)map[d] << 13) | cr, abits);
        }
    }
    __syncthreads();
    if (t < NKT) g_hcnt[j * NKT + t] = min(sc[t], HCAP);
}

// ---------------- launch 5: layer-1 deltas (slot scatter + tf32 mma epilogue, fp16 out) ----------------
__global__ __launch_bounds__(256) void k_layer1(const float* __restrict__ plb)
{
    __shared__ float Hs[64 * 65];

    const int kt = blockIdx.x;
    const int j  = blockIdx.y;
    const int t  = threadIdx.x;
    const int seg = j * NKT + kt;
    const int n = g_dcnt[seg];
    if (n == 0) return;
    const int ne = g_hcnt[seg];

    for (int idx = t; idx < n * 65; idx += 256) Hs[idx] = 0.f;
    __syncthreads();

    {
        const int sub = (t & 3) * 16;
        for (int idx = t >> 2; idx < ne; idx += 64) {
            int2 ent = g_hits[seg * HCAP + idx];
            int slot = ent.x >> 13, cr = ent.x & 8191;
            float a = __int_as_float(ent.y);
            const float4* fp = (const float4*)(g_feat + cr * C + sub);
            float* h = Hs + slot * 65 + sub;
#pragma unroll
            for (int q = 0; q < 4; q++) {
                float4 v = fp[q];
                atomicAdd(h + 4*q + 0, a * v.x);
                atomicAdd(h + 4*q + 1, a * v.y);
                atomicAdd(h + 4*q + 2, a * v.z);
                atomicAdd(h + 4*q + 3, a * v.w);
            }
        }
    }
    __syncthreads();

    const int wid = t >> 5, lane = t & 31;
    const int r0l = lane >> 2;
    const int cl = lane & 3;
    const float* Wh = g_wfrag + 10240;
    const float* Wl = g_wfrag + 14336;
    const size_t segbase = (size_t)seg * 4096;
    for (int mt = 0; mt * 16 < n; mt++) {
        const int m0 = mt * 16 + r0l;
        const int m1 = m0 + 8;
        float acc[4] = {0.f, 0.f, 0.f, 0.f};
#pragma unroll
        for (int kk = 0; kk < 8; kk++) {
            int c0 = kk * 8 + cl;
            float a0f = (m0 < n) ? Hs[m0 * 65 + c0] : 0.f;
            float a1f = (m1 < n) ? Hs[m1 * 65 + c0] : 0.f;
            float a2f = (m0 < n) ? Hs[m0 * 65 + c0 + 4] : 0.f;
            float a3f = (m1 < n) ? Hs[m1 * 65 + c0 + 4] : 0.f;
            uint32_t ah0 = tf32h(a0f), ah1 = tf32h(a1f), ah2 = tf32h(a2f), ah3 = tf32h(a3f);
            uint32_t al0 = tf32h(a0f - __uint_as_float(ah0));
            uint32_t al1 = tf32h(a1f - __uint_as_float(ah1));
            uint32_t al2 = tf32h(a2f - __uint_as_float(ah2));
            uint32_t al3 = tf32h(a3f - __uint_as_float(ah3));
            int fo = ((kk * 8 + wid) * 32 + lane) * 2;
            uint2 bh = *(const uint2*)(Wh + fo);
            uint2 bl = *(const uint2*)(Wl + fo);
            mma_tf32(acc, ah0, ah1, ah2, ah3, bh.x, bh.y);
            mma_tf32(acc, ah0, ah1, ah2, ah3, bl.x, bl.y);
            mma_tf32(acc, al0, al1, al2, al3, bh.x, bh.y);
        }
        int cg = wid * 8 + cl * 2;
        float b0 = plb[cg], b1 = plb[cg + 1];
        float crc0 = fmaxf(b0, 0.f), crc1 = fmaxf(b1, 0.f);
        if (m0 < n) {
            *(__half2*)(g_delta_h + segbase + (size_t)m0 * 64 + cg) =
                __floats2half2_rn(fmaxf(acc[0] + b0, 0.f) - crc0,
                                  fmaxf(acc[1] + b1, 0.f) - crc1);
        }
        if (m1 < n) {
            *(__half2*)(g_delta_h + segbase + (size_t)m1 * 64 + cg) =
                __floats2half2_rn(fmaxf(acc[2] + b0, 0.f) - crc0,
                                  fmaxf(acc[3] + b1, 0.f) - crc1);
        }
    }
}

// ---------------- bf16 split GEMM phases (M=128, packed operands, IN-PLACE) ----------------
__device__ __forceinline__ void gemm64_bf(
    U32* AHi, U32* ALo, const U32* WHi, const U32* WLo,
    const float* __restrict__ bias, int wid, int lane)
{
    const int wr = wid & 7;
    const int wc = wid >> 3;
    const int rb = wr * 16 + (lane >> 2);
    const int cl = lane & 3;
    float acc[4][4];
#pragma unroll
    for (int a = 0; a < 4; a++)
#pragma unroll
        for (int b = 0; b < 4; b++) acc[a][b] = 0.f;
#pragma unroll
    for (int kk = 0; kk < 4; kk++) {
        const int ai = kk * 8 + cl;
        U32 ah0 = AHi[rb * 36 + ai],       ah1 = AHi[(rb + 8) * 36 + ai];
        U32 ah2 = AHi[rb * 36 + ai + 4],   ah3 = AHi[(rb + 8) * 36 + ai + 4];
        U32 al0 = ALo[rb * 36 + ai],       al1 = ALo[(rb + 8) * 36 + ai];
        U32 al2 = ALo[rb * 36 + ai + 4],   al3 = ALo[(rb + 8) * 36 + ai + 4];
#pragma unroll
        for (int t4 = 0; t4 < 4; t4++) {
            int fo = ((kk * 8 + wc * 4 + t4) * 32 + lane) * 2;
            uint2 bh = *(const uint2*)(WHi + fo);
            uint2 bl = *(const uint2*)(WLo + fo);
            mma_bf16(acc[t4], ah0, ah1, ah2, ah3, bh.x, bh.y);
            mma_bf16(acc[t4], ah0, ah1, ah2, ah3, bl.x, bl.y);
            mma_bf16(acc[t4], al0, al1, al2, al3, bh.x, bh.y);
        }
    }
    __syncthreads();
#pragma unroll
    for (int t4 = 0; t4 < 4; t4++) {
        int cg = (wc * 4 + t4) * 8 + cl * 2;
        int pi = (wc * 4 + t4) * 4 + cl;
        float b0 = bias[cg], b1 = bias[cg + 1];
        float v0 = fmaxf(acc[t4][0] + b0, 0.f), v1 = fmaxf(acc[t4][1] + b1, 0.f);
        float v2 = fmaxf(acc[t4][2] + b0, 0.f), v3 = fmaxf(acc[t4][3] + b1, 0.f);
        U32 h, l;
        packpair(v0, v1, h, l);
        AHi[rb * 36 + pi] = h; ALo[rb * 36 + pi] = l;
        packpair(v2, v3, h, l);
        AHi[(rb + 8) * 36 + pi] = h; ALo[(rb + 8) * 36 + pi] = l;
    }
}

__device__ __forceinline__ void gemm32_bf(
    const U32* AHi, const U32* ALo, const U32* WHi, const U32* WLo,
    const float* __restrict__ bias, float* outB, int wid, int lane)
{
    const int wr = wid & 7;
    const int wc = wid >> 3;
    const int rb = wr * 16 + (lane >> 2);
    const int cl = lane & 3;
    float acc[2][4];
#pragma unroll
    for (int a = 0; a < 2; a++)
#pragma unroll
        for (int b = 0; b < 4; b++) acc[a][b] = 0.f;
#pragma unroll
    for (int kk = 0; kk < 4; kk++) {
        const int ai = kk * 8 + cl;
        U32 ah0 = AHi[rb * 36 + ai],       ah1 = AHi[(rb + 8) * 36 + ai];
        U32 ah2 = AHi[rb * 36 + ai + 4],   ah3 = AHi[(rb + 8) * 36 + ai + 4];
        U32 al0 = ALo[rb * 36 + ai],       al1 = ALo[(rb + 8) * 36 + ai];
        U32 al2 = ALo[rb * 36 + ai + 4],   al3 = ALo[(rb + 8) * 36 + ai + 4];
#pragma unroll
        for (int t2 = 0; t2 < 2; t2++) {
            int fo = ((kk * 4 + wc * 2 + t2) * 32 + lane) * 2;
            uint2 bh = *(const uint2*)(WHi + fo);
            uint2 bl = *(const uint2*)(WLo + fo);
            mma_bf16(acc[t2], ah0, ah1, ah2, ah3, bh.x, bh.y);
            mma_bf16(acc[t2], ah0, ah1, ah2, ah3, bl.x, bl.y);
            mma_bf16(acc[t2], al0, al1, al2, al3, bh.x, bh.y);
        }
    }
#pragma unroll
    for (int t2 = 0; t2 < 2; t2++) {
        int cg = (wc * 2 + t2) * 8 + cl * 2;
        float b0 = bias[cg], b1 = bias[cg + 1];
        *(float2*)(outB + (size_t)rb * 32 + cg) =
            make_float2(acc[t2][0] + b0, acc[t2][1] + b1);
        *(float2*)(outB + (size_t)(rb + 8) * 32 + cg) =
            make_float2(acc[t2][2] + b0, acc[t2][3] + b1);
    }
}

// ---------------- launch 6: layer 2 (fp16 gather + split-bf16 tensor MLP) ----------------
__global__ __launch_bounds__(512, 2) void k_layer2(
    const float* __restrict__ plb0,
    const float* __restrict__ plb1, const float* __restrict__ ob1,
    const float* __restrict__ ob2, float* __restrict__ out)
{
    extern __shared__ U32 su[];
    U32* Wf  = su + L2U_W;
    U32* AHi = su + L2U_AHI;
    U32* ALo = su + L2U_ALO;
    float* rvS = (float*)(su + L2U_RV);
    int*   rcS = (int*)(su + L2U_RC);
    unsigned char* islotS = (unsigned char*)(su + L2U_ISL);

    const int i    = blockIdx.x;
    const int half = blockIdx.y;
    const int t    = threadIdx.x;
    const int wid  = t >> 5;
    const int lane = t & 31;

    {
        const uint4* src = (const uint4*)g_wfrag;
        uint4* dst = (uint4*)Wf;
#pragma unroll
        for (int q = 0; q < 5; q++) dst[t + q * 512] = src[t + q * 512];
    }
    const int rn = g_row_cnt[i];
    if (t < rn) { rcS[t] = g_row_col[i * 192 + t]; rvS[t] = g_row_val[i * 192 + t]; }
    __syncthreads();

    const float sI = g_srow[i];

    for (int it = 0; it < 4; it++) {
        const int ktbase = half * 8 + it * 2;
        for (int idx = t; idx < rn * 32; idx += 512) {
            int r = idx >> 5, w = idx & 31;
            ((unsigned*)islotS)[r * 32 + w] =
                ((const unsigned*)g_islot)[(rcS[r] * 16 + ktbase) * 16 + w];
        }
        __syncthreads();

        // Phase A: fp16 gather -> fp32 acc -> pack hi/lo bf16 pairs
        {
            const int row = t >> 2;
            const int sub = (t & 3) * 16;
            float4 acc[4];
#pragma unroll
            for (int q = 0; q < 4; q++) {
                float4 b = *(const float4*)(plb0 + sub + q * 4);
                acc[q] = make_float4(sI * fmaxf(b.x, 0.f), sI * fmaxf(b.y, 0.f),
                                     sI * fmaxf(b.z, 0.f), sI * fmaxf(b.w, 0.f));
            }
            const int ktoff = ktbase + (row >> 6);
            for (int r = 0; r < rn; r++) {
                unsigned slot = islotS[r * 128 + row];
                if (slot != 0xFFu) {
                    float a = rvS[r];
                    int seg = rcS[r] * 16 + ktoff;
                    const uint4* dp = (const uint4*)(g_delta_h + ((size_t)seg * 64 + slot) * 64 + sub);
                    uint4 w0 = dp[0], w1 = dp[1];
                    float2 f;
                    f = __half22float2(*(__half2*)&w0.x); acc[0].x += a * f.x; acc[0].y += a * f.y;
                    f = __half22float2(*(__half2*)&w0.y); acc[0].z += a * f.x; acc[0].w += a * f.y;
                    f = __half22float2(*(__half2*)&w0.z); acc[1].x += a * f.x; acc[1].y += a * f.y;
                    f = __half22float2(*(__half2*)&w0.w); acc[1].z += a * f.x; acc[1].w += a * f.y;
                    f = __half22float2(*(__half2*)&w1.x); acc[2].x += a * f.x; acc[2].y += a * f.y;
                    f = __half22float2(*(__half2*)&w1.y); acc[2].z += a * f.x; acc[2].w += a * f.y;
                    f = __half22float2(*(__half2*)&w1.z); acc[3].x += a * f.x; acc[3].y += a * f.y;
                    f = __half22float2(*(__half2*)&w1.w); acc[3].z += a * f.x; acc[3].w += a * f.y;
                }
            }
            U32* hp = AHi + row * 36 + (sub >> 1);
            U32* lp = ALo + row * 36 + (sub >> 1);
#pragma unroll
            for (int q = 0; q < 4; q++) {
                U32 h, l;
                packpair(acc[q].x, acc[q].y, h, l);
                hp[2 * q] = h; lp[2 * q] = l;
                packpair(acc[q].z, acc[q].w, h, l);
                hp[2 * q + 1] = h; lp[2 * q + 1] = l;
            }
        }
        __syncthreads();

        gemm64_bf(AHi, ALo, Wf, Wf + 2048, plb1, wid, lane);
        __syncthreads();
        gemm64_bf(AHi, ALo, Wf + 4096, Wf + 6144, ob1, wid, lane);
        __syncthreads();
        gemm32_bf(AHi, ALo, Wf + 8192, Wf + 9216, ob2,
                  out + ((size_t)i * NTOT + half * 512 + it * 128) * 32, wid, lane);
        __syncthreads();
    }
}

// ---------------- launch ----------------
extern "C" void kernel_launch(void* const* d_in, const int* in_sizes, int n_in,
                              void* d_out, int out_size)
{
    const float* node_x = (const float*)d_in[0];
    const float* edge_x = (const float*)d_in[1];
    const float* face_x = (const float*)d_in[2];
    const float* nW1 = (const float*)d_in[3];  const float* nb1 = (const float*)d_in[4];
    const float* nW2 = (const float*)d_in[5];  const float* nb2 = (const float*)d_in[6];
    const float* eW1 = (const float*)d_in[7];  const float* eb1 = (const float*)d_in[8];
    const float* eW2 = (const float*)d_in[9];  const float* eb2 = (const float*)d_in[10];
    const float* fW1 = (const float*)d_in[11]; const float* fb1 = (const float*)d_in[12];
    const float* fW2 = (const float*)d_in[13]; const float* fb2 = (const float*)d_in[14];
    const float* oW1 = (const float*)d_in[15]; const float* ob1 = (const float*)d_in[16];
    const float* oW2 = (const float*)d_in[17]; const float* ob2 = (const float*)d_in[18];
    const float* plW = (const float*)d_in[19]; const float* plb = (const float*)d_in[20];
    const int* edge_index = (const int*)d_in[21];
    const int* face_nodes = (const int*)d_in[22];
    float* out = (float*)d_out;

    cudaFuncSetAttribute(k_layer2, cudaFuncAttributeMaxDynamicSharedMemorySize, SMEM_TC);

    k_init<<<1472, 128>>>(node_x, edge_x, face_x, nW1, nb1, nW2, nb2,
                          eW1, eb1, eW2, eb2, fW1, fb1, fW2, fb2,
                          plW, plW + 4096, oW1, oW2);
    k_edges<<<(ETOT + NTOT + 255) / 256, 256>>>(edge_index, face_nodes);
    k_scale_csr<<<NTOT, 256>>>();
    k_hits<<<NTOT, 256>>>();
    k_layer1<<<dim3(NKT, NTOT), 256>>>(plb);
    k_layer2<<<dim3(NTOT, 2), 512, SMEM_TC>>>(plb, plb + 64, ob1, ob2, out);
    (void)in_sizes; (void)n_in; (void)out_size;
}